// round 1
// baseline (speedup 1.0000x reference)
#include <cuda_runtime.h>
#include <cuda_bf16.h>
#include <cstddef>

// Problem constants
#define NN 10000
#define EE 160000
#define CC 4
#define CFD 16
#define RR 7
#define HH 256
#define LL 2
#define EIN 560           // 2H + CF + 2CF
#define NIN 2048          // R*H + H
#define EPSV 1e-5f

// ---------------------------------------------------------------------------
// Scratch: one big static device buffer, carved by offsets (floats).
// ---------------------------------------------------------------------------
#define OFF_CA    ((size_t)0)                         // N*16
#define OFF_MIN   (OFF_CA   + (size_t)NN*16)          // E*560
#define OFF_M1    (OFF_MIN  + (size_t)EE*EIN)         // E*256
#define OFF_M     (OFF_M1   + (size_t)EE*HH)          // E*256
#define OFF_PHI   (OFF_M    + (size_t)EE*HH)          // E*16
#define OFF_AGG   (OFF_PHI  + (size_t)EE*16)          // N*R*H
#define OFF_NINB  (OFF_AGG  + (size_t)NN*RR*HH)       // N*2048
#define OFF_H1    (OFF_NINB + (size_t)NN*NIN)         // N*256
#define OFF_HBUF  (OFF_H1   + (size_t)NN*HH)          // N*256
#define OFF_XBUF  (OFF_HBUF + (size_t)NN*HH)          // N*12
#define OFF_XACC  (OFF_XBUF + (size_t)NN*12)          // N*12
#define OFF_CNT   (OFF_XACC + (size_t)NN*12)          // N
#define TOTAL_F   (OFF_CNT  + (size_t)NN)

__device__ float g_buf[TOTAL_F];

__device__ __forceinline__ float silu_f(float v) { return v / (1.0f + __expf(-v)); }

// ---------------------------------------------------------------------------
// Utility: zero a float range
// ---------------------------------------------------------------------------
__global__ void zero_kernel(float* __restrict__ p, size_t n) {
    size_t i = (size_t)blockIdx.x * blockDim.x + threadIdx.x;
    if (i < n) p[i] = 0.0f;
}

// ---------------------------------------------------------------------------
// ca[n,f] = sum_c attr[n,c,f]*cw[n,c] / sum_c cw[n,c]
// ---------------------------------------------------------------------------
__global__ void ca_kernel(const float* __restrict__ attr, const float* __restrict__ cw,
                          float* __restrict__ ca) {
    int n = blockIdx.x * blockDim.x + threadIdx.x;
    if (n >= NN) return;
    float w0 = cw[n*4+0], w1 = cw[n*4+1], w2 = cw[n*4+2], w3 = cw[n*4+3];
    float inv = 1.0f / (w0 + w1 + w2 + w3);
    const float* a = attr + (size_t)n * 64;
#pragma unroll
    for (int f = 0; f < 16; f++)
        ca[n*16+f] = (a[f]*w0 + a[16+f]*w1 + a[32+f]*w2 + a[48+f]*w3) * inv;
}

// ---------------------------------------------------------------------------
// cnt[n] = #edges with row == n
// ---------------------------------------------------------------------------
__global__ void cnt_kernel(const int* __restrict__ el, float* __restrict__ cnt) {
    int e = blockIdx.x * blockDim.x + threadIdx.x;
    if (e >= EE) return;
    atomicAdd(&cnt[el[3*e]], 1.0f);
}

// ---------------------------------------------------------------------------
// Build m_in row for each edge: [h[row] | h[col] | rad_feat | ca[row] | ca[col]]
// rad_feat = silu(radial(16) @ W_rad(16x16) + b_rad)
// One block (128 thr) per edge.
// ---------------------------------------------------------------------------
__global__ void edge_build_kernel(const float* __restrict__ h, const float* __restrict__ x,
                                  const int* __restrict__ el, const float* __restrict__ cw,
                                  const float* __restrict__ ca,
                                  const float* __restrict__ Wrad, const float* __restrict__ brad,
                                  float* __restrict__ minb) {
    int e = blockIdx.x;
    int t = threadIdx.x;
    int row = el[3*e], col = el[3*e+1];
    float* out = minb + (size_t)e * EIN;

    // h[row] -> cols [0,256), h[col] -> [256,512)  (128 float4 total)
    const float4* hr = (const float4*)(h + (size_t)row * HH);
    const float4* hc = (const float4*)(h + (size_t)col * HH);
    float4* o4 = (float4*)out;
    o4[t] = (t < 64) ? hr[t] : hc[t - 64];

    // ca[row] -> [528,544), ca[col] -> [544,560)
    if (t < 4)       ((float4*)(out + 528))[t]     = ((const float4*)(ca + (size_t)row*16))[t];
    else if (t < 8)  ((float4*)(out + 544))[t - 4] = ((const float4*)(ca + (size_t)col*16))[t - 4];

    __shared__ float rad[16];
    if (t < 16) {
        int i = t >> 2, j = t & 3;
        float dx = x[row*12 + i*3 + 0] - x[col*12 + j*3 + 0];
        float dy = x[row*12 + i*3 + 1] - x[col*12 + j*3 + 1];
        float dz = x[row*12 + i*3 + 2] - x[col*12 + j*3 + 2];
        rad[t] = (dx*dx + dy*dy + dz*dz) * cw[row*4 + i] * cw[col*4 + j];
    }
    __syncthreads();
    if (t < 16) {
        float acc = brad[t];
#pragma unroll
        for (int k = 0; k < 16; k++) acc = fmaf(rad[k], Wrad[k*16 + t], acc);
        out[512 + t] = silu_f(acc);
    }
}

// ---------------------------------------------------------------------------
// SGEMM: C(MxNc) = act(A(MxK) @ B(KxNc) + bias), optional per-row scale.
// BM=BN=128, BK=8, 256 threads, 8x8 per-thread tile.
// ACT: 0 = none, 1 = silu, 2 = silu then *rowscale
// Requires: Nc % 128 == 0, K % 8 == 0. M edge guarded.
// ---------------------------------------------------------------------------
template <int ACT>
__global__ void sgemm_kernel(const float* __restrict__ A, const float* __restrict__ B,
                             const float* __restrict__ bias, const float* __restrict__ rowscale,
                             float* __restrict__ Cm, int M, int Nc, int K) {
    const int BM = 128, BN = 128, BK = 8, TM = 8, TN = 8;
    __shared__ float As[BK][BM];
    __shared__ float Bs[BK][BN];
    int tid = threadIdx.x;
    int rowBase = blockIdx.y * BM;
    int colBase = blockIdx.x * BN;
    int trow = (tid / 16) * TM;
    int tcol = (tid % 16) * TN;

    float acc[TM][TN];
#pragma unroll
    for (int i = 0; i < TM; i++)
#pragma unroll
        for (int j = 0; j < TN; j++) acc[i][j] = 0.0f;

    int aRow = tid >> 1;
    int aCol = (tid & 1) * 4;
    int bRow = tid >> 5;
    int bCol = (tid & 31) * 4;
    bool aInM = (rowBase + aRow) < M;
    const float* Aptr = A + (size_t)(rowBase + aRow) * K + aCol;
    const float* Bptr = B + (size_t)bRow * Nc + colBase + bCol;

    for (int k0 = 0; k0 < K; k0 += BK) {
        float4 av = aInM ? *(const float4*)Aptr : make_float4(0.f, 0.f, 0.f, 0.f);
        As[aCol + 0][aRow] = av.x;
        As[aCol + 1][aRow] = av.y;
        As[aCol + 2][aRow] = av.z;
        As[aCol + 3][aRow] = av.w;
        *(float4*)&Bs[bRow][bCol] = *(const float4*)Bptr;
        __syncthreads();
#pragma unroll
        for (int k = 0; k < BK; k++) {
            float ar[TM], br[TN];
#pragma unroll
            for (int i = 0; i < TM; i++) ar[i] = As[k][trow + i];
#pragma unroll
            for (int j = 0; j < TN; j++) br[j] = Bs[k][tcol + j];
#pragma unroll
            for (int i = 0; i < TM; i++)
#pragma unroll
                for (int j = 0; j < TN; j++)
                    acc[i][j] = fmaf(ar[i], br[j], acc[i][j]);
        }
        __syncthreads();
        Aptr += BK;
        Bptr += (size_t)BK * Nc;
    }

#pragma unroll
    for (int i = 0; i < TM; i++) {
        int r = rowBase + trow + i;
        if (r >= M) continue;
        float sc = (ACT == 2) ? rowscale[r] : 1.0f;
#pragma unroll
        for (int j = 0; j < TN; j++) {
            int c = colBase + tcol + j;
            float v = acc[i][j] + bias[c];
            if (ACT >= 1) v = silu_f(v);
            if (ACT == 2) v *= sc;
            Cm[(size_t)r * Nc + c] = v;
        }
    }
}

// ---------------------------------------------------------------------------
// phi = A(Ex256) @ W(256x16)   (no bias/act). 16 rows per block, 256 threads.
// ---------------------------------------------------------------------------
__global__ void gemm_phi_kernel(const float* __restrict__ A, const float* __restrict__ W,
                                float* __restrict__ out, int M) {
    __shared__ float Ws[256 * 16];
    __shared__ float Ar[16][256];
    int tid = threadIdx.x;
    for (int i = tid; i < 256 * 16; i += 256) Ws[i] = W[i];
    int e0 = blockIdx.x * 16;
    for (int i = tid; i < 16 * 64; i += 256) {
        int r = i / 64, c4 = i % 64;
        int e = e0 + r;
        float4 v = (e < M) ? ((const float4*)(A + (size_t)e * 256))[c4]
                           : make_float4(0.f, 0.f, 0.f, 0.f);
        *(float4*)&Ar[r][c4 * 4] = v;
    }
    __syncthreads();
    int r = tid >> 4, n = tid & 15;
    int e = e0 + r;
    if (e >= M) return;
    float acc = 0.0f;
#pragma unroll 16
    for (int k = 0; k < 256; k++) acc = fmaf(Ar[r][k], Ws[k * 16 + n], acc);
    out[(size_t)e * 16 + n] = acc;
}

// ---------------------------------------------------------------------------
// x scatter: trans[e,i,:] = 0.25 * sum_j xd[e,i,j,:] * phi[e,i,j]; atomicAdd into xacc[row]
// One warp per edge; lanes 0..11 handle (i,d).
// ---------------------------------------------------------------------------
__global__ void x_scatter_kernel(const float* __restrict__ x, const int* __restrict__ el,
                                 const float* __restrict__ phi, float* __restrict__ xacc) {
    int e = blockIdx.x * 8 + (threadIdx.x >> 5);
    if (e >= EE) return;
    int lane = threadIdx.x & 31;
    if (lane >= 12) return;
    int row = el[3*e], col = el[3*e+1];
    int i = lane / 3, d = lane % 3;
    float xr = x[row*12 + i*3 + d];
    float s = 0.0f;
#pragma unroll
    for (int j = 0; j < 4; j++) {
        float xd = xr - x[col*12 + j*3 + d];
        s = fmaf(xd, phi[(size_t)e*16 + i*4 + j], s);
    }
    atomicAdd(&xacc[row*12 + lane], s * 0.25f);
}

// ---------------------------------------------------------------------------
// agg[(col*R+rel)*H + t] += m[e*H + t]   (one thread per (e,t))
// ---------------------------------------------------------------------------
__global__ void agg_scatter_kernel(const int* __restrict__ el, const float* __restrict__ m,
                                   float* __restrict__ agg) {
    size_t idx = (size_t)blockIdx.x * blockDim.x + threadIdx.x;
    if (idx >= (size_t)EE * HH) return;
    int e = (int)(idx >> 8);
    int t = (int)(idx & 255);
    int col = el[3*e+1], rel = el[3*e+2];
    atomicAdd(&agg[((size_t)col * RR + rel) * HH + t], m[idx]);
}

// ---------------------------------------------------------------------------
// nin[n] = [agg row (1792) | h row (256)]   (float4 copies)
// ---------------------------------------------------------------------------
__global__ void nin_concat_kernel(const float* __restrict__ agg, const float* __restrict__ h,
                                  float* __restrict__ nin) {
    size_t i = (size_t)blockIdx.x * blockDim.x + threadIdx.x;  // in float4 units
    if (i >= (size_t)NN * 512) return;
    int n = (int)(i / 512);
    int c4 = (int)(i % 512);
    float4 v = (c4 < 448) ? ((const float4*)(agg + (size_t)n * 1792))[c4]
                          : ((const float4*)(h + (size_t)n * 256))[c4 - 448];
    ((float4*)(nin + (size_t)n * 2048))[c4] = v;
}

// ---------------------------------------------------------------------------
// LayerNorm over H=256, one block per node.
// ---------------------------------------------------------------------------
__global__ void ln_kernel(const float* __restrict__ h2, const float* __restrict__ g,
                          const float* __restrict__ b, float* __restrict__ out) {
    int n = blockIdx.x;
    int t = threadIdx.x;
    float v = h2[(size_t)n * 256 + t];
    float a = v, sq = v * v;
#pragma unroll
    for (int o = 16; o > 0; o >>= 1) {
        a  += __shfl_down_sync(0xFFFFFFFFu, a, o);
        sq += __shfl_down_sync(0xFFFFFFFFu, sq, o);
    }
    __shared__ float s1[8], s2[8];
    if ((t & 31) == 0) { s1[t >> 5] = a; s2[t >> 5] = sq; }
    __syncthreads();
    __shared__ float mu, rs;
    if (t == 0) {
        float A = 0.f, B = 0.f;
#pragma unroll
        for (int i = 0; i < 8; i++) { A += s1[i]; B += s2[i]; }
        float m = A * (1.0f / 256.0f);
        mu = m;
        rs = rsqrtf(B * (1.0f / 256.0f) - m * m + EPSV);
    }
    __syncthreads();
    out[(size_t)n * 256 + t] = (v - mu) * rs * g[t] + b[t];
}

// ---------------------------------------------------------------------------
// x_out = x_in + xacc / max(cnt,1)
// ---------------------------------------------------------------------------
__global__ void x_final_kernel(const float* __restrict__ xin, const float* __restrict__ xacc,
                               const float* __restrict__ cnt, float* __restrict__ xout) {
    int i = blockIdx.x * blockDim.x + threadIdx.x;
    if (i >= NN * 12) return;
    int n = i / 12;
    xout[i] = xin[i] + xacc[i] / fmaxf(cnt[n], 1.0f);
}

// ---------------------------------------------------------------------------
// Host orchestration
// ---------------------------------------------------------------------------
extern "C" void kernel_launch(void* const* d_in, const int* in_sizes, int n_in,
                              void* d_out, int out_size) {
    // Identify first 6 tensors by unique element counts (robust to metadata ordering).
    const float* input  = nullptr;
    const float* coords = nullptr;
    const float* attr   = nullptr;
    const float* cw     = nullptr;
    const float* ew     = nullptr;
    const int*   el     = nullptr;
    for (int i = 0; i < 6; i++) {
        switch (in_sizes[i]) {
            case NN * HH:        input  = (const float*)d_in[i]; break;  // 2,560,000
            case NN * CC * 3:    coords = (const float*)d_in[i]; break;  // 120,000
            case NN * CC * CFD:  attr   = (const float*)d_in[i]; break;  // 640,000
            case NN * CC:        cw     = (const float*)d_in[i]; break;  // 40,000
            case EE:             ew     = (const float*)d_in[i]; break;  // 160,000
            case EE * 3:         el     = (const int*)  d_in[i]; break;  // 480,000
        }
    }
    // Params 6..20 are in the same relative order under both possible metadata orders.
    const float* W_rad = (const float*)d_in[6];
    const float* b_rad = (const float*)d_in[7];
    const float* W_e1  = (const float*)d_in[8];
    const float* b_e1  = (const float*)d_in[9];
    const float* W_e2  = (const float*)d_in[10];
    const float* b_e2  = (const float*)d_in[11];
    const float* W_c1  = (const float*)d_in[12];
    const float* b_c1  = (const float*)d_in[13];
    const float* W_c2  = (const float*)d_in[14];
    const float* W_n1  = (const float*)d_in[15];
    const float* b_n1  = (const float*)d_in[16];
    const float* W_n2  = (const float*)d_in[17];
    const float* b_n2  = (const float*)d_in[18];
    const float* ln_g  = (const float*)d_in[19];
    const float* ln_b  = (const float*)d_in[20];

    float* buf = nullptr;
    cudaGetSymbolAddress((void**)&buf, g_buf);

    float* g_ca   = buf + OFF_CA;
    float* g_min  = buf + OFF_MIN;
    float* g_m1   = buf + OFF_M1;
    float* g_m    = buf + OFF_M;
    float* g_phi  = buf + OFF_PHI;
    float* g_agg  = buf + OFF_AGG;
    float* g_nin  = buf + OFF_NINB;
    float* g_h1   = buf + OFF_H1;
    float* g_hbuf = buf + OFF_HBUF;
    float* g_xbuf = buf + OFF_XBUF;
    float* g_xacc = buf + OFF_XACC;
    float* g_cnt  = buf + OFF_CNT;

    // --- one-time per call: ca, cnt ---
    ca_kernel<<<(NN + 255) / 256, 256>>>(attr, cw, g_ca);
    zero_kernel<<<(NN + 255) / 256, 256>>>(g_cnt, (size_t)NN);
    cnt_kernel<<<(EE + 255) / 256, 256>>>(el, g_cnt);

    for (int l = 0; l < LL; l++) {
        const float* h_in = (l == 0) ? input  : g_hbuf;
        const float* x_in = (l == 0) ? coords : g_xbuf;
        float* h_out = (l == LL - 1) ? (float*)d_out : g_hbuf;
        float* x_out = (l == LL - 1) ? ((float*)d_out + (size_t)NN * HH) : g_xbuf;

        const float* Wr = W_rad + (size_t)l * 16 * 16;
        const float* br = b_rad + (size_t)l * 16;
        const float* We1 = W_e1 + (size_t)l * EIN * HH;
        const float* be1 = b_e1 + (size_t)l * HH;
        const float* We2 = W_e2 + (size_t)l * HH * HH;
        const float* be2 = b_e2 + (size_t)l * HH;
        const float* Wc1 = W_c1 + (size_t)l * HH * HH;
        const float* bc1 = b_c1 + (size_t)l * HH;
        const float* Wc2 = W_c2 + (size_t)l * HH * 16;
        const float* Wn1 = W_n1 + (size_t)l * NIN * HH;
        const float* bn1 = b_n1 + (size_t)l * HH;
        const float* Wn2 = W_n2 + (size_t)l * HH * HH;
        const float* bn2 = b_n2 + (size_t)l * HH;
        const float* lg  = ln_g + (size_t)l * HH;
        const float* lb  = ln_b + (size_t)l * HH;

        // Zero accumulators
        zero_kernel<<<((size_t)NN * RR * HH + 255) / 256, 256>>>(g_agg, (size_t)NN * RR * HH);
        zero_kernel<<<(NN * 12 + 255) / 256, 256>>>(g_xacc, (size_t)NN * 12);

        // Edge feature build (incl. radial MLP)
        edge_build_kernel<<<EE, 128>>>(h_in, x_in, el, cw, g_ca, Wr, br, g_min);

        // Edge MLPs
        sgemm_kernel<1><<<dim3(2, (EE + 127) / 128), 256>>>(g_min, We1, be1, nullptr, g_m1, EE, HH, EIN);
        sgemm_kernel<2><<<dim3(2, (EE + 127) / 128), 256>>>(g_m1, We2, be2, ew, g_m, EE, HH, HH);
        sgemm_kernel<1><<<dim3(2, (EE + 127) / 128), 256>>>(g_m, Wc1, bc1, nullptr, g_m1, EE, HH, HH);
        gemm_phi_kernel<<<(EE + 15) / 16, 256>>>(g_m1, Wc2, g_phi, EE);

        // Coordinate update scatter
        x_scatter_kernel<<<(EE + 7) / 8, 256>>>(x_in, el, g_phi, g_xacc);

        // Message aggregation scatter
        agg_scatter_kernel<<<(unsigned)(((size_t)EE * HH + 255) / 256), 256>>>(el, g_m, g_agg);

        // Node MLP
        nin_concat_kernel<<<(unsigned)(((size_t)NN * 512 + 255) / 256), 256>>>(g_agg, h_in, g_nin);
        sgemm_kernel<1><<<dim3(2, (NN + 127) / 128), 256>>>(g_nin, Wn1, bn1, nullptr, g_h1, NN, HH, NIN);
        sgemm_kernel<0><<<dim3(2, (NN + 127) / 128), 256>>>(g_h1, Wn2, bn2, nullptr, g_m, NN, HH, HH);
        ln_kernel<<<NN, 256>>>(g_m, lg, lb, h_out);

        // Coordinate finalize
        x_final_kernel<<<(NN * 12 + 255) / 256, 256>>>(x_in, g_xacc, g_cnt, x_out);
    }
}

// round 2
// speedup vs baseline: 2.3539x; 2.3539x over previous
#include <cuda_runtime.h>
#include <cstddef>
#include <cstdint>

#define NN 10000
#define EE 160000
#define RR 7
#define HH 256
#define LL 2
#define EPSV 1e-5f

#define OFF_CA    ((size_t)0)
#define OFF_HCA   (OFF_CA   + (size_t)NN*16)
#define OFF_WPQ   (OFF_HCA  + (size_t)NN*272)
#define OFF_PQ    (OFF_WPQ  + (size_t)272*512)
#define OFF_M1    (OFF_PQ   + (size_t)NN*512)
#define OFF_M     (OFF_M1   + (size_t)EE*HH)
#define OFF_PHI   (OFF_M    + (size_t)EE*HH)
#define OFF_AGG   (OFF_PHI  + (size_t)EE*16)
#define OFF_NIN   (OFF_AGG  + (size_t)NN*RR*HH)
#define OFF_H1    (OFF_NIN  + (size_t)NN*2048)
#define OFF_HBUF  (OFF_H1   + (size_t)NN*HH)
#define OFF_XBUF  (OFF_HBUF + (size_t)NN*HH)
#define OFF_XACC  (OFF_XBUF + (size_t)NN*12)
#define OFF_CNT   (OFF_XACC + (size_t)NN*12)
#define TOTAL_F   (OFF_CNT  + (size_t)NN)

__device__ float g_buf[TOTAL_F];

__device__ __forceinline__ float silu_f(float v) { return v / (1.0f + __expf(-v)); }

__device__ __forceinline__ unsigned f2tf32(float f) {
    unsigned u;
    asm("cvt.rna.tf32.f32 %0, %1;" : "=r"(u) : "f"(f));
    return u;
}
__device__ __forceinline__ float4 cvt4(float4 v) {
    return make_float4(__uint_as_float(f2tf32(v.x)), __uint_as_float(f2tf32(v.y)),
                       __uint_as_float(f2tf32(v.z)), __uint_as_float(f2tf32(v.w)));
}

__global__ void zero4_kernel(float4* __restrict__ p, size_t n4) {
    size_t i = (size_t)blockIdx.x * blockDim.x + threadIdx.x;
    if (i < n4) p[i] = make_float4(0.f, 0.f, 0.f, 0.f);
}

__global__ void ca_kernel(const float* __restrict__ attr, const float* __restrict__ cw,
                          float* __restrict__ ca) {
    int n = blockIdx.x * blockDim.x + threadIdx.x;
    if (n >= NN) return;
    float w0 = cw[n*4+0], w1 = cw[n*4+1], w2 = cw[n*4+2], w3 = cw[n*4+3];
    float inv = 1.0f / (w0 + w1 + w2 + w3);
    const float* a = attr + (size_t)n * 64;
#pragma unroll
    for (int f = 0; f < 16; f++)
        ca[n*16+f] = (a[f]*w0 + a[16+f]*w1 + a[32+f]*w2 + a[48+f]*w3) * inv;
}

__global__ void cnt_kernel(const int* __restrict__ el, float* __restrict__ cnt) {
    int e = blockIdx.x * blockDim.x + threadIdx.x;
    if (e >= EE) return;
    atomicAdd(&cnt[el[3*e]], 1.0f);
}

__global__ void hca_kernel(const float* __restrict__ h, const float* __restrict__ ca,
                           float* __restrict__ hca) {
    size_t i = (size_t)blockIdx.x * blockDim.x + threadIdx.x;
    if (i >= (size_t)NN * 68) return;
    int n = (int)(i / 68), c = (int)(i % 68);
    float4 v = (c < 64) ? ((const float4*)(h + (size_t)n * 256))[c]
                        : ((const float4*)(ca + (size_t)n * 16))[c - 64];
    ((float4*)(hca + (size_t)n * 272))[c] = v;
}

__global__ void wpq_kernel(const float* __restrict__ We1, float* __restrict__ Wpq) {
    int i = blockIdx.x * blockDim.x + threadIdx.x;
    if (i >= 272 * 512) return;
    int r = i / 512, c = i % 512;
    int j = (c < 256) ? c : c - 256;
    int k;
    if (c < 256) k = (r < 256) ? r : 528 + (r - 256);
    else         k = (r < 256) ? 256 + r : 544 + (r - 256);
    Wpq[i] = We1[(size_t)k * 256 + j];
}

template <int ACT>
__global__ __launch_bounds__(256, 1) void tf32_gemm_kernel(
    const float* __restrict__ A, const float* __restrict__ B,
    const float* __restrict__ bias, const float* __restrict__ rowscale,
    float* __restrict__ C, int M, int Nc, int K)
{
    __shared__ __align__(16) float As[2][128][20];
    __shared__ __align__(16) float Bs[2][16][136];
    int tid = threadIdx.x;
    int rowBase = blockIdx.y * 128, colBase = blockIdx.x * 128;

    int ar = tid >> 2,  ac = (tid & 3) * 4;
    int br = tid >> 5,  bc = (tid & 31) * 4;
    bool a0ok = (rowBase + ar)      < M;
    bool a1ok = (rowBase + ar + 64) < M;
    const float* Ap0 = A + (size_t)(rowBase + ar)      * K + ac;
    const float* Ap1 = A + (size_t)(rowBase + ar + 64) * K + ac;
    const float* Bp0 = B + (size_t)br       * Nc + colBase + bc;
    const float* Bp1 = B + (size_t)(br + 8) * Nc + colBase + bc;

    int warp = tid >> 5, lane = tid & 31;
    int wm = warp >> 1, wn = warp & 1;
    int gr = lane >> 2, gc = lane & 3;

    float c_[2][8][4];
#pragma unroll
    for (int i = 0; i < 2; i++)
#pragma unroll
        for (int j = 0; j < 8; j++)
#pragma unroll
            for (int q = 0; q < 4; q++) c_[i][j][q] = 0.0f;

    float4 ra0, ra1, rb0, rb1;
    const float4 z4 = make_float4(0.f, 0.f, 0.f, 0.f);

    ra0 = a0ok ? *(const float4*)Ap0 : z4;
    ra1 = a1ok ? *(const float4*)Ap1 : z4;
    rb0 = *(const float4*)Bp0;
    rb1 = *(const float4*)Bp1;
    Ap0 += 16; Ap1 += 16; Bp0 += (size_t)16 * Nc; Bp1 += (size_t)16 * Nc;
    *(float4*)&As[0][ar][ac]      = cvt4(ra0);
    *(float4*)&As[0][ar + 64][ac] = cvt4(ra1);
    *(float4*)&Bs[0][br][bc]      = cvt4(rb0);
    *(float4*)&Bs[0][br + 8][bc]  = cvt4(rb1);
    __syncthreads();

    int nt = K >> 4;
    for (int t = 0; t < nt; t++) {
        int cur = t & 1;
        bool more = (t + 1 < nt);
        if (more) {
            ra0 = a0ok ? *(const float4*)Ap0 : z4;
            ra1 = a1ok ? *(const float4*)Ap1 : z4;
            rb0 = *(const float4*)Bp0;
            rb1 = *(const float4*)Bp1;
            Ap0 += 16; Ap1 += 16; Bp0 += (size_t)16 * Nc; Bp1 += (size_t)16 * Nc;
        }
#pragma unroll
        for (int kk = 0; kk < 16; kk += 8) {
            unsigned af[2][4], bf[8][2];
#pragma unroll
            for (int i = 0; i < 2; i++) {
                int r0 = wm * 32 + i * 16 + gr;
                af[i][0] = __float_as_uint(As[cur][r0][kk + gc]);
                af[i][1] = __float_as_uint(As[cur][r0 + 8][kk + gc]);
                af[i][2] = __float_as_uint(As[cur][r0][kk + gc + 4]);
                af[i][3] = __float_as_uint(As[cur][r0 + 8][kk + gc + 4]);
            }
#pragma unroll
            for (int j = 0; j < 8; j++) {
                int cn = wn * 64 + j * 8 + gr;
                bf[j][0] = __float_as_uint(Bs[cur][kk + gc][cn]);
                bf[j][1] = __float_as_uint(Bs[cur][kk + gc + 4][cn]);
            }
#pragma unroll
            for (int i = 0; i < 2; i++)
#pragma unroll
                for (int j = 0; j < 8; j++) {
                    asm volatile(
                        "mma.sync.aligned.m16n8k8.row.col.f32.tf32.tf32.f32 "
                        "{%0,%1,%2,%3}, {%4,%5,%6,%7}, {%8,%9}, {%0,%1,%2,%3};\n"
                        : "+f"(c_[i][j][0]), "+f"(c_[i][j][1]),
                          "+f"(c_[i][j][2]), "+f"(c_[i][j][3])
                        : "r"(af[i][0]), "r"(af[i][1]), "r"(af[i][2]), "r"(af[i][3]),
                          "r"(bf[j][0]), "r"(bf[j][1]));
                }
        }
        if (more) {
            int nxt = 1 - cur;
            *(float4*)&As[nxt][ar][ac]      = cvt4(ra0);
            *(float4*)&As[nxt][ar + 64][ac] = cvt4(ra1);
            *(float4*)&Bs[nxt][br][bc]      = cvt4(rb0);
            *(float4*)&Bs[nxt][br + 8][bc]  = cvt4(rb1);
        }
        __syncthreads();
    }

#pragma unroll
    for (int i = 0; i < 2; i++) {
        int r0 = rowBase + wm * 32 + i * 16 + gr;
#pragma unroll
        for (int half = 0; half < 2; half++) {
            int r = r0 + half * 8;
            if (r >= M) continue;
            float sc = (ACT == 2) ? rowscale[r] : 1.0f;
#pragma unroll
            for (int j = 0; j < 8; j++) {
                int cn = colBase + wn * 64 + j * 8 + gc * 2;
                float b0 = bias ? bias[cn] : 0.f;
                float b1 = bias ? bias[cn + 1] : 0.f;
                float v0 = c_[i][j][half * 2 + 0] + b0;
                float v1 = c_[i][j][half * 2 + 1] + b1;
                if (ACT >= 1) { v0 = silu_f(v0); v1 = silu_f(v1); }
                if (ACT == 2) { v0 *= sc; v1 *= sc; }
                *(float2*)&C[(size_t)r * Nc + cn] = make_float2(v0, v1);
            }
        }
    }
}

// Edge fuse: m1[e] = silu(PQ[row][0:256] + PQ[col][256:512] + rad_feat@W1c + be1)
__global__ __launch_bounds__(256) void edge_fuse_kernel(
    const float* __restrict__ PQ,
    const float* __restrict__ x, const int* __restrict__ el,
    const float* __restrict__ cw,
    const float* __restrict__ Wrad, const float* __restrict__ brad,
    const float* __restrict__ W1c, const float* __restrict__ be1,
    float* __restrict__ m1)
{
    __shared__ __align__(16) float sW1c[16][256];
    __shared__ __align__(16) float sWrad[16][16];
    __shared__ float sbrad[16];
    __shared__ __align__(16) float sbe1[256];
    int tid = threadIdx.x;
    for (int i = tid; i < 16 * 256; i += 256) sW1c[i >> 8][i & 255] = W1c[i];
    for (int i = tid; i < 256; i += 256) { sbe1[i] = be1[i]; }
    if (tid < 256) { int r = tid >> 4, c = tid & 15; sWrad[r][c] = Wrad[tid]; }
    if (tid < 16) sbrad[tid] = brad[tid];
    __syncthreads();

    int warp = tid >> 5, lane = tid & 31;
#pragma unroll 1
    for (int ei = 0; ei < 8; ei++) {
        int e = blockIdx.x * 64 + warp * 8 + ei;
        int row = el[3*e], col = el[3*e+1];

        float rad = 0.f;
        if (lane < 16) {
            int i = lane >> 2, j = lane & 3;
            float dx = x[row*12 + i*3 + 0] - x[col*12 + j*3 + 0];
            float dy = x[row*12 + i*3 + 1] - x[col*12 + j*3 + 1];
            float dz = x[row*12 + i*3 + 2] - x[col*12 + j*3 + 2];
            rad = (dx*dx + dy*dy + dz*dz) * cw[row*4 + i] * cw[col*4 + j];
        }
        float acc = (lane < 16) ? sbrad[lane] : 0.f;
#pragma unroll
        for (int k = 0; k < 16; k++) {
            float rk = __shfl_sync(0xFFFFFFFFu, rad, k);
            acc = fmaf(rk, sWrad[k][lane & 15], acc);
        }
        float rf = silu_f(acc);

        const float4* Pr = (const float4*)(PQ + (size_t)row * 512);        // P part
        const float4* Qc = (const float4*)(PQ + (size_t)col * 512 + 256);  // Q part
        float4* Om = (float4*)(m1 + (size_t)e * 256);
#pragma unroll
        for (int half = 0; half < 2; half++) {
            int o4 = lane * 2 + half;
            float4 p = Pr[o4], q = Qc[o4];
            float4 b = ((const float4*)sbe1)[o4];
            float4 s = make_float4(p.x + q.x + b.x, p.y + q.y + b.y,
                                   p.z + q.z + b.z, p.w + q.w + b.w);
#pragma unroll
            for (int k = 0; k < 16; k++) {
                float rk = __shfl_sync(0xFFFFFFFFu, rf, k);
                float4 w = ((const float4*)&sW1c[k][0])[o4];
                s.x = fmaf(rk, w.x, s.x); s.y = fmaf(rk, w.y, s.y);
                s.z = fmaf(rk, w.z, s.z); s.w = fmaf(rk, w.w, s.w);
            }
            s.x = silu_f(s.x); s.y = silu_f(s.y); s.z = silu_f(s.z); s.w = silu_f(s.w);
            Om[o4] = s;
        }
    }
}

__global__ void gemm_phi_kernel(const float* __restrict__ A, const float* __restrict__ W,
                                float* __restrict__ out, int M) {
    __shared__ float Ws[256 * 16];
    __shared__ float Ar[16][256];
    int tid = threadIdx.x;
    for (int i = tid; i < 256 * 16; i += 256) Ws[i] = W[i];
    int e0 = blockIdx.x * 16;
    for (int i = tid; i < 16 * 64; i += 256) {
        int r = i / 64, c4 = i % 64;
        int e = e0 + r;
        float4 v = (e < M) ? ((const float4*)(A + (size_t)e * 256))[c4]
                           : make_float4(0.f, 0.f, 0.f, 0.f);
        *(float4*)&Ar[r][c4 * 4] = v;
    }
    __syncthreads();
    int r = tid >> 4, n = tid & 15;
    int e = e0 + r;
    if (e >= M) return;
    float acc = 0.0f;
#pragma unroll 16
    for (int k = 0; k < 256; k++) acc = fmaf(Ar[r][k], Ws[k * 16 + n], acc);
    out[(size_t)e * 16 + n] = acc;
}

__global__ void x_scatter_kernel(const float* __restrict__ x, const int* __restrict__ el,
                                 const float* __restrict__ phi, float* __restrict__ xacc) {
    int e = blockIdx.x * 8 + (threadIdx.x >> 5);
    if (e >= EE) return;
    int lane = threadIdx.x & 31;
    if (lane >= 12) return;
    int row = el[3*e], col = el[3*e+1];
    int i = lane / 3, d = lane % 3;
    float xr = x[row*12 + i*3 + d];
    float s = 0.0f;
#pragma unroll
    for (int j = 0; j < 4; j++) {
        float xd = xr - x[col*12 + j*3 + d];
        s = fmaf(xd, phi[(size_t)e*16 + i*4 + j], s);
    }
    atomicAdd(&xacc[row*12 + lane], s * 0.25f);
}

__global__ void agg_scatter_kernel(const int* __restrict__ el, const float* __restrict__ m,
                                   float* __restrict__ agg) {
    size_t idx = (size_t)blockIdx.x * blockDim.x + threadIdx.x;
    if (idx >= (size_t)EE * HH) return;
    int e = (int)(idx >> 8);
    int t = (int)(idx & 255);
    int col = el[3*e+1], rel = el[3*e+2];
    atomicAdd(&agg[((size_t)col * RR + rel) * HH + t], m[idx]);
}

__global__ void nin_concat_kernel(const float* __restrict__ agg, const float* __restrict__ h,
                                  float* __restrict__ nin) {
    size_t i = (size_t)blockIdx.x * blockDim.x + threadIdx.x;
    if (i >= (size_t)NN * 512) return;
    int n = (int)(i / 512);
    int c4 = (int)(i % 512);
    float4 v = (c4 < 448) ? ((const float4*)(agg + (size_t)n * 1792))[c4]
                          : ((const float4*)(h + (size_t)n * 256))[c4 - 448];
    ((float4*)(nin + (size_t)n * 2048))[c4] = v;
}

__global__ void ln_kernel(const float* __restrict__ h2, const float* __restrict__ g,
                          const float* __restrict__ b, float* __restrict__ out) {
    int n = blockIdx.x;
    int t = threadIdx.x;
    float v = h2[(size_t)n * 256 + t];
    float a = v, sq = v * v;
#pragma unroll
    for (int o = 16; o > 0; o >>= 1) {
        a  += __shfl_down_sync(0xFFFFFFFFu, a, o);
        sq += __shfl_down_sync(0xFFFFFFFFu, sq, o);
    }
    __shared__ float s1[8], s2[8];
    if ((t & 31) == 0) { s1[t >> 5] = a; s2[t >> 5] = sq; }
    __syncthreads();
    __shared__ float mu, rs;
    if (t == 0) {
        float A = 0.f, B = 0.f;
#pragma unroll
        for (int i = 0; i < 8; i++) { A += s1[i]; B += s2[i]; }
        float m = A * (1.0f / 256.0f);
        mu = m;
        rs = rsqrtf(B * (1.0f / 256.0f) - m * m + EPSV);
    }
    __syncthreads();
    out[(size_t)n * 256 + t] = (v - mu) * rs * g[t] + b[t];
}

__global__ void x_final_kernel(const float* __restrict__ xin, const float* __restrict__ xacc,
                               const float* __restrict__ cnt, float* __restrict__ xout) {
    int i = blockIdx.x * blockDim.x + threadIdx.x;
    if (i >= NN * 12) return;
    int n = i / 12;
    xout[i] = xin[i] + xacc[i] / fmaxf(cnt[n], 1.0f);
}

extern "C" void kernel_launch(void* const* d_in, const int* in_sizes, int n_in,
                              void* d_out, int out_size) {
    const float* input  = nullptr;
    const float* coords = nullptr;
    const float* attr   = nullptr;
    const float* cw     = nullptr;
    const float* ew     = nullptr;
    const int*   el     = nullptr;
    for (int i = 0; i < 6; i++) {
        switch (in_sizes[i]) {
            case NN * HH:     input  = (const float*)d_in[i]; break;
            case NN * 4 * 3:  coords = (const float*)d_in[i]; break;
            case NN * 4 * 16: attr   = (const float*)d_in[i]; break;
            case NN * 4:      cw     = (const float*)d_in[i]; break;
            case EE:          ew     = (const float*)d_in[i]; break;
            case EE * 3:      el     = (const int*)  d_in[i]; break;
        }
    }
    const float* W_rad = (const float*)d_in[6];
    const float* b_rad = (const float*)d_in[7];
    const float* W_e1  = (const float*)d_in[8];
    const float* b_e1  = (const float*)d_in[9];
    const float* W_e2  = (const float*)d_in[10];
    const float* b_e2  = (const float*)d_in[11];
    const float* W_c1  = (const float*)d_in[12];
    const float* b_c1  = (const float*)d_in[13];
    const float* W_c2  = (const float*)d_in[14];
    const float* W_n1  = (const float*)d_in[15];
    const float* b_n1  = (const float*)d_in[16];
    const float* W_n2  = (const float*)d_in[17];
    const float* b_n2  = (const float*)d_in[18];
    const float* ln_g  = (const float*)d_in[19];
    const float* ln_b  = (const float*)d_in[20];

    float* buf = nullptr;
    cudaGetSymbolAddress((void**)&buf, g_buf);

    float* g_ca   = buf + OFF_CA;
    float* g_hca  = buf + OFF_HCA;
    float* g_wpq  = buf + OFF_WPQ;
    float* g_pq   = buf + OFF_PQ;
    float* g_m1   = buf + OFF_M1;
    float* g_m    = buf + OFF_M;
    float* g_phi  = buf + OFF_PHI;
    float* g_agg  = buf + OFF_AGG;
    float* g_nin  = buf + OFF_NIN;
    float* g_h1   = buf + OFF_H1;
    float* g_hbuf = buf + OFF_HBUF;
    float* g_xbuf = buf + OFF_XBUF;
    float* g_xacc = buf + OFF_XACC;
    float* g_cnt  = buf + OFF_CNT;

    ca_kernel<<<(NN + 255) / 256, 256>>>(attr, cw, g_ca);
    zero4_kernel<<<(NN/4 + 255) / 256, 256>>>((float4*)g_cnt, (size_t)NN / 4);
    cnt_kernel<<<(EE + 255) / 256, 256>>>(el, g_cnt);

    for (int l = 0; l < LL; l++) {
        const float* h_in = (l == 0) ? input  : g_hbuf;
        const float* x_in = (l == 0) ? coords : g_xbuf;
        float* h_out = (l == LL - 1) ? (float*)d_out : g_hbuf;
        float* x_out = (l == LL - 1) ? ((float*)d_out + (size_t)NN * HH) : g_xbuf;

        const float* Wr  = W_rad + (size_t)l * 256;
        const float* br  = b_rad + (size_t)l * 16;
        const float* We1 = W_e1 + (size_t)l * 560 * 256;
        const float* be1 = b_e1 + (size_t)l * 256;
        const float* We2 = W_e2 + (size_t)l * 256 * 256;
        const float* be2 = b_e2 + (size_t)l * 256;
        const float* Wc1 = W_c1 + (size_t)l * 256 * 256;
        const float* bc1 = b_c1 + (size_t)l * 256;
        const float* Wc2 = W_c2 + (size_t)l * 256 * 16;
        const float* Wn1 = W_n1 + (size_t)l * 2048 * 256;
        const float* bn1 = b_n1 + (size_t)l * 256;
        const float* Wn2 = W_n2 + (size_t)l * 256 * 256;
        const float* bn2 = b_n2 + (size_t)l * 256;
        const float* lg  = ln_g + (size_t)l * 256;
        const float* lb  = ln_b + (size_t)l * 256;

        hca_kernel<<<(unsigned)(((size_t)NN * 68 + 255) / 256), 256>>>(h_in, g_ca, g_hca);
        wpq_kernel<<<(272 * 512 + 255) / 256, 256>>>(We1, g_wpq);
        tf32_gemm_kernel<0><<<dim3(4, (NN + 127) / 128), 256>>>(
            g_hca, g_wpq, nullptr, nullptr, g_pq, NN, 512, 272);

        zero4_kernel<<<(unsigned)(((size_t)NN*RR*HH/4 + 255) / 256), 256>>>((float4*)g_agg, (size_t)NN*RR*HH/4);
        zero4_kernel<<<(NN*12/4 + 255) / 256, 256>>>((float4*)g_xacc, (size_t)NN*12/4);

        edge_fuse_kernel<<<EE / 64, 256>>>(g_pq, x_in, el, cw,
                                           Wr, br, We1 + (size_t)512 * 256, be1, g_m1);

        tf32_gemm_kernel<2><<<dim3(2, EE / 128), 256>>>(g_m1, We2, be2, ew, g_m, EE, 256, 256);
        tf32_gemm_kernel<1><<<dim3(2, EE / 128), 256>>>(g_m, Wc1, bc1, nullptr, g_m1, EE, 256, 256);
        gemm_phi_kernel<<<EE / 16, 256>>>(g_m1, Wc2, g_phi, EE);

        x_scatter_kernel<<<EE / 8, 256>>>(x_in, el, g_phi, g_xacc);
        agg_scatter_kernel<<<(unsigned)(((size_t)EE * HH + 255) / 256), 256>>>(el, g_m, g_agg);

        nin_concat_kernel<<<(unsigned)(((size_t)NN * 512 + 255) / 256), 256>>>(g_agg, h_in, g_nin);
        tf32_gemm_kernel<1><<<dim3(2, (NN + 127) / 128), 256>>>(g_nin, Wn1, bn1, nullptr, g_h1, NN, 256, 2048);
        tf32_gemm_kernel<0><<<dim3(2, (NN + 127) / 128), 256>>>(g_h1, Wn2, bn2, nullptr, g_pq, NN, 256, 256);
        ln_kernel<<<NN, 256>>>(g_pq, lg, lb, h_out);

        x_final_kernel<<<(NN * 12 + 255) / 256, 256>>>(x_in, g_xacc, g_cnt, x_out);
    }
}

// round 3
// speedup vs baseline: 3.2610x; 1.3854x over previous
#include <cuda_runtime.h>
#include <cstddef>
#include <cstdint>

#define NN 10000
#define EE 160000
#define RR 7
#define HH 256
#define LL 2
#define EPSV 1e-5f

// ---------------- scratch ----------------
#define OFF_CA    ((size_t)0)                         // N*16
#define OFF_WPQ   (OFF_CA   + (size_t)NN*16)          // 272*512
#define OFF_PQ    (OFF_WPQ  + (size_t)272*512)        // N*512
#define OFF_M1    (OFF_PQ   + (size_t)NN*512)         // E*256
#define OFF_M     (OFF_M1   + (size_t)EE*HH)          // E*256
#define OFF_AGG   (OFF_M    + (size_t)EE*HH)          // N*R*H
#define OFF_H1    (OFF_AGG  + (size_t)NN*RR*HH)       // N*256
#define OFF_HBUF  (OFF_H1   + (size_t)NN*HH)          // N*256
#define OFF_XBUF  (OFF_HBUF + (size_t)NN*HH)          // N*12
#define OFF_XACC  (OFF_XBUF + (size_t)NN*12)          // N*12
#define OFF_CNT   (OFF_XACC + (size_t)NN*12)          // N
#define TOTAL_F   (OFF_CNT  + (size_t)NN)

__device__ float g_buf[TOTAL_F];

__device__ __forceinline__ float silu_f(float v) { return v / (1.0f + __expf(-v)); }

__device__ __forceinline__ unsigned f2tf32(float f) {
    unsigned u;
    asm("cvt.rna.tf32.f32 %0, %1;" : "=r"(u) : "f"(f));
    return u;
}

__device__ __forceinline__ void cp_async16(uint32_t dst, const void* src, bool p) {
    asm volatile("cp.async.cg.shared.global [%0], [%1], 16, %2;\n"
                 :: "r"(dst), "l"(src), "r"(p ? 16 : 0));
}
__device__ __forceinline__ void cp_commit() {
    asm volatile("cp.async.commit_group;\n");
}
template <int Np> __device__ __forceinline__ void cp_wait() {
    asm volatile("cp.async.wait_group %0;\n" :: "n"(Np));
}

// ---------------- small kernels ----------------
__global__ void zero4_kernel(float4* __restrict__ p, size_t n4) {
    size_t i = (size_t)blockIdx.x * blockDim.x + threadIdx.x;
    if (i < n4) p[i] = make_float4(0.f, 0.f, 0.f, 0.f);
}

__global__ void ca_kernel(const float* __restrict__ attr, const float* __restrict__ cw,
                          float* __restrict__ ca) {
    int n = blockIdx.x * blockDim.x + threadIdx.x;
    if (n >= NN) return;
    float w0 = cw[n*4+0], w1 = cw[n*4+1], w2 = cw[n*4+2], w3 = cw[n*4+3];
    float inv = 1.0f / (w0 + w1 + w2 + w3);
    const float* a = attr + (size_t)n * 64;
#pragma unroll
    for (int f = 0; f < 16; f++)
        ca[n*16+f] = (a[f]*w0 + a[16+f]*w1 + a[32+f]*w2 + a[48+f]*w3) * inv;
}

__global__ void cnt_kernel(const int* __restrict__ el, float* __restrict__ cnt) {
    int e = blockIdx.x * blockDim.x + threadIdx.x;
    if (e >= EE) return;
    atomicAdd(&cnt[el[3*e]], 1.0f);
}

__global__ void wpq_kernel(const float* __restrict__ We1, float* __restrict__ Wpq) {
    int i = blockIdx.x * blockDim.x + threadIdx.x;
    if (i >= 272 * 512) return;
    int r = i / 512, c = i % 512;
    int j = (c < 256) ? c : c - 256;
    int k;
    if (c < 256) k = (r < 256) ? r : 528 + (r - 256);
    else         k = (r < 256) ? 256 + r : 544 + (r - 256);
    Wpq[i] = We1[(size_t)k * 256 + j];
}

// ---------------- tf32 GEMM, cp.async 3-stage ----------------
// C(MxNc) = act(A'(MxK) @ B(KxNc) + bias)
// A' rows: cols [0,K1) from A (stride lda), cols [K1,K) from A2 (stride lda2).
// ACT: 0 none, 1 silu, 2 silu*rowscale. FUSE_AGG: scatter C rows into agg.
#define AS_STRIDE 28
#define BS_STRIDE 136
#define AS_SZ (128 * AS_STRIDE)
#define BS_SZ (16 * BS_STRIDE)
#define GEMM_SMEM_BYTES (3 * (AS_SZ + BS_SZ) * 4)

template <int ACT, bool FUSE_AGG>
__global__ __launch_bounds__(256) void tf32_gemm_kernel(
    const float* __restrict__ A, int lda,
    const float* __restrict__ A2, int lda2, int K1,
    const float* __restrict__ B,
    const float* __restrict__ bias, const float* __restrict__ rowscale,
    float* __restrict__ C,
    const int* __restrict__ el, float* __restrict__ agg,
    int M, int Nc, int K)
{
    extern __shared__ float smem[];
    float* AsBase = smem;
    float* BsBase = smem + 3 * AS_SZ;
    uint32_t su = (uint32_t)__cvta_generic_to_shared(smem);

    int tid = threadIdx.x;
    int rowBase = blockIdx.y * 128, colBase = blockIdx.x * 128;
    int warp = tid >> 5, lane = tid & 31;
    int wm = warp >> 1, wn = warp & 1;
    int gr = lane >> 2, gc = lane & 3;

    float c_[2][8][4];
#pragma unroll
    for (int i = 0; i < 2; i++)
#pragma unroll
        for (int j = 0; j < 8; j++)
#pragma unroll
            for (int q = 0; q < 4; q++) c_[i][j][q] = 0.0f;

    int nt = K >> 4;

    // stage loader
    auto load_stage = [&](int s, int t) {
        int k0 = t << 4;
#pragma unroll
        for (int c = 0; c < 2; c++) {
            int idx = tid + c * 256;
            int arow = idx >> 2, ach = (idx & 3) * 4;
            int r = rowBase + arow;
            int k = k0 + ach;
            const float* src = (k >= K1) ? (A2 + (size_t)r * lda2 + (k - K1))
                                         : (A  + (size_t)r * lda  + k);
            cp_async16(su + (uint32_t)(s * AS_SZ + arow * AS_STRIDE + ach) * 4, src, r < M);
        }
#pragma unroll
        for (int c = 0; c < 2; c++) {
            int idx = tid + c * 256;
            int brow = idx >> 5, bch = (idx & 31) * 4;
            const float* src = B + (size_t)(k0 + brow) * Nc + colBase + bch;
            cp_async16(su + (uint32_t)(3 * AS_SZ + s * BS_SZ + brow * BS_STRIDE + bch) * 4, src, true);
        }
        cp_commit();
    };

    // prologue: stages 0,1
    load_stage(0, 0);
    if (1 < nt) load_stage(1, 1); else cp_commit();

    for (int t = 0; t < nt; t++) {
        cp_wait<1>();
        __syncthreads();
        int cur = t % 3;
        if (t + 2 < nt) load_stage((t + 2) % 3, t + 2);
        const float* As = AsBase + cur * AS_SZ;
        const float* Bs = BsBase + cur * BS_SZ;
#pragma unroll
        for (int kk = 0; kk < 16; kk += 8) {
            unsigned af[2][4], bf[8][2];
#pragma unroll
            for (int i = 0; i < 2; i++) {
                int r0 = wm * 32 + i * 16 + gr;
                af[i][0] = f2tf32(As[r0 * AS_STRIDE + kk + gc]);
                af[i][1] = f2tf32(As[(r0 + 8) * AS_STRIDE + kk + gc]);
                af[i][2] = f2tf32(As[r0 * AS_STRIDE + kk + gc + 4]);
                af[i][3] = f2tf32(As[(r0 + 8) * AS_STRIDE + kk + gc + 4]);
            }
#pragma unroll
            for (int j = 0; j < 8; j++) {
                int cn = wn * 64 + j * 8 + gr;
                bf[j][0] = f2tf32(Bs[(kk + gc) * BS_STRIDE + cn]);
                bf[j][1] = f2tf32(Bs[(kk + gc + 4) * BS_STRIDE + cn]);
            }
#pragma unroll
            for (int i = 0; i < 2; i++)
#pragma unroll
                for (int j = 0; j < 8; j++) {
                    asm volatile(
                        "mma.sync.aligned.m16n8k8.row.col.f32.tf32.tf32.f32 "
                        "{%0,%1,%2,%3}, {%4,%5,%6,%7}, {%8,%9}, {%0,%1,%2,%3};\n"
                        : "+f"(c_[i][j][0]), "+f"(c_[i][j][1]),
                          "+f"(c_[i][j][2]), "+f"(c_[i][j][3])
                        : "r"(af[i][0]), "r"(af[i][1]), "r"(af[i][2]), "r"(af[i][3]),
                          "r"(bf[j][0]), "r"(bf[j][1]));
                }
        }
        __syncthreads();
    }

    // epilogue
#pragma unroll
    for (int i = 0; i < 2; i++) {
        int rr0 = rowBase + wm * 32 + i * 16 + gr;
#pragma unroll
        for (int half = 0; half < 2; half++) {
            int r = rr0 + half * 8;
            if (r >= M) continue;
            float sc = (ACT == 2) ? rowscale[r] : 1.0f;
            size_t ab = 0;
            if (FUSE_AGG) {
                int cc = el[3 * r + 1], rl = el[3 * r + 2];
                ab = ((size_t)cc * RR + rl) * 256;
            }
#pragma unroll
            for (int j = 0; j < 8; j++) {
                int cn = colBase + wn * 64 + j * 8 + gc * 2;
                float b0 = bias ? bias[cn] : 0.f;
                float b1 = bias ? bias[cn + 1] : 0.f;
                float v0 = c_[i][j][half * 2 + 0] + b0;
                float v1 = c_[i][j][half * 2 + 1] + b1;
                if (ACT >= 1) { v0 = silu_f(v0); v1 = silu_f(v1); }
                if (ACT == 2) { v0 *= sc; v1 *= sc; }
                *(float2*)&C[(size_t)r * Nc + cn] = make_float2(v0, v1);
                if (FUSE_AGG) {
                    atomicAdd(&agg[ab + cn], v0);
                    atomicAdd(&agg[ab + cn + 1], v1);
                }
            }
        }
    }
}

// ---------------- edge fuse ----------------
// m1[e] = silu(PQ[row][0:256] + PQ[col][256:512] + rad_feat@W1c + be1)
__global__ __launch_bounds__(256) void edge_fuse_kernel(
    const float* __restrict__ PQ,
    const float* __restrict__ x, const int* __restrict__ el,
    const float* __restrict__ cw,
    const float* __restrict__ Wrad, const float* __restrict__ brad,
    const float* __restrict__ W1c, const float* __restrict__ be1,
    float* __restrict__ m1)
{
    __shared__ __align__(16) float sW1c[16][256];
    __shared__ float sWrad[16][16];
    __shared__ float sbrad[16];
    __shared__ __align__(16) float sbe1[256];
    __shared__ float srad[8][16];
    __shared__ float srf[8][16];
    int tid = threadIdx.x;
    for (int i = tid; i < 16 * 256; i += 256) sW1c[i >> 8][i & 255] = W1c[i];
    sbe1[tid] = be1[tid];
    { int r = tid >> 4, c = tid & 15; sWrad[r][c] = Wrad[tid]; }
    if (tid < 16) sbrad[tid] = brad[tid];
    __syncthreads();

    int warp = tid >> 5, lane = tid & 31;
#pragma unroll 1
    for (int ei = 0; ei < 8; ei++) {
        int e = blockIdx.x * 64 + warp * 8 + ei;
        int row = el[3*e], col = el[3*e+1];

        if (lane < 16) {
            int i = lane >> 2, j = lane & 3;
            float dx = x[row*12 + i*3 + 0] - x[col*12 + j*3 + 0];
            float dy = x[row*12 + i*3 + 1] - x[col*12 + j*3 + 1];
            float dz = x[row*12 + i*3 + 2] - x[col*12 + j*3 + 2];
            srad[warp][lane] = (dx*dx + dy*dy + dz*dz) * cw[row*4 + i] * cw[col*4 + j];
        }
        __syncwarp();
        if (lane < 16) {
            float acc = sbrad[lane];
#pragma unroll
            for (int k = 0; k < 16; k++) acc = fmaf(srad[warp][k], sWrad[k][lane], acc);
            srf[warp][lane] = silu_f(acc);
        }
        __syncwarp();

        const float4* Pr = (const float4*)(PQ + (size_t)row * 512);
        const float4* Qc = (const float4*)(PQ + (size_t)col * 512 + 256);
        float4* Om = (float4*)(m1 + (size_t)e * 256);
#pragma unroll
        for (int half = 0; half < 2; half++) {
            int o4 = lane * 2 + half;
            float4 p = Pr[o4], q = Qc[o4];
            float4 b = ((const float4*)sbe1)[o4];
            float4 s = make_float4(p.x + q.x + b.x, p.y + q.y + b.y,
                                   p.z + q.z + b.z, p.w + q.w + b.w);
#pragma unroll
            for (int k = 0; k < 16; k++) {
                float rk = srf[warp][k];
                float4 w = ((const float4*)&sW1c[k][0])[o4];
                s.x = fmaf(rk, w.x, s.x); s.y = fmaf(rk, w.y, s.y);
                s.z = fmaf(rk, w.z, s.z); s.w = fmaf(rk, w.w, s.w);
            }
            s.x = silu_f(s.x); s.y = silu_f(s.y); s.z = silu_f(s.z); s.w = silu_f(s.w);
            Om[o4] = s;
        }
        __syncwarp();
    }
}

// ---------------- phi + x scatter fused ----------------
// phi[e][n] = t1[e] @ Wc2[:,n]; then trans reduce over j and atomic into xacc.
__global__ __launch_bounds__(256) void phi_x_kernel(
    const float* __restrict__ A, const float* __restrict__ W,
    const float* __restrict__ x, const int* __restrict__ el,
    float* __restrict__ xacc)
{
    __shared__ float Ws[256 * 16];
    __shared__ float Ar[16][256];
    int tid = threadIdx.x;
    for (int i = tid; i < 256 * 16; i += 256) Ws[i] = W[i];
    int e0 = blockIdx.x * 16;
    for (int i = tid; i < 16 * 64; i += 256) {
        int r = i / 64, c4 = i % 64;
        float4 v = ((const float4*)(A + (size_t)(e0 + r) * 256))[c4];
        *(float4*)&Ar[r][c4 * 4] = v;
    }
    __syncthreads();
    int r = tid >> 4, n = tid & 15;
    int e = e0 + r;
    float acc = 0.0f;
#pragma unroll 16
    for (int k = 0; k < 256; k++) acc = fmaf(Ar[r][k], Ws[k * 16 + n], acc);

    int i = n >> 2, j = n & 3;
    int row = el[3*e], col = el[3*e+1];
    float c0 = (x[row*12 + i*3 + 0] - x[col*12 + j*3 + 0]) * acc;
    float c1 = (x[row*12 + i*3 + 1] - x[col*12 + j*3 + 1]) * acc;
    float c2 = (x[row*12 + i*3 + 2] - x[col*12 + j*3 + 2]) * acc;
    const unsigned mask = 0xFFFFFFFFu;
    c0 += __shfl_xor_sync(mask, c0, 1); c0 += __shfl_xor_sync(mask, c0, 2);
    c1 += __shfl_xor_sync(mask, c1, 1); c1 += __shfl_xor_sync(mask, c1, 2);
    c2 += __shfl_xor_sync(mask, c2, 1); c2 += __shfl_xor_sync(mask, c2, 2);
    if (j == 0) {
        atomicAdd(&xacc[row*12 + i*3 + 0], c0 * 0.25f);
        atomicAdd(&xacc[row*12 + i*3 + 1], c1 * 0.25f);
        atomicAdd(&xacc[row*12 + i*3 + 2], c2 * 0.25f);
    }
}

// ---------------- layernorm ----------------
__global__ void ln_kernel(const float* __restrict__ h2, const float* __restrict__ g,
                          const float* __restrict__ b, float* __restrict__ out) {
    int n = blockIdx.x;
    int t = threadIdx.x;
    float v = h2[(size_t)n * 256 + t];
    float a = v, sq = v * v;
#pragma unroll
    for (int o = 16; o > 0; o >>= 1) {
        a  += __shfl_down_sync(0xFFFFFFFFu, a, o);
        sq += __shfl_down_sync(0xFFFFFFFFu, sq, o);
    }
    __shared__ float s1[8], s2[8];
    if ((t & 31) == 0) { s1[t >> 5] = a; s2[t >> 5] = sq; }
    __syncthreads();
    __shared__ float mu, rs;
    if (t == 0) {
        float A = 0.f, B = 0.f;
#pragma unroll
        for (int i = 0; i < 8; i++) { A += s1[i]; B += s2[i]; }
        float m = A * (1.0f / 256.0f);
        mu = m;
        rs = rsqrtf(B * (1.0f / 256.0f) - m * m + EPSV);
    }
    __syncthreads();
    out[(size_t)n * 256 + t] = (v - mu) * rs * g[t] + b[t];
}

__global__ void x_final_kernel(const float* __restrict__ xin, const float* __restrict__ xacc,
                               const float* __restrict__ cnt, float* __restrict__ xout) {
    int i = blockIdx.x * blockDim.x + threadIdx.x;
    if (i >= NN * 12) return;
    int n = i / 12;
    xout[i] = xin[i] + xacc[i] / fmaxf(cnt[n], 1.0f);
}

// ---------------- host ----------------
extern "C" void kernel_launch(void* const* d_in, const int* in_sizes, int n_in,
                              void* d_out, int out_size) {
    const float* input  = nullptr;
    const float* coords = nullptr;
    const float* attr   = nullptr;
    const float* cw     = nullptr;
    const float* ew     = nullptr;
    const int*   el     = nullptr;
    for (int i = 0; i < 6; i++) {
        switch (in_sizes[i]) {
            case NN * HH:     input  = (const float*)d_in[i]; break;
            case NN * 4 * 3:  coords = (const float*)d_in[i]; break;
            case NN * 4 * 16: attr   = (const float*)d_in[i]; break;
            case NN * 4:      cw     = (const float*)d_in[i]; break;
            case EE:          ew     = (const float*)d_in[i]; break;
            case EE * 3:      el     = (const int*)  d_in[i]; break;
        }
    }
    const float* W_rad = (const float*)d_in[6];
    const float* b_rad = (const float*)d_in[7];
    const float* W_e1  = (const float*)d_in[8];
    const float* b_e1  = (const float*)d_in[9];
    const float* W_e2  = (const float*)d_in[10];
    const float* b_e2  = (const float*)d_in[11];
    const float* W_c1  = (const float*)d_in[12];
    const float* b_c1  = (const float*)d_in[13];
    const float* W_c2  = (const float*)d_in[14];
    const float* W_n1  = (const float*)d_in[15];
    const float* b_n1  = (const float*)d_in[16];
    const float* W_n2  = (const float*)d_in[17];
    const float* b_n2  = (const float*)d_in[18];
    const float* ln_g  = (const float*)d_in[19];
    const float* ln_b  = (const float*)d_in[20];

    float* buf = nullptr;
    cudaGetSymbolAddress((void**)&buf, g_buf);

    float* g_ca   = buf + OFF_CA;
    float* g_wpq  = buf + OFF_WPQ;
    float* g_pq   = buf + OFF_PQ;
    float* g_m1   = buf + OFF_M1;
    float* g_m    = buf + OFF_M;
    float* g_agg  = buf + OFF_AGG;
    float* g_h1   = buf + OFF_H1;
    float* g_hbuf = buf + OFF_HBUF;
    float* g_xbuf = buf + OFF_XBUF;
    float* g_xacc = buf + OFF_XACC;
    float* g_cnt  = buf + OFF_CNT;

    cudaFuncSetAttribute(tf32_gemm_kernel<0, false>,
                         cudaFuncAttributeMaxDynamicSharedMemorySize, GEMM_SMEM_BYTES);
    cudaFuncSetAttribute(tf32_gemm_kernel<1, false>,
                         cudaFuncAttributeMaxDynamicSharedMemorySize, GEMM_SMEM_BYTES);
    cudaFuncSetAttribute(tf32_gemm_kernel<2, true>,
                         cudaFuncAttributeMaxDynamicSharedMemorySize, GEMM_SMEM_BYTES);

    const int KBIG = 1 << 30;

    ca_kernel<<<(NN + 255) / 256, 256>>>(attr, cw, g_ca);
    zero4_kernel<<<(NN/4 + 255) / 256, 256>>>((float4*)g_cnt, (size_t)NN / 4);
    cnt_kernel<<<(EE + 255) / 256, 256>>>(el, g_cnt);

    for (int l = 0; l < LL; l++) {
        const float* h_in = (l == 0) ? input  : g_hbuf;
        const float* x_in = (l == 0) ? coords : g_xbuf;
        float* h_out = (l == LL - 1) ? (float*)d_out : g_hbuf;
        float* x_out = (l == LL - 1) ? ((float*)d_out + (size_t)NN * HH) : g_xbuf;

        const float* Wr  = W_rad + (size_t)l * 256;
        const float* br  = b_rad + (size_t)l * 16;
        const float* We1 = W_e1 + (size_t)l * 560 * 256;
        const float* be1 = b_e1 + (size_t)l * 256;
        const float* We2 = W_e2 + (size_t)l * 256 * 256;
        const float* be2 = b_e2 + (size_t)l * 256;
        const float* Wc1 = W_c1 + (size_t)l * 256 * 256;
        const float* bc1 = b_c1 + (size_t)l * 256;
        const float* Wc2 = W_c2 + (size_t)l * 256 * 16;
        const float* Wn1 = W_n1 + (size_t)l * 2048 * 256;
        const float* bn1 = b_n1 + (size_t)l * 256;
        const float* Wn2 = W_n2 + (size_t)l * 256 * 256;
        const float* bn2 = b_n2 + (size_t)l * 256;
        const float* lg  = ln_g + (size_t)l * 256;
        const float* lb  = ln_b + (size_t)l * 256;

        // PQ = [h|ca] @ Wpq  (N x 512), dual-source A
        wpq_kernel<<<(272 * 512 + 255) / 256, 256>>>(We1, g_wpq);
        tf32_gemm_kernel<0, false><<<dim3(4, (NN + 127) / 128), 256, GEMM_SMEM_BYTES>>>(
            h_in, 256, g_ca, 16, 256,
            g_wpq, nullptr, nullptr, g_pq, nullptr, nullptr, NN, 512, 272);

        zero4_kernel<<<(unsigned)(((size_t)NN*RR*HH/4 + 255) / 256), 256>>>(
            (float4*)g_agg, (size_t)NN*RR*HH/4);
        zero4_kernel<<<(NN*12/4 + 255) / 256, 256>>>((float4*)g_xacc, (size_t)NN*12/4);

        // m1 = silu(P[row]+Q[col]+rad_feat@W1c+be1)
        edge_fuse_kernel<<<EE / 64, 256>>>(g_pq, x_in, el, cw,
                                           Wr, br, We1 + (size_t)512 * 256, be1, g_m1);

        // m = silu(m1@We2+be2)*ew, fused agg scatter
        tf32_gemm_kernel<2, true><<<dim3(2, EE / 128), 256, GEMM_SMEM_BYTES>>>(
            g_m1, 256, nullptr, 0, KBIG,
            We2, be2, ew, g_m, el, g_agg, EE, 256, 256);

        // t1 = silu(m@Wc1+bc1)
        tf32_gemm_kernel<1, false><<<dim3(2, EE / 128), 256, GEMM_SMEM_BYTES>>>(
            g_m, 256, nullptr, 0, KBIG,
            Wc1, bc1, nullptr, g_m1, nullptr, nullptr, EE, 256, 256);

        // phi + x scatter
        phi_x_kernel<<<EE / 16, 256>>>(g_m1, Wc2, x_in, el, g_xacc);

        // h1 = silu([agg|h]@Wn1+bn1), dual-source A
        tf32_gemm_kernel<1, false><<<dim3(2, (NN + 127) / 128), 256, GEMM_SMEM_BYTES>>>(
            g_agg, 1792, h_in, 256, 1792,
            Wn1, bn1, nullptr, g_h1, nullptr, nullptr, NN, 256, 2048);

        // h2 = h1@Wn2+bn2
        tf32_gemm_kernel<0, false><<<dim3(2, (NN + 127) / 128), 256, GEMM_SMEM_BYTES>>>(
            g_h1, 256, nullptr, 0, KBIG,
            Wn2, bn2, nullptr, g_pq, nullptr, nullptr, NN, 256, 256);

        ln_kernel<<<NN, 256>>>(g_pq, lg, lb, h_out);
        x_final_kernel<<<(NN * 12 + 255) / 256, 256>>>(x_in, g_xacc, g_cnt, x_out);
    }
}

// round 4
// speedup vs baseline: 3.3893x; 1.0393x over previous
#include <cuda_runtime.h>
#include <cstddef>
#include <cstdint>

#define NN 10000
#define EE 160000
#define RR 7
#define HH 256
#define LL 2
#define EPSV 1e-5f

// ---------------- scratch ----------------
#define OFF_CA    ((size_t)0)                         // N*16
#define OFF_WPQ   (OFF_CA   + (size_t)NN*16)          // 272*512
#define OFF_PQ    (OFF_WPQ  + (size_t)272*512)        // N*512
#define OFF_M1    (OFF_PQ   + (size_t)NN*512)         // E*256
#define OFF_M     (OFF_M1   + (size_t)EE*HH)          // E*256
#define OFF_AGG   (OFF_M    + (size_t)EE*HH)          // N*R*H
#define OFF_H1    (OFF_AGG  + (size_t)NN*RR*HH)       // N*256
#define OFF_HBUF  (OFF_H1   + (size_t)NN*HH)          // N*256
#define OFF_XBUF  (OFF_HBUF + (size_t)NN*HH)          // N*12
#define OFF_XACC  (OFF_XBUF + (size_t)NN*12)          // N*12
#define OFF_CNT   (OFF_XACC + (size_t)NN*12)          // N
#define OFF_WE2T  (OFF_CNT  + (size_t)NN)             // 65536
#define OFF_WC1T  (OFF_WE2T + (size_t)65536)          // 65536
#define OFF_WN2T  (OFF_WC1T + (size_t)65536)          // 65536
#define OFF_WN1T  (OFF_WN2T + (size_t)65536)          // 524288
#define TOTAL_F   (OFF_WN1T + (size_t)524288)

__device__ float g_buf[TOTAL_F];

__device__ __forceinline__ float silu_f(float v) { return v / (1.0f + __expf(-v)); }

__device__ __forceinline__ unsigned f2tf32(float f) {
    unsigned u;
    asm("cvt.rna.tf32.f32 %0, %1;" : "=r"(u) : "f"(f));
    return u;
}
__device__ __forceinline__ float tf32r(float v) { return __uint_as_float(f2tf32(v)); }

__device__ __forceinline__ void cp_async16(uint32_t dst, const void* src, bool p) {
    asm volatile("cp.async.cg.shared.global [%0], [%1], 16, %2;\n"
                 :: "r"(dst), "l"(src), "r"(p ? 16 : 0));
}
__device__ __forceinline__ void cp_commit() {
    asm volatile("cp.async.commit_group;\n");
}
template <int Np> __device__ __forceinline__ void cp_wait() {
    asm volatile("cp.async.wait_group %0;\n" :: "n"(Np));
}

// ---------------- small kernels ----------------
__global__ void zero4_kernel(float4* __restrict__ p, size_t n4) {
    size_t i = (size_t)blockIdx.x * blockDim.x + threadIdx.x;
    if (i < n4) p[i] = make_float4(0.f, 0.f, 0.f, 0.f);
}

__global__ void ca_kernel(const float* __restrict__ attr, const float* __restrict__ cw,
                          float* __restrict__ ca) {
    int n = blockIdx.x * blockDim.x + threadIdx.x;
    if (n >= NN) return;
    float w0 = cw[n*4+0], w1 = cw[n*4+1], w2 = cw[n*4+2], w3 = cw[n*4+3];
    float inv = 1.0f / (w0 + w1 + w2 + w3);
    const float* a = attr + (size_t)n * 64;
#pragma unroll
    for (int f = 0; f < 16; f++)
        ca[n*16+f] = (a[f]*w0 + a[16+f]*w1 + a[32+f]*w2 + a[48+f]*w3) * inv;
}

__global__ void cnt_kernel(const int* __restrict__ el, float* __restrict__ cnt) {
    int e = blockIdx.x * blockDim.x + threadIdx.x;
    if (e >= EE) return;
    atomicAdd(&cnt[el[3*e]], 1.0f);
}

// Wpq pack (tf32-rounded)
__global__ void wpq_kernel(const float* __restrict__ We1, float* __restrict__ Wpq) {
    int i = blockIdx.x * blockDim.x + threadIdx.x;
    if (i >= 272 * 512) return;
    int r = i / 512, c = i % 512;
    int j = (c < 256) ? c : c - 256;
    int k;
    if (c < 256) k = (r < 256) ? r : 528 + (r - 256);
    else         k = (r < 256) ? 256 + r : 544 + (r - 256);
    Wpq[i] = tf32r(We1[(size_t)k * 256 + j]);
}

// tf32-round the other weight matrices (per layer). total = 3*65536 + 524288
__global__ void wprep_kernel(const float* __restrict__ We2, const float* __restrict__ Wc1,
                             const float* __restrict__ Wn1, const float* __restrict__ Wn2,
                             float* __restrict__ dWe2, float* __restrict__ dWc1,
                             float* __restrict__ dWn1, float* __restrict__ dWn2) {
    int i = blockIdx.x * blockDim.x + threadIdx.x;
    if (i < 65536)            dWe2[i]          = tf32r(We2[i]);
    else if (i < 131072)      dWc1[i - 65536]  = tf32r(Wc1[i - 65536]);
    else if (i < 196608)      dWn2[i - 131072] = tf32r(Wn2[i - 131072]);
    else if (i < 720896)      dWn1[i - 196608] = tf32r(Wn1[i - 196608]);
}

// ---------------- tf32 GEMM, cp.async 4-stage ----------------
// C(MxNc) = act(A'(MxK) @ B(KxNc) + bias); A' cols [0,K1) from A, rest from A2.
// B must be pre-rounded to tf32. CVT_A: round A-fragments in-loop.
// OUT_TF32: round C values before store (and before agg atomics).
#define AS_STRIDE 28
#define BS_STRIDE 136
#define AS_SZ (128 * AS_STRIDE)
#define BS_SZ (16 * BS_STRIDE)
#define NSTG 4
#define GEMM_SMEM_BYTES (NSTG * (AS_SZ + BS_SZ) * 4)

template <int ACT, bool FUSE_AGG, bool CVT_A, bool OUT_TF32>
__global__ __launch_bounds__(256) void tf32_gemm_kernel(
    const float* __restrict__ A, int lda,
    const float* __restrict__ A2, int lda2, int K1,
    const float* __restrict__ B,
    const float* __restrict__ bias, const float* __restrict__ rowscale,
    float* __restrict__ C,
    const int* __restrict__ el, float* __restrict__ agg,
    int M, int Nc, int K)
{
    extern __shared__ float smem[];
    float* AsBase = smem;
    float* BsBase = smem + NSTG * AS_SZ;
    uint32_t su = (uint32_t)__cvta_generic_to_shared(smem);

    int tid = threadIdx.x;
    int rowBase = blockIdx.y * 128, colBase = blockIdx.x * 128;
    int warp = tid >> 5, lane = tid & 31;
    int wm = warp >> 1, wn = warp & 1;
    int gr = lane >> 2, gc = lane & 3;

    float c_[2][8][4];
#pragma unroll
    for (int i = 0; i < 2; i++)
#pragma unroll
        for (int j = 0; j < 8; j++)
#pragma unroll
            for (int q = 0; q < 4; q++) c_[i][j][q] = 0.0f;

    int nt = K >> 4;

    auto load_stage = [&](int s, int t) {
        int k0 = t << 4;
#pragma unroll
        for (int c = 0; c < 2; c++) {
            int idx = tid + c * 256;
            int arow = idx >> 2, ach = (idx & 3) * 4;
            int r = rowBase + arow;
            int k = k0 + ach;
            const float* src = (k >= K1) ? (A2 + (size_t)r * lda2 + (k - K1))
                                         : (A  + (size_t)r * lda  + k);
            cp_async16(su + (uint32_t)(s * AS_SZ + arow * AS_STRIDE + ach) * 4, src, r < M);
        }
#pragma unroll
        for (int c = 0; c < 2; c++) {
            int idx = tid + c * 256;
            int brow = idx >> 5, bch = (idx & 31) * 4;
            const float* src = B + (size_t)(k0 + brow) * Nc + colBase + bch;
            cp_async16(su + (uint32_t)(NSTG * AS_SZ + s * BS_SZ + brow * BS_STRIDE + bch) * 4, src, true);
        }
        cp_commit();
    };

    // prologue: commit NSTG-1 groups (empty if past end)
#pragma unroll
    for (int s = 0; s < NSTG - 1; s++) {
        if (s < nt) load_stage(s, s); else cp_commit();
    }

    for (int t = 0; t < nt; t++) {
        cp_wait<NSTG - 2>();
        __syncthreads();
        int cur = t % NSTG;
        if (t + NSTG - 1 < nt) load_stage((t + NSTG - 1) % NSTG, t + NSTG - 1);
        else cp_commit();
        const float* As = AsBase + cur * AS_SZ;
        const float* Bs = BsBase + cur * BS_SZ;
#pragma unroll
        for (int kk = 0; kk < 16; kk += 8) {
            unsigned af[2][4], bf[8][2];
#pragma unroll
            for (int i = 0; i < 2; i++) {
                int r0 = wm * 32 + i * 16 + gr;
                float a0 = As[r0 * AS_STRIDE + kk + gc];
                float a1 = As[(r0 + 8) * AS_STRIDE + kk + gc];
                float a2 = As[r0 * AS_STRIDE + kk + gc + 4];
                float a3 = As[(r0 + 8) * AS_STRIDE + kk + gc + 4];
                if (CVT_A) {
                    af[i][0] = f2tf32(a0); af[i][1] = f2tf32(a1);
                    af[i][2] = f2tf32(a2); af[i][3] = f2tf32(a3);
                } else {
                    af[i][0] = __float_as_uint(a0); af[i][1] = __float_as_uint(a1);
                    af[i][2] = __float_as_uint(a2); af[i][3] = __float_as_uint(a3);
                }
            }
#pragma unroll
            for (int j = 0; j < 8; j++) {
                int cn = wn * 64 + j * 8 + gr;
                bf[j][0] = __float_as_uint(Bs[(kk + gc) * BS_STRIDE + cn]);
                bf[j][1] = __float_as_uint(Bs[(kk + gc + 4) * BS_STRIDE + cn]);
            }
#pragma unroll
            for (int i = 0; i < 2; i++)
#pragma unroll
                for (int j = 0; j < 8; j++) {
                    asm volatile(
                        "mma.sync.aligned.m16n8k8.row.col.f32.tf32.tf32.f32 "
                        "{%0,%1,%2,%3}, {%4,%5,%6,%7}, {%8,%9}, {%0,%1,%2,%3};\n"
                        : "+f"(c_[i][j][0]), "+f"(c_[i][j][1]),
                          "+f"(c_[i][j][2]), "+f"(c_[i][j][3])
                        : "r"(af[i][0]), "r"(af[i][1]), "r"(af[i][2]), "r"(af[i][3]),
                          "r"(bf[j][0]), "r"(bf[j][1]));
                }
        }
        __syncthreads();
    }

    // epilogue
#pragma unroll
    for (int i = 0; i < 2; i++) {
        int rr0 = rowBase + wm * 32 + i * 16 + gr;
#pragma unroll
        for (int half = 0; half < 2; half++) {
            int r = rr0 + half * 8;
            if (r >= M) continue;
            float sc = (ACT == 2) ? rowscale[r] : 1.0f;
            size_t ab = 0;
            if (FUSE_AGG) {
                int cc = el[3 * r + 1], rl = el[3 * r + 2];
                ab = ((size_t)cc * RR + rl) * 256;
            }
#pragma unroll
            for (int j = 0; j < 8; j++) {
                int cn = colBase + wn * 64 + j * 8 + gc * 2;
                float b0 = bias ? bias[cn] : 0.f;
                float b1 = bias ? bias[cn + 1] : 0.f;
                float v0 = c_[i][j][half * 2 + 0] + b0;
                float v1 = c_[i][j][half * 2 + 1] + b1;
                if (ACT >= 1) { v0 = silu_f(v0); v1 = silu_f(v1); }
                if (ACT == 2) { v0 *= sc; v1 *= sc; }
                if (OUT_TF32) { v0 = tf32r(v0); v1 = tf32r(v1); }
                *(float2*)&C[(size_t)r * Nc + cn] = make_float2(v0, v1);
                if (FUSE_AGG) {
                    atomicAdd(&agg[ab + cn], v0);
                    atomicAdd(&agg[ab + cn + 1], v1);
                }
            }
        }
    }
}

// ---------------- edge fuse ----------------
// m1[e] = tf32(silu(PQ[row][0:256] + PQ[col][256:512] + rad_feat@W1c + be1))
__global__ __launch_bounds__(256) void edge_fuse_kernel(
    const float* __restrict__ PQ,
    const float* __restrict__ x, const int* __restrict__ el,
    const float* __restrict__ cw,
    const float* __restrict__ Wrad, const float* __restrict__ brad,
    const float* __restrict__ W1c, const float* __restrict__ be1,
    float* __restrict__ m1)
{
    __shared__ __align__(16) float sW1c[16][256];
    __shared__ float sWrad[16][16];
    __shared__ float sbrad[16];
    __shared__ __align__(16) float sbe1[256];
    __shared__ float srad[8][16];
    __shared__ float srf[8][16];
    int tid = threadIdx.x;
    for (int i = tid; i < 16 * 256; i += 256) sW1c[i >> 8][i & 255] = W1c[i];
    sbe1[tid] = be1[tid];
    { int r = tid >> 4, c = tid & 15; sWrad[r][c] = Wrad[tid]; }
    if (tid < 16) sbrad[tid] = brad[tid];
    __syncthreads();

    int warp = tid >> 5, lane = tid & 31;
#pragma unroll 1
    for (int ei = 0; ei < 8; ei++) {
        int e = blockIdx.x * 64 + warp * 8 + ei;
        int row = el[3*e], col = el[3*e+1];

        if (lane < 16) {
            int i = lane >> 2, j = lane & 3;
            float dx = x[row*12 + i*3 + 0] - x[col*12 + j*3 + 0];
            float dy = x[row*12 + i*3 + 1] - x[col*12 + j*3 + 1];
            float dz = x[row*12 + i*3 + 2] - x[col*12 + j*3 + 2];
            srad[warp][lane] = (dx*dx + dy*dy + dz*dz) * cw[row*4 + i] * cw[col*4 + j];
        }
        __syncwarp();
        if (lane < 16) {
            float acc = sbrad[lane];
#pragma unroll
            for (int k = 0; k < 16; k++) acc = fmaf(srad[warp][k], sWrad[k][lane], acc);
            srf[warp][lane] = silu_f(acc);
        }
        __syncwarp();

        const float4* Pr = (const float4*)(PQ + (size_t)row * 512);
        const float4* Qc = (const float4*)(PQ + (size_t)col * 512 + 256);
        float4* Om = (float4*)(m1 + (size_t)e * 256);
#pragma unroll
        for (int half = 0; half < 2; half++) {
            int o4 = lane * 2 + half;
            float4 p = Pr[o4], q = Qc[o4];
            float4 b = ((const float4*)sbe1)[o4];
            float4 s = make_float4(p.x + q.x + b.x, p.y + q.y + b.y,
                                   p.z + q.z + b.z, p.w + q.w + b.w);
#pragma unroll
            for (int k = 0; k < 16; k++) {
                float rk = srf[warp][k];
                float4 w = ((const float4*)&sW1c[k][0])[o4];
                s.x = fmaf(rk, w.x, s.x); s.y = fmaf(rk, w.y, s.y);
                s.z = fmaf(rk, w.z, s.z); s.w = fmaf(rk, w.w, s.w);
            }
            s.x = tf32r(silu_f(s.x)); s.y = tf32r(silu_f(s.y));
            s.z = tf32r(silu_f(s.z)); s.w = tf32r(silu_f(s.w));
            Om[o4] = s;
        }
        __syncwarp();
    }
}

// ---------------- phi + x scatter fused ----------------
__global__ __launch_bounds__(256) void phi_x_kernel(
    const float* __restrict__ A, const float* __restrict__ W,
    const float* __restrict__ x, const int* __restrict__ el,
    float* __restrict__ xacc)
{
    __shared__ float Ws[256 * 16];
    __shared__ float Ar[16][256];
    int tid = threadIdx.x;
    for (int i = tid; i < 256 * 16; i += 256) Ws[i] = W[i];
    int e0 = blockIdx.x * 16;
    for (int i = tid; i < 16 * 64; i += 256) {
        int r = i / 64, c4 = i % 64;
        float4 v = ((const float4*)(A + (size_t)(e0 + r) * 256))[c4];
        *(float4*)&Ar[r][c4 * 4] = v;
    }
    __syncthreads();
    int r = tid >> 4, n = tid & 15;
    int e = e0 + r;
    float acc = 0.0f;
#pragma unroll 16
    for (int k = 0; k < 256; k++) acc = fmaf(Ar[r][k], Ws[k * 16 + n], acc);

    int i = n >> 2, j = n & 3;
    int row = el[3*e], col = el[3*e+1];
    float c0 = (x[row*12 + i*3 + 0] - x[col*12 + j*3 + 0]) * acc;
    float c1 = (x[row*12 + i*3 + 1] - x[col*12 + j*3 + 1]) * acc;
    float c2 = (x[row*12 + i*3 + 2] - x[col*12 + j*3 + 2]) * acc;
    const unsigned mask = 0xFFFFFFFFu;
    c0 += __shfl_xor_sync(mask, c0, 1); c0 += __shfl_xor_sync(mask, c0, 2);
    c1 += __shfl_xor_sync(mask, c1, 1); c1 += __shfl_xor_sync(mask, c1, 2);
    c2 += __shfl_xor_sync(mask, c2, 1); c2 += __shfl_xor_sync(mask, c2, 2);
    if (j == 0) {
        atomicAdd(&xacc[row*12 + i*3 + 0], c0 * 0.25f);
        atomicAdd(&xacc[row*12 + i*3 + 1], c1 * 0.25f);
        atomicAdd(&xacc[row*12 + i*3 + 2], c2 * 0.25f);
    }
}

// ---------------- layernorm ----------------
__global__ void ln_kernel(const float* __restrict__ h2, const float* __restrict__ g,
                          const float* __restrict__ b, float* __restrict__ out) {
    int n = blockIdx.x;
    int t = threadIdx.x;
    float v = h2[(size_t)n * 256 + t];
    float a = v, sq = v * v;
#pragma unroll
    for (int o = 16; o > 0; o >>= 1) {
        a  += __shfl_down_sync(0xFFFFFFFFu, a, o);
        sq += __shfl_down_sync(0xFFFFFFFFu, sq, o);
    }
    __shared__ float s1[8], s2[8];
    if ((t & 31) == 0) { s1[t >> 5] = a; s2[t >> 5] = sq; }
    __syncthreads();
    __shared__ float mu, rs;
    if (t == 0) {
        float A = 0.f, B = 0.f;
#pragma unroll
        for (int i = 0; i < 8; i++) { A += s1[i]; B += s2[i]; }
        float m = A * (1.0f / 256.0f);
        mu = m;
        rs = rsqrtf(B * (1.0f / 256.0f) - m * m + EPSV);
    }
    __syncthreads();
    out[(size_t)n * 256 + t] = (v - mu) * rs * g[t] + b[t];
}

__global__ void x_final_kernel(const float* __restrict__ xin, const float* __restrict__ xacc,
                               const float* __restrict__ cnt, float* __restrict__ xout) {
    int i = blockIdx.x * blockDim.x + threadIdx.x;
    if (i >= NN * 12) return;
    int n = i / 12;
    xout[i] = xin[i] + xacc[i] / fmaxf(cnt[n], 1.0f);
}

// ---------------- host ----------------
extern "C" void kernel_launch(void* const* d_in, const int* in_sizes, int n_in,
                              void* d_out, int out_size) {
    const float* input  = nullptr;
    const float* coords = nullptr;
    const float* attr   = nullptr;
    const float* cw     = nullptr;
    const float* ew     = nullptr;
    const int*   el     = nullptr;
    for (int i = 0; i < 6; i++) {
        switch (in_sizes[i]) {
            case NN * HH:     input  = (const float*)d_in[i]; break;
            case NN * 4 * 3:  coords = (const float*)d_in[i]; break;
            case NN * 4 * 16: attr   = (const float*)d_in[i]; break;
            case NN * 4:      cw     = (const float*)d_in[i]; break;
            case EE:          ew     = (const float*)d_in[i]; break;
            case EE * 3:      el     = (const int*)  d_in[i]; break;
        }
    }
    const float* W_rad = (const float*)d_in[6];
    const float* b_rad = (const float*)d_in[7];
    const float* W_e1  = (const float*)d_in[8];
    const float* b_e1  = (const float*)d_in[9];
    const float* W_e2  = (const float*)d_in[10];
    const float* b_e2  = (const float*)d_in[11];
    const float* W_c1  = (const float*)d_in[12];
    const float* b_c1  = (const float*)d_in[13];
    const float* W_c2  = (const float*)d_in[14];
    const float* W_n1  = (const float*)d_in[15];
    const float* b_n1  = (const float*)d_in[16];
    const float* W_n2  = (const float*)d_in[17];
    const float* b_n2  = (const float*)d_in[18];
    const float* ln_g  = (const float*)d_in[19];
    const float* ln_b  = (const float*)d_in[20];

    float* buf = nullptr;
    cudaGetSymbolAddress((void**)&buf, g_buf);

    float* g_ca   = buf + OFF_CA;
    float* g_wpq  = buf + OFF_WPQ;
    float* g_pq   = buf + OFF_PQ;
    float* g_m1   = buf + OFF_M1;
    float* g_m    = buf + OFF_M;
    float* g_agg  = buf + OFF_AGG;
    float* g_h1   = buf + OFF_H1;
    float* g_hbuf = buf + OFF_HBUF;
    float* g_xbuf = buf + OFF_XBUF;
    float* g_xacc = buf + OFF_XACC;
    float* g_cnt  = buf + OFF_CNT;
    float* g_we2t = buf + OFF_WE2T;
    float* g_wc1t = buf + OFF_WC1T;
    float* g_wn2t = buf + OFF_WN2T;
    float* g_wn1t = buf + OFF_WN1T;

    cudaFuncSetAttribute((const void*)tf32_gemm_kernel<0, false, true, false>,
                         cudaFuncAttributeMaxDynamicSharedMemorySize, GEMM_SMEM_BYTES);
    cudaFuncSetAttribute((const void*)tf32_gemm_kernel<2, true, false, true>,
                         cudaFuncAttributeMaxDynamicSharedMemorySize, GEMM_SMEM_BYTES);
    cudaFuncSetAttribute((const void*)tf32_gemm_kernel<1, false, false, false>,
                         cudaFuncAttributeMaxDynamicSharedMemorySize, GEMM_SMEM_BYTES);
    cudaFuncSetAttribute((const void*)tf32_gemm_kernel<1, false, true, true>,
                         cudaFuncAttributeMaxDynamicSharedMemorySize, GEMM_SMEM_BYTES);
    cudaFuncSetAttribute((const void*)tf32_gemm_kernel<0, false, false, false>,
                         cudaFuncAttributeMaxDynamicSharedMemorySize, GEMM_SMEM_BYTES);

    const int KBIG = 1 << 30;

    ca_kernel<<<(NN + 255) / 256, 256>>>(attr, cw, g_ca);
    zero4_kernel<<<(NN/4 + 255) / 256, 256>>>((float4*)g_cnt, (size_t)NN / 4);
    cnt_kernel<<<(EE + 255) / 256, 256>>>(el, g_cnt);

    for (int l = 0; l < LL; l++) {
        const float* h_in = (l == 0) ? input  : g_hbuf;
        const float* x_in = (l == 0) ? coords : g_xbuf;
        float* h_out = (l == LL - 1) ? (float*)d_out : g_hbuf;
        float* x_out = (l == LL - 1) ? ((float*)d_out + (size_t)NN * HH) : g_xbuf;

        const float* Wr  = W_rad + (size_t)l * 256;
        const float* br  = b_rad + (size_t)l * 16;
        const float* We1 = W_e1 + (size_t)l * 560 * 256;
        const float* be1 = b_e1 + (size_t)l * 256;
        const float* We2 = W_e2 + (size_t)l * 256 * 256;
        const float* be2 = b_e2 + (size_t)l * 256;
        const float* Wc1 = W_c1 + (size_t)l * 256 * 256;
        const float* bc1 = b_c1 + (size_t)l * 256;
        const float* Wc2 = W_c2 + (size_t)l * 256 * 16;
        const float* Wn1 = W_n1 + (size_t)l * 2048 * 256;
        const float* bn1 = b_n1 + (size_t)l * 256;
        const float* Wn2 = W_n2 + (size_t)l * 256 * 256;
        const float* bn2 = b_n2 + (size_t)l * 256;
        const float* lg  = ln_g + (size_t)l * 256;
        const float* lb  = ln_b + (size_t)l * 256;

        // Weight prep (tf32-rounded copies)
        wpq_kernel<<<(272 * 512 + 255) / 256, 256>>>(We1, g_wpq);
        wprep_kernel<<<(720896 + 255) / 256, 256>>>(We2, Wc1, Wn1, Wn2,
                                                    g_we2t, g_wc1t, g_wn1t, g_wn2t);

        // PQ = [h|ca] @ Wpq  (N x 512)
        tf32_gemm_kernel<0, false, true, false><<<dim3(4, (NN + 127) / 128), 256, GEMM_SMEM_BYTES>>>(
            h_in, 256, g_ca, 16, 256,
            g_wpq, nullptr, nullptr, g_pq, nullptr, nullptr, NN, 512, 272);

        zero4_kernel<<<(unsigned)(((size_t)NN*RR*HH/4 + 255) / 256), 256>>>(
            (float4*)g_agg, (size_t)NN*RR*HH/4);
        zero4_kernel<<<(NN*12/4 + 255) / 256, 256>>>((float4*)g_xacc, (size_t)NN*12/4);

        // m1 = tf32(silu(P[row]+Q[col]+rad_feat@W1c+be1))
        edge_fuse_kernel<<<EE / 64, 256>>>(g_pq, x_in, el, cw,
                                           Wr, br, We1 + (size_t)512 * 256, be1, g_m1);

        // m = tf32(silu(m1@We2+be2)*ew), fused agg scatter
        tf32_gemm_kernel<2, true, false, true><<<dim3(2, EE / 128), 256, GEMM_SMEM_BYTES>>>(
            g_m1, 256, nullptr, 0, KBIG,
            g_we2t, be2, ew, g_m, el, g_agg, EE, 256, 256);

        // t1 = silu(m@Wc1+bc1)
        tf32_gemm_kernel<1, false, false, false><<<dim3(2, EE / 128), 256, GEMM_SMEM_BYTES>>>(
            g_m, 256, nullptr, 0, KBIG,
            g_wc1t, bc1, nullptr, g_m1, nullptr, nullptr, EE, 256, 256);

        // phi + x scatter
        phi_x_kernel<<<EE / 16, 256>>>(g_m1, Wc2, x_in, el, g_xacc);

        // h1 = tf32(silu([agg|h]@Wn1+bn1))
        tf32_gemm_kernel<1, false, true, true><<<dim3(2, (NN + 127) / 128), 256, GEMM_SMEM_BYTES>>>(
            g_agg, 1792, h_in, 256, 1792,
            g_wn1t, bn1, nullptr, g_h1, nullptr, nullptr, NN, 256, 2048);

        // h2 = h1@Wn2+bn2
        tf32_gemm_kernel<0, false, false, false><<<dim3(2, (NN + 127) / 128), 256, GEMM_SMEM_BYTES>>>(
            g_h1, 256, nullptr, 0, KBIG,
            g_wn2t, bn2, nullptr, g_pq, nullptr, nullptr, NN, 256, 256);

        ln_kernel<<<NN, 256>>>(g_pq, lg, lb, h_out);
        x_final_kernel<<<(NN * 12 + 255) / 256, 256>>>(x_in, g_xacc, g_cnt, x_out);
    }
}

// round 7
// speedup vs baseline: 3.4315x; 1.0125x over previous
#include <cuda_runtime.h>
#include <cstddef>
#include <cstdint>

#define NN 10000
#define EE 160000
#define RR 7
#define HH 256
#define LL 2
#define EPSV 1e-5f

// ---------------- scratch ----------------
#define OFF_CA    ((size_t)0)                         // N*16
#define OFF_WPQ   (OFF_CA   + (size_t)NN*16)          // 272*512
#define OFF_PQ    (OFF_WPQ  + (size_t)272*512)        // N*512
#define OFF_M1    (OFF_PQ   + (size_t)NN*512)         // E*256
#define OFF_M     (OFF_M1   + (size_t)EE*HH)          // E*256
#define OFF_AGG   (OFF_M    + (size_t)EE*HH)          // N*R*H (1792)
#define OFF_H1    (OFF_AGG  + (size_t)NN*RR*HH)       // N*256
#define OFF_HBUF  (OFF_H1   + (size_t)NN*HH)          // N*256
#define OFF_XBUF  (OFF_HBUF + (size_t)NN*HH)          // N*12
#define OFF_XACC  (OFF_XBUF + (size_t)NN*12)          // N*12
#define OFF_CNT   (OFF_XACC + (size_t)NN*12)          // N
#define OFF_WE2T  (OFF_CNT  + (size_t)NN)             // 65536
#define OFF_WC1T  (OFF_WE2T + (size_t)65536)          // 65536
#define OFF_WN2T  (OFF_WC1T + (size_t)65536)          // 65536
#define OFF_WN1T  (OFF_WN2T + (size_t)65536)          // 524288
#define TOTAL_F   (OFF_WN1T + (size_t)524288)

__device__ float g_buf[TOTAL_F];

__device__ __forceinline__ float silu_f(float v) { return v / (1.0f + __expf(-v)); }

__device__ __forceinline__ unsigned f2tf32(float f) {
    unsigned u;
    asm("cvt.rna.tf32.f32 %0, %1;" : "=r"(u) : "f"(f));
    return u;
}
__device__ __forceinline__ float tf32r(float v) { return __uint_as_float(f2tf32(v)); }

__device__ __forceinline__ void cp_async16(uint32_t dst, const void* src, bool p) {
    asm volatile("cp.async.cg.shared.global [%0], [%1], 16, %2;\n"
                 :: "r"(dst), "l"(src), "r"(p ? 16 : 0));
}
__device__ __forceinline__ void cp_commit() {
    asm volatile("cp.async.commit_group;\n");
}
template <int Np> __device__ __forceinline__ void cp_wait() {
    asm volatile("cp.async.wait_group %0;\n" :: "n"(Np));
}
__device__ __forceinline__ void red_add_v2(float* addr, float a, float b) {
    asm volatile("red.global.add.v2.f32 [%0], {%1, %2};"
                 :: "l"(addr), "f"(a), "f"(b) : "memory");
}

// ---------------- small kernels ----------------
__global__ void zero4_kernel(float4* __restrict__ p, size_t n4) {
    size_t i = (size_t)blockIdx.x * blockDim.x + threadIdx.x;
    if (i < n4) p[i] = make_float4(0.f, 0.f, 0.f, 0.f);
}

__global__ void ca_kernel(const float* __restrict__ attr, const float* __restrict__ cw,
                          float* __restrict__ ca) {
    int n = blockIdx.x * blockDim.x + threadIdx.x;
    if (n >= NN) return;
    float w0 = cw[n*4+0], w1 = cw[n*4+1], w2 = cw[n*4+2], w3 = cw[n*4+3];
    float inv = 1.0f / (w0 + w1 + w2 + w3);
    const float* a = attr + (size_t)n * 64;
#pragma unroll
    for (int f = 0; f < 16; f++)
        ca[n*16+f] = (a[f]*w0 + a[16+f]*w1 + a[32+f]*w2 + a[48+f]*w3) * inv;
}

__global__ void cnt_kernel(const int* __restrict__ el, float* __restrict__ cnt) {
    int e = blockIdx.x * blockDim.x + threadIdx.x;
    if (e >= EE) return;
    atomicAdd(&cnt[el[3*e]], 1.0f);
}

// Wpq pack (tf32-rounded, [K=272, Nc=512])
__global__ void wpq_kernel(const float* __restrict__ We1, float* __restrict__ Wpq) {
    int i = blockIdx.x * blockDim.x + threadIdx.x;
    if (i >= 272 * 512) return;
    int r = i / 512, c = i % 512;
    int j = (c < 256) ? c : c - 256;
    int k;
    if (c < 256) k = (r < 256) ? r : 528 + (r - 256);
    else         k = (r < 256) ? 256 + r : 544 + (r - 256);
    Wpq[i] = tf32r(We1[(size_t)k * 256 + j]);
}

// per-layer prep: tf32-round weights + zero agg + zero xacc
#define PREP_W  720896
#define PREP_AGG (PREP_W + (size_t)NN*RR*HH/4)
#define PREP_TOT (PREP_AGG + (size_t)NN*12/4)
__global__ void prep_kernel(const float* __restrict__ We2, const float* __restrict__ Wc1,
                            const float* __restrict__ Wn1, const float* __restrict__ Wn2,
                            float* __restrict__ dWe2, float* __restrict__ dWc1,
                            float* __restrict__ dWn1, float* __restrict__ dWn2,
                            float4* __restrict__ agg4, float4* __restrict__ xacc4) {
    size_t i = (size_t)blockIdx.x * blockDim.x + threadIdx.x;
    if (i < 65536)            dWe2[i]          = tf32r(We2[i]);
    else if (i < 131072)      dWc1[i - 65536]  = tf32r(Wc1[i - 65536]);
    else if (i < 196608)      dWn2[i - 131072] = tf32r(Wn2[i - 131072]);
    else if (i < PREP_W)      dWn1[i - 196608] = tf32r(Wn1[i - 196608]);
    else if (i < PREP_AGG)    agg4[i - PREP_W] = make_float4(0.f, 0.f, 0.f, 0.f);
    else if (i < PREP_TOT)    xacc4[i - PREP_AGG] = make_float4(0.f, 0.f, 0.f, 0.f);
}

// ---------------- tf32 GEMM, cp.async 4-stage ----------------
#define AS_STRIDE 28
#define BS_STRIDE 136
#define AS_SZ (128 * AS_STRIDE)
#define BS_SZ (16 * BS_STRIDE)
#define NSTG 4
#define GEMM_SMEM_BYTES (NSTG * (AS_SZ + BS_SZ) * 4)

template <int ACT, bool FUSE_AGG, bool CVT_A, bool OUT_TF32>
__global__ __launch_bounds__(256) void tf32_gemm_kernel(
    const float* __restrict__ A, int lda,
    const float* __restrict__ A2, int lda2, int K1,
    const float* __restrict__ B,
    const float* __restrict__ bias, const float* __restrict__ rowscale,
    float* __restrict__ C,
    const int* __restrict__ el, float* __restrict__ agg,
    int M, int Nc, int K)
{
    extern __shared__ float smem[];
    float* AsBase = smem;
    float* BsBase = smem + NSTG * AS_SZ;
    uint32_t su = (uint32_t)__cvta_generic_to_shared(smem);

    int tid = threadIdx.x;
    int rowBase = blockIdx.y * 128, colBase = blockIdx.x * 128;
    int warp = tid >> 5, lane = tid & 31;
    int wm = warp >> 1, wn = warp & 1;
    int gr = lane >> 2, gc = lane & 3;

    float c_[2][8][4];
#pragma unroll
    for (int i = 0; i < 2; i++)
#pragma unroll
        for (int j = 0; j < 8; j++)
#pragma unroll
            for (int q = 0; q < 4; q++) c_[i][j][q] = 0.0f;

    int nt = K >> 4;

    auto load_stage = [&](int s, int t) {
        int k0 = t << 4;
#pragma unroll
        for (int c = 0; c < 2; c++) {
            int idx = tid + c * 256;
            int arow = idx >> 2, ach = (idx & 3) * 4;
            int r = rowBase + arow;
            int k = k0 + ach;
            const float* src = (k >= K1) ? (A2 + (size_t)r * lda2 + (k - K1))
                                         : (A  + (size_t)r * lda  + k);
            cp_async16(su + (uint32_t)(s * AS_SZ + arow * AS_STRIDE + ach) * 4, src, r < M);
        }
#pragma unroll
        for (int c = 0; c < 2; c++) {
            int idx = tid + c * 256;
            int brow = idx >> 5, bch = (idx & 31) * 4;
            const float* src = B + (size_t)(k0 + brow) * Nc + colBase + bch;
            cp_async16(su + (uint32_t)(NSTG * AS_SZ + s * BS_SZ + brow * BS_STRIDE + bch) * 4, src, true);
        }
        cp_commit();
    };

#pragma unroll
    for (int s = 0; s < NSTG - 1; s++) {
        if (s < nt) load_stage(s, s); else cp_commit();
    }

    for (int t = 0; t < nt; t++) {
        cp_wait<NSTG - 2>();
        __syncthreads();
        int cur = t % NSTG;
        if (t + NSTG - 1 < nt) load_stage((t + NSTG - 1) % NSTG, t + NSTG - 1);
        else cp_commit();
        const float* As = AsBase + cur * AS_SZ;
        const float* Bs = BsBase + cur * BS_SZ;
#pragma unroll
        for (int kk = 0; kk < 16; kk += 8) {
            unsigned af[2][4], bf[8][2];
#pragma unroll
            for (int i = 0; i < 2; i++) {
                int r0 = wm * 32 + i * 16 + gr;
                float a0 = As[r0 * AS_STRIDE + kk + gc];
                float a1 = As[(r0 + 8) * AS_STRIDE + kk + gc];
                float a2 = As[r0 * AS_STRIDE + kk + gc + 4];
                float a3 = As[(r0 + 8) * AS_STRIDE + kk + gc + 4];
                if (CVT_A) {
                    af[i][0] = f2tf32(a0); af[i][1] = f2tf32(a1);
                    af[i][2] = f2tf32(a2); af[i][3] = f2tf32(a3);
                } else {
                    af[i][0] = __float_as_uint(a0); af[i][1] = __float_as_uint(a1);
                    af[i][2] = __float_as_uint(a2); af[i][3] = __float_as_uint(a3);
                }
            }
#pragma unroll
            for (int j = 0; j < 8; j++) {
                int cn = wn * 64 + j * 8 + gr;
                bf[j][0] = __float_as_uint(Bs[(kk + gc) * BS_STRIDE + cn]);
                bf[j][1] = __float_as_uint(Bs[(kk + gc + 4) * BS_STRIDE + cn]);
            }
#pragma unroll
            for (int i = 0; i < 2; i++)
#pragma unroll
                for (int j = 0; j < 8; j++) {
                    asm volatile(
                        "mma.sync.aligned.m16n8k8.row.col.f32.tf32.tf32.f32 "
                        "{%0,%1,%2,%3}, {%4,%5,%6,%7}, {%8,%9}, {%0,%1,%2,%3};\n"
                        : "+f"(c_[i][j][0]), "+f"(c_[i][j][1]),
                          "+f"(c_[i][j][2]), "+f"(c_[i][j][3])
                        : "r"(af[i][0]), "r"(af[i][1]), "r"(af[i][2]), "r"(af[i][3]),
                          "r"(bf[j][0]), "r"(bf[j][1]));
                }
        }
        __syncthreads();
    }

#pragma unroll
    for (int i = 0; i < 2; i++) {
        int rr0 = rowBase + wm * 32 + i * 16 + gr;
#pragma unroll
        for (int half = 0; half < 2; half++) {
            int r = rr0 + half * 8;
            if (r >= M) continue;
            float sc = (ACT == 2) ? rowscale[r] : 1.0f;
            size_t ab = 0;
            if (FUSE_AGG) {
                int cc = el[3 * r + 1], rl = el[3 * r + 2];
                ab = ((size_t)cc * RR + rl) * 256;
            }
#pragma unroll
            for (int j = 0; j < 8; j++) {
                int cn = colBase + wn * 64 + j * 8 + gc * 2;
                float b0 = bias ? bias[cn] : 0.f;
                float b1 = bias ? bias[cn + 1] : 0.f;
                float v0 = c_[i][j][half * 2 + 0] + b0;
                float v1 = c_[i][j][half * 2 + 1] + b1;
                if (ACT >= 1) { v0 = silu_f(v0); v1 = silu_f(v1); }
                if (ACT == 2) { v0 *= sc; v1 *= sc; }
                if (OUT_TF32) { v0 = tf32r(v0); v1 = tf32r(v1); }
                *(float2*)&C[(size_t)r * Nc + cn] = make_float2(v0, v1);
                if (FUSE_AGG) red_add_v2(&agg[ab + cn], v0, v1);
            }
        }
    }
}

// ---------------- fused Wc1 GEMM + phi + x-scatter ----------------
// t1 = silu(m@Wc1 + bc1) computed in regs; phi partial = t1_cols @ Wc2;
// trans partial scattered into xacc. No t1 store. Grid (2, EE/128).
__global__ __launch_bounds__(256) void gemm_phix_kernel(
    const float* __restrict__ A,            // m (tf32-rounded), E x 256
    const float* __restrict__ B,            // Wc1 tf32 [256,256]
    const float* __restrict__ bc1,
    const float* __restrict__ Wc2,          // [256,16] fp32
    const float* __restrict__ x, const int* __restrict__ el,
    float* __restrict__ xacc)
{
    extern __shared__ float smem[];
    float* AsBase = smem;
    float* BsBase = smem + NSTG * AS_SZ;
    uint32_t su = (uint32_t)__cvta_generic_to_shared(smem);

    int tid = threadIdx.x;
    int rowBase = blockIdx.y * 128, colBase = blockIdx.x * 128;
    int warp = tid >> 5, lane = tid & 31;
    int wm = warp >> 1, wn = warp & 1;
    int gr = lane >> 2, gc = lane & 3;

    float c_[2][8][4];
#pragma unroll
    for (int i = 0; i < 2; i++)
#pragma unroll
        for (int j = 0; j < 8; j++)
#pragma unroll
            for (int q = 0; q < 4; q++) c_[i][j][q] = 0.0f;

    const int nt = 256 >> 4;

    auto load_stage = [&](int s, int t) {
        int k0 = t << 4;
#pragma unroll
        for (int c = 0; c < 2; c++) {
            int idx = tid + c * 256;
            int arow = idx >> 2, ach = (idx & 3) * 4;
            cp_async16(su + (uint32_t)(s * AS_SZ + arow * AS_STRIDE + ach) * 4,
                       A + (size_t)(rowBase + arow) * 256 + k0 + ach, true);
        }
#pragma unroll
        for (int c = 0; c < 2; c++) {
            int idx = tid + c * 256;
            int brow = idx >> 5, bch = (idx & 31) * 4;
            cp_async16(su + (uint32_t)(NSTG * AS_SZ + s * BS_SZ + brow * BS_STRIDE + bch) * 4,
                       B + (size_t)(k0 + brow) * 256 + colBase + bch, true);
        }
        cp_commit();
    };

#pragma unroll
    for (int s = 0; s < NSTG - 1; s++) load_stage(s, s);

    for (int t = 0; t < nt; t++) {
        cp_wait<NSTG - 2>();
        __syncthreads();
        int cur = t % NSTG;
        if (t + NSTG - 1 < nt) load_stage((t + NSTG - 1) % NSTG, t + NSTG - 1);
        else cp_commit();
        const float* As = AsBase + cur * AS_SZ;
        const float* Bs = BsBase + cur * BS_SZ;
#pragma unroll
        for (int kk = 0; kk < 16; kk += 8) {
            unsigned af[2][4], bf[8][2];
#pragma unroll
            for (int i = 0; i < 2; i++) {
                int r0 = wm * 32 + i * 16 + gr;
                af[i][0] = __float_as_uint(As[r0 * AS_STRIDE + kk + gc]);
                af[i][1] = __float_as_uint(As[(r0 + 8) * AS_STRIDE + kk + gc]);
                af[i][2] = __float_as_uint(As[r0 * AS_STRIDE + kk + gc + 4]);
                af[i][3] = __float_as_uint(As[(r0 + 8) * AS_STRIDE + kk + gc + 4]);
            }
#pragma unroll
            for (int j = 0; j < 8; j++) {
                int cn = wn * 64 + j * 8 + gr;
                bf[j][0] = __float_as_uint(Bs[(kk + gc) * BS_STRIDE + cn]);
                bf[j][1] = __float_as_uint(Bs[(kk + gc + 4) * BS_STRIDE + cn]);
            }
#pragma unroll
            for (int i = 0; i < 2; i++)
#pragma unroll
                for (int j = 0; j < 8; j++) {
                    asm volatile(
                        "mma.sync.aligned.m16n8k8.row.col.f32.tf32.tf32.f32 "
                        "{%0,%1,%2,%3}, {%4,%5,%6,%7}, {%8,%9}, {%0,%1,%2,%3};\n"
                        : "+f"(c_[i][j][0]), "+f"(c_[i][j][1]),
                          "+f"(c_[i][j][2]), "+f"(c_[i][j][3])
                        : "r"(af[i][0]), "r"(af[i][1]), "r"(af[i][2]), "r"(af[i][3]),
                          "r"(bf[j][0]), "r"(bf[j][1]));
                }
        }
        __syncthreads();
    }

    // ---- epilogue: phi partial over this CTA's 128 cols ----
    float* sT  = smem;                    // [128][36] t1 chunk staging (row-major)
    float* sW2 = smem + 128 * 36;         // [128][17] Wc2 slice
    float* sB1 = sW2 + 128 * 17;          // [128] bias slice

    if (tid < 128) sB1[tid] = bc1[colBase + tid];
    for (int idx = tid; idx < 128 * 16; idx += 256) {
        int rr = idx >> 4, n = idx & 15;
        sW2[rr * 17 + n] = Wc2[(size_t)(colBase + rr) * 16 + n];
    }

    float p[8];
#pragma unroll
    for (int n = 0; n < 8; n++) p[n] = 0.0f;
    int pr = tid >> 1;
    int pn0 = (tid & 1) * 8;

#pragma unroll 1
    for (int ch = 0; ch < 4; ch++) {
        __syncthreads();
        if (wn == (ch >> 1)) {
            int jb = (ch & 1) * 4;
#pragma unroll
            for (int jj = 0; jj < 4; jj++) {
                int j = jb + jj;
                int lcol = j * 8 + gc * 2 - (ch & 1) * 32;   // [0,32)
                float bb0 = sB1[wn * 64 + j * 8 + gc * 2];
                float bb1 = sB1[wn * 64 + j * 8 + gc * 2 + 1];
#pragma unroll
                for (int i = 0; i < 2; i++)
#pragma unroll
                    for (int half = 0; half < 2; half++) {
                        int lr = wm * 32 + i * 16 + half * 8 + gr;
                        float v0 = silu_f(c_[i][j][half * 2 + 0] + bb0);
                        float v1 = silu_f(c_[i][j][half * 2 + 1] + bb1);
                        *(float2*)&sT[lr * 36 + lcol] = make_float2(v0, v1);
                    }
            }
        }
        __syncthreads();
#pragma unroll
        for (int cb = 0; cb < 8; cb++) {
            float4 t4 = *(const float4*)&sT[pr * 36 + cb * 4];
#pragma unroll
            for (int k = 0; k < 4; k++) {
                float tv = (&t4.x)[k];
                int wr = ch * 32 + cb * 4 + k;
#pragma unroll
                for (int n = 0; n < 8; n++)
                    p[n] = fmaf(tv, sW2[wr * 17 + pn0 + n], p[n]);
            }
        }
    }

    float q[8];
#pragma unroll
    for (int n = 0; n < 8; n++) q[n] = __shfl_xor_sync(0xFFFFFFFFu, p[n], 1);

    if ((tid & 1) == 0) {
        float phi[16];
#pragma unroll
        for (int n = 0; n < 8; n++) { phi[n] = p[n]; phi[8 + n] = q[n]; }
        int e = rowBase + pr;
        int rw = el[3 * e], cl = el[3 * e + 1];
        float xr[12], xc[12];
#pragma unroll
        for (int d = 0; d < 12; d++) { xr[d] = x[rw * 12 + d]; xc[d] = x[cl * 12 + d]; }
#pragma unroll
        for (int i2 = 0; i2 < 4; i2++)
#pragma unroll
            for (int d = 0; d < 3; d++) {
                float s = 0.0f;
#pragma unroll
                for (int j2 = 0; j2 < 4; j2++)
                    s = fmaf(xr[i2 * 3 + d] - xc[j2 * 3 + d], phi[i2 * 4 + j2], s);
                atomicAdd(&xacc[rw * 12 + i2 * 3 + d], 0.25f * s);
            }
    }
}

// ---------------- edge fuse ----------------
__global__ __launch_bounds__(256) void edge_fuse_kernel(
    const float* __restrict__ PQ,
    const float* __restrict__ x, const int* __restrict__ el,
    const float* __restrict__ cw,
    const float* __restrict__ Wrad, const float* __restrict__ brad,
    const float* __restrict__ W1c, const float* __restrict__ be1,
    float* __restrict__ m1)
{
    __shared__ __align__(16) float sW1c[16][256];
    __shared__ float sWrad[16][16];
    __shared__ float sbrad[16];
    __shared__ __align__(16) float sbe1[256];
    __shared__ float srad[8][16];
    __shared__ float srf[8][16];
    int tid = threadIdx.x;
    for (int i = tid; i < 16 * 256; i += 256) sW1c[i >> 8][i & 255] = W1c[i];
    sbe1[tid] = be1[tid];
    { int r = tid >> 4, c = tid & 15; sWrad[r][c] = Wrad[tid]; }
    if (tid < 16) sbrad[tid] = brad[tid];
    __syncthreads();

    int warp = tid >> 5, lane = tid & 31;
#pragma unroll 1
    for (int ei = 0; ei < 8; ei++) {
        int e = blockIdx.x * 64 + warp * 8 + ei;
        int row = el[3*e], col = el[3*e+1];

        if (lane < 16) {
            int i = lane >> 2, j = lane & 3;
            float dx = x[row*12 + i*3 + 0] - x[col*12 + j*3 + 0];
            float dy = x[row*12 + i*3 + 1] - x[col*12 + j*3 + 1];
            float dz = x[row*12 + i*3 + 2] - x[col*12 + j*3 + 2];
            srad[warp][lane] = (dx*dx + dy*dy + dz*dz) * cw[row*4 + i] * cw[col*4 + j];
        }
        __syncwarp();
        if (lane < 16) {
            float acc = sbrad[lane];
#pragma unroll
            for (int k = 0; k < 16; k++) acc = fmaf(srad[warp][k], sWrad[k][lane], acc);
            srf[warp][lane] = silu_f(acc);
        }
        __syncwarp();

        const float4* Pr = (const float4*)(PQ + (size_t)row * 512);
        const float4* Qc = (const float4*)(PQ + (size_t)col * 512 + 256);
        float4* Om = (float4*)(m1 + (size_t)e * 256);
#pragma unroll
        for (int half = 0; half < 2; half++) {
            int o4 = lane * 2 + half;
            float4 pv = Pr[o4], qv = Qc[o4];
            float4 b = ((const float4*)sbe1)[o4];
            float4 s = make_float4(pv.x + qv.x + b.x, pv.y + qv.y + b.y,
                                   pv.z + qv.z + b.z, pv.w + qv.w + b.w);
#pragma unroll
            for (int k = 0; k < 16; k++) {
                float rk = srf[warp][k];
                float4 w = ((const float4*)&sW1c[k][0])[o4];
                s.x = fmaf(rk, w.x, s.x); s.y = fmaf(rk, w.y, s.y);
                s.z = fmaf(rk, w.z, s.z); s.w = fmaf(rk, w.w, s.w);
            }
            s.x = tf32r(silu_f(s.x)); s.y = tf32r(silu_f(s.y));
            s.z = tf32r(silu_f(s.z)); s.w = tf32r(silu_f(s.w));
            Om[o4] = s;
        }
        __syncwarp();
    }
}

// ---------------- layernorm ----------------
__global__ void ln_kernel(const float* __restrict__ h2, const float* __restrict__ g,
                          const float* __restrict__ b, float* __restrict__ out) {
    int n = blockIdx.x;
    int t = threadIdx.x;
    float v = h2[(size_t)n * 256 + t];
    float a = v, sq = v * v;
#pragma unroll
    for (int o = 16; o > 0; o >>= 1) {
        a  += __shfl_down_sync(0xFFFFFFFFu, a, o);
        sq += __shfl_down_sync(0xFFFFFFFFu, sq, o);
    }
    __shared__ float s1[8], s2[8];
    if ((t & 31) == 0) { s1[t >> 5] = a; s2[t >> 5] = sq; }
    __syncthreads();
    __shared__ float mu, rs;
    if (t == 0) {
        float A = 0.f, B = 0.f;
#pragma unroll
        for (int i = 0; i < 8; i++) { A += s1[i]; B += s2[i]; }
        float m = A * (1.0f / 256.0f);
        mu = m;
        rs = rsqrtf(B * (1.0f / 256.0f) - m * m + EPSV);
    }
    __syncthreads();
    out[(size_t)n * 256 + t] = (v - mu) * rs * g[t] + b[t];
}

__global__ void x_final_kernel(const float* __restrict__ xin, const float* __restrict__ xacc,
                               const float* __restrict__ cnt, float* __restrict__ xout) {
    int i = blockIdx.x * blockDim.x + threadIdx.x;
    if (i >= NN * 12) return;
    int n = i / 12;
    xout[i] = xin[i] + xacc[i] / fmaxf(cnt[n], 1.0f);
}

// ---------------- host ----------------
extern "C" void kernel_launch(void* const* d_in, const int* in_sizes, int n_in,
                              void* d_out, int out_size) {
    const float* input  = nullptr;
    const float* coords = nullptr;
    const float* attr   = nullptr;
    const float* cw     = nullptr;
    const float* ew     = nullptr;
    const int*   el     = nullptr;
    for (int i = 0; i < 6; i++) {
        switch (in_sizes[i]) {
            case NN * HH:     input  = (const float*)d_in[i]; break;
            case NN * 4 * 3:  coords = (const float*)d_in[i]; break;
            case NN * 4 * 16: attr   = (const float*)d_in[i]; break;
            case NN * 4:      cw     = (const float*)d_in[i]; break;
            case EE:          ew     = (const float*)d_in[i]; break;
            case EE * 3:      el     = (const int*)  d_in[i]; break;
        }
    }
    const float* W_rad = (const float*)d_in[6];
    const float* b_rad = (const float*)d_in[7];
    const float* W_e1  = (const float*)d_in[8];
    const float* b_e1  = (const float*)d_in[9];
    const float* W_e2  = (const float*)d_in[10];
    const float* b_e2  = (const float*)d_in[11];
    const float* W_c1  = (const float*)d_in[12];
    const float* b_c1  = (const float*)d_in[13];
    const float* W_c2  = (const float*)d_in[14];
    const float* W_n1  = (const float*)d_in[15];
    const float* b_n1  = (const float*)d_in[16];
    const float* W_n2  = (const float*)d_in[17];
    const float* b_n2  = (const float*)d_in[18];
    const float* ln_g  = (const float*)d_in[19];
    const float* ln_b  = (const float*)d_in[20];

    float* buf = nullptr;
    cudaGetSymbolAddress((void**)&buf, g_buf);

    float* g_ca   = buf + OFF_CA;
    float* g_wpq  = buf + OFF_WPQ;
    float* g_pq   = buf + OFF_PQ;
    float* g_m1   = buf + OFF_M1;
    float* g_m    = buf + OFF_M;
    float* g_agg  = buf + OFF_AGG;
    float* g_h1   = buf + OFF_H1;
    float* g_hbuf = buf + OFF_HBUF;
    float* g_xbuf = buf + OFF_XBUF;
    float* g_xacc = buf + OFF_XACC;
    float* g_cnt  = buf + OFF_CNT;
    float* g_we2t = buf + OFF_WE2T;
    float* g_wc1t = buf + OFF_WC1T;
    float* g_wn2t = buf + OFF_WN2T;
    float* g_wn1t = buf + OFF_WN1T;

    cudaFuncSetAttribute((const void*)tf32_gemm_kernel<0, false, true, false>,
                         cudaFuncAttributeMaxDynamicSharedMemorySize, GEMM_SMEM_BYTES);
    cudaFuncSetAttribute((const void*)tf32_gemm_kernel<2, true, false, true>,
                         cudaFuncAttributeMaxDynamicSharedMemorySize, GEMM_SMEM_BYTES);
    cudaFuncSetAttribute((const void*)tf32_gemm_kernel<1, false, true, true>,
                         cudaFuncAttributeMaxDynamicSharedMemorySize, GEMM_SMEM_BYTES);
    cudaFuncSetAttribute((const void*)tf32_gemm_kernel<0, false, false, false>,
                         cudaFuncAttributeMaxDynamicSharedMemorySize, GEMM_SMEM_BYTES);
    cudaFuncSetAttribute((const void*)gemm_phix_kernel,
                         cudaFuncAttributeMaxDynamicSharedMemorySize, GEMM_SMEM_BYTES);

    const int KBIG = 1 << 30;

    // launch 0
    ca_kernel<<<(NN + 255) / 256, 256>>>(attr, cw, g_ca);

    for (int l = 0; l < LL; l++) {
        const float* h_in = (l == 0) ? input  : g_hbuf;
        const float* x_in = (l == 0) ? coords : g_xbuf;
        float* h_out = (l == LL - 1) ? (float*)d_out : g_hbuf;
        float* x_out = (l == LL - 1) ? ((float*)d_out + (size_t)NN * HH) : g_xbuf;

        const float* Wr  = W_rad + (size_t)l * 256;
        const float* br  = b_rad + (size_t)l * 16;
        const float* We1 = W_e1 + (size_t)l * 560 * 256;
        const float* be1 = b_e1 + (size_t)l * 256;
        const float* We2 = W_e2 + (size_t)l * 256 * 256;
        const float* be2 = b_e2 + (size_t)l * 256;
        const float* Wc1 = W_c1 + (size_t)l * 256 * 256;
        const float* bc1 = b_c1 + (size_t)l * 256;
        const float* Wc2 = W_c2 + (size_t)l * 256 * 16;
        const float* Wn1 = W_n1 + (size_t)l * 2048 * 256;
        const float* bn1 = b_n1 + (size_t)l * 256;
        const float* Wn2 = W_n2 + (size_t)l * 256 * 256;
        const float* bn2 = b_n2 + (size_t)l * 256;
        const float* lg  = ln_g + (size_t)l * 256;
        const float* lb  = ln_b + (size_t)l * 256;

        // launches 1,2 (layer 0): weight prep + zero agg/xacc
        wpq_kernel<<<(272 * 512 + 255) / 256, 256>>>(We1, g_wpq);
        prep_kernel<<<(unsigned)((PREP_TOT + 255) / 256), 256>>>(
            We2, Wc1, Wn1, Wn2, g_we2t, g_wc1t, g_wn1t, g_wn2t,
            (float4*)g_agg, (float4*)g_xacc);

        // launch 3: PQ = [h|ca] @ Wpq
        tf32_gemm_kernel<0, false, true, false><<<dim3(4, (NN + 127) / 128), 256, GEMM_SMEM_BYTES>>>(
            h_in, 256, g_ca, 16, 256,
            g_wpq, nullptr, nullptr, g_pq, nullptr, nullptr, NN, 512, 272);

        // launch 4: m1 = tf32(silu(P[row]+Q[col]+rad_feat@W1c+be1))
        edge_fuse_kernel<<<EE / 64, 256>>>(g_pq, x_in, el, cw,
                                           Wr, br, We1 + (size_t)512 * 256, be1, g_m1);

        // launch 5 (ncu target): m = tf32(silu(m1@We2+be2)*ew) + agg scatter (red.v2)
        tf32_gemm_kernel<2, true, false, true><<<dim3(2, EE / 128), 256, GEMM_SMEM_BYTES>>>(
            g_m1, 256, nullptr, 0, KBIG,
            g_we2t, be2, ew, g_m, el, g_agg, EE, 256, 256);

        if (l == 0) {
            zero4_kernel<<<(NN/4 + 255) / 256, 256>>>((float4*)g_cnt, (size_t)NN / 4);
            cnt_kernel<<<(EE + 255) / 256, 256>>>(el, g_cnt);
        }

        // fused Wc1 GEMM + phi + x scatter (t1 never stored)
        gemm_phix_kernel<<<dim3(2, EE / 128), 256, GEMM_SMEM_BYTES>>>(
            g_m, g_wc1t, bc1, Wc2, x_in, el, g_xacc);

        // h1 = tf32(silu([agg|h]@Wn1+bn1))
        tf32_gemm_kernel<1, false, true, true><<<dim3(2, (NN + 127) / 128), 256, GEMM_SMEM_BYTES>>>(
            g_agg, 1792, h_in, 256, 1792,
            g_wn1t, bn1, nullptr, g_h1, nullptr, nullptr, NN, 256, 2048);

        // h2 = h1@Wn2+bn2
        tf32_gemm_kernel<0, false, false, false><<<dim3(2, (NN + 127) / 128), 256, GEMM_SMEM_BYTES>>>(
            g_h1, 256, nullptr, 0, KBIG,
            g_wn2t, bn2, nullptr, g_pq, nullptr, nullptr, NN, 256, 256);

        ln_kernel<<<NN, 256>>>(g_pq, lg, lb, h_out);
        x_final_kernel<<<(NN * 12 + 255) / 256, 256>>>(x_in, g_xacc, g_cnt, x_out);
    }
}

// round 8
// speedup vs baseline: 4.1553x; 1.2109x over previous
#include <cuda_runtime.h>
#include <cuda_fp16.h>
#include <cstddef>
#include <cstdint>

#define NN 10000
#define EE 160000
#define RR 7
#define HH 256
#define LL 2
#define EPSV 1e-5f

// ---------------- scratch (float units) ----------------
#define OFF_CA    ((size_t)0)                          // N*16
#define OFF_PQ    (OFF_CA   + (size_t)160000)          // N*512
#define OFF_HCAH  (OFF_PQ   + (size_t)5120000)         // N*288 half
#define OFF_M1H   (OFF_HCAH + (size_t)1440000)         // E*256 half
#define OFF_MH    (OFF_M1H  + (size_t)20480000)        // E*256 half
#define OFF_AGG   (OFF_MH   + (size_t)20480000)        // N*1792 f32
#define OFF_NINH  (OFF_AGG  + (size_t)17920000)        // N*2048 half
#define OFF_H1H   (OFF_NINH + (size_t)10240000)        // N*256 half
#define OFF_HBUF  (OFF_H1H  + (size_t)1280000)         // N*256 f32
#define OFF_XBUF  (OFF_HBUF + (size_t)2560000)         // N*12
#define OFF_XACC  (OFF_XBUF + (size_t)120000)          // N*12
#define OFF_CNT   (OFF_XACC + (size_t)120000)          // N
#define OFF_WPQT  (OFF_CNT  + (size_t)10000)           // 512*288 half
#define OFF_WE2T  (OFF_WPQT + (size_t)73728)           // 256*256 half
#define OFF_WC1T  (OFF_WE2T + (size_t)32768)
#define OFF_WN2T  (OFF_WC1T + (size_t)32768)
#define OFF_WN1T  (OFF_WN2T + (size_t)32768)           // 256*2048 half
#define TOTAL_F   (OFF_WN1T + (size_t)262144)

__device__ float g_buf[TOTAL_F];

__device__ __forceinline__ float silu_f(float v) { return v / (1.0f + __expf(-v)); }

__device__ __forceinline__ void cp_async16(uint32_t dst, const void* src, bool p) {
    asm volatile("cp.async.cg.shared.global [%0], [%1], 16, %2;\n"
                 :: "r"(dst), "l"(src), "r"(p ? 16 : 0));
}
__device__ __forceinline__ void cp_commit() {
    asm volatile("cp.async.commit_group;\n");
}
template <int Np> __device__ __forceinline__ void cp_wait() {
    asm volatile("cp.async.wait_group %0;\n" :: "n"(Np));
}
__device__ __forceinline__ void red_add_v2(float* addr, float a, float b) {
    asm volatile("red.global.add.v2.f32 [%0], {%1, %2};"
                 :: "l"(addr), "f"(a), "f"(b) : "memory");
}

// ---------------- small kernels ----------------
__global__ void ca_kernel(const float* __restrict__ attr, const float* __restrict__ cw,
                          float* __restrict__ ca) {
    int n = blockIdx.x * blockDim.x + threadIdx.x;
    if (n >= NN) return;
    float w0 = cw[n*4+0], w1 = cw[n*4+1], w2 = cw[n*4+2], w3 = cw[n*4+3];
    float inv = 1.0f / (w0 + w1 + w2 + w3);
    const float* a = attr + (size_t)n * 64;
#pragma unroll
    for (int f = 0; f < 16; f++)
        ca[n*16+f] = (a[f]*w0 + a[16+f]*w1 + a[32+f]*w2 + a[48+f]*w3) * inv;
}

__global__ void cnt_kernel(const int* __restrict__ el, float* __restrict__ cnt) {
    int e = blockIdx.x * blockDim.x + threadIdx.x;
    if (e >= EE) return;
    atomicAdd(&cnt[el[3*e]], 1.0f);
}

// 32x32 tile transpose: W [K][256] f32 -> WT [256][K] half
__device__ __forceinline__ void transpose_tile(const float* __restrict__ W,
                                               __half* __restrict__ WT,
                                               int kb, int nb, int K) {
    __shared__ float t[32][33];
    int tx = threadIdx.x & 31, ty = threadIdx.x >> 5;
#pragma unroll
    for (int d = 0; d < 32; d += 8)
        t[ty + d][tx] = W[(size_t)(kb + ty + d) * 256 + nb + tx];
    __syncthreads();
#pragma unroll
    for (int d = 0; d < 32; d += 8)
        WT[(size_t)(nb + ty + d) * K + kb + tx] = __float2half_rn(t[tx][ty + d]);
}

// merged weight prep: 1280 blocks
__global__ void wprep_all(const float* __restrict__ We2, const float* __restrict__ Wc1,
                          const float* __restrict__ Wn2, const float* __restrict__ Wn1,
                          const float* __restrict__ We1,
                          __half* __restrict__ We2T, __half* __restrict__ Wc1T,
                          __half* __restrict__ Wn2T, __half* __restrict__ Wn1T,
                          __half* __restrict__ WpqT) {
    int bid = blockIdx.x;
    if (bid < 192) {
        int w = bid >> 6;
        const float* W = (w == 0) ? We2 : (w == 1) ? Wc1 : Wn2;
        __half* O = (w == 0) ? We2T : (w == 1) ? Wc1T : Wn2T;
        int t = bid & 63;
        transpose_tile(W, O, (t >> 3) * 32, (t & 7) * 32, 256);
    } else if (bid < 704) {
        int t = bid - 192;
        transpose_tile(Wn1, Wn1T, (t >> 3) * 32, (t & 7) * 32, 2048);
    } else {
        int i = (bid - 704) * 256 + threadIdx.x;   // over 512*288
        int n = i / 288, k = i % 288;
        float v = 0.f;
        if (k < 272) {
            int j = (n < 256) ? n : n - 256;
            int kk = (n < 256) ? ((k < 256) ? k : 528 + (k - 256))
                               : ((k < 256) ? 256 + k : 544 + (k - 256));
            v = We1[(size_t)kk * 256 + j];
        }
        WpqT[i] = __float2half_rn(v);
    }
}

// hca pack (half) + zero agg/xacc/cnt.  ranges over 5,952,500 threads
#define HPZ_HCA   1440000u
#define HPZ_AGG   (HPZ_HCA + 4480000u)
#define HPZ_XACC  (HPZ_AGG + 30000u)
#define HPZ_TOT   (HPZ_XACC + 2500u)
__global__ void hca_pack_zero(const float* __restrict__ h, const float* __restrict__ ca,
                              __half2* __restrict__ hca2,
                              float4* __restrict__ agg4, float4* __restrict__ xacc4,
                              float4* __restrict__ cnt4) {
    unsigned i = blockIdx.x * 256 + threadIdx.x;
    const float4 z4 = make_float4(0.f, 0.f, 0.f, 0.f);
    if (i < HPZ_HCA) {
        int n = i / 144, c2 = (int)(i % 144) * 2;
        float v0 = 0.f, v1 = 0.f;
        if (c2 < 256)      { v0 = h[n*256 + c2];      v1 = h[n*256 + c2 + 1]; }
        else if (c2 < 272) { v0 = ca[n*16 + c2 - 256]; v1 = ca[n*16 + c2 - 255]; }
        hca2[i] = __floats2half2_rn(v0, v1);
    } else if (i < HPZ_AGG)  agg4[i - HPZ_HCA] = z4;
    else if (i < HPZ_XACC)   xacc4[i - HPZ_AGG] = z4;
    else if (i < HPZ_TOT)    cnt4[i - HPZ_XACC] = z4;
}

// nin pack: [agg(1792) | h(256)] -> half, N*1024 half2
__global__ void nin_pack(const float* __restrict__ agg, const float* __restrict__ h,
                         __half2* __restrict__ nin2) {
    unsigned i = blockIdx.x * 256 + threadIdx.x;
    if (i >= (unsigned)NN * 1024) return;
    int n = i >> 10, c2 = (int)(i & 1023) * 2;
    float v0, v1;
    if (c2 < 1792) { v0 = agg[(size_t)n*1792 + c2]; v1 = agg[(size_t)n*1792 + c2 + 1]; }
    else           { v0 = h[(size_t)n*256 + c2 - 1792]; v1 = h[(size_t)n*256 + c2 - 1791]; }
    nin2[i] = __floats2half2_rn(v0, v1);
}

// ---------------- fp16 GEMM (m16n8k16), cp.async 3-stage ----------------
// C(MxNc) = act(A(MxK) @ B^T + bias); A half [M][lda], B half [Nc][K] n-major.
#define HAS 56                      // smem stride in halves (112B, conflict-free)
#define HA_SZ (128 * HAS)           // halves per A (or B) stage
#define HNSTG 3
#define HSMEM_BYTES (HNSTG * 2 * HA_SZ * 2)

template <int ACT, bool FUSE_AGG, bool OUT_HALF>
__global__ __launch_bounds__(256) void hgemm_kernel(
    const __half* __restrict__ A, int lda,
    const __half* __restrict__ B,
    const float* __restrict__ bias, const float* __restrict__ rowscale,
    void* __restrict__ Cv,
    const int* __restrict__ el, float* __restrict__ agg,
    int M, int Nc, int K)
{
    extern __shared__ __half hsm[];
    __half* AsBase = hsm;
    __half* BsBase = hsm + HNSTG * HA_SZ;
    uint32_t su = (uint32_t)__cvta_generic_to_shared(hsm);

    int tid = threadIdx.x;
    int rowBase = blockIdx.y * 128, colBase = blockIdx.x * 128;
    int warp = tid >> 5, lane = tid & 31;
    int wm = warp >> 1, wn = warp & 1;
    int gr = lane >> 2, gc = lane & 3;

    float c_[2][8][4];
#pragma unroll
    for (int i = 0; i < 2; i++)
#pragma unroll
        for (int j = 0; j < 8; j++)
#pragma unroll
            for (int q = 0; q < 4; q++) c_[i][j][q] = 0.0f;

    int nt = K >> 5;

    auto load_stage = [&](int s, int t) {
        int k0 = t << 5;
#pragma unroll
        for (int c = 0; c < 2; c++) {
            int L = tid + c * 256;
            int arow = L >> 2, ach = (L & 3) * 8;
            int r = rowBase + arow;
            cp_async16(su + (uint32_t)(s * HA_SZ + arow * HAS + ach) * 2,
                       A + (size_t)r * lda + k0 + ach, r < M);
        }
#pragma unroll
        for (int c = 0; c < 2; c++) {
            int L = tid + c * 256;
            int nrow = L >> 2, bch = (L & 3) * 8;
            cp_async16(su + (uint32_t)(HNSTG * HA_SZ + s * HA_SZ + nrow * HAS + bch) * 2,
                       B + (size_t)(colBase + nrow) * K + k0 + bch, true);
        }
        cp_commit();
    };

#pragma unroll
    for (int s = 0; s < HNSTG - 1; s++) {
        if (s < nt) load_stage(s, s); else cp_commit();
    }

    for (int t = 0; t < nt; t++) {
        cp_wait<HNSTG - 2>();
        __syncthreads();
        int cur = t % HNSTG;
        if (t + HNSTG - 1 < nt) load_stage((t + HNSTG - 1) % HNSTG, t + HNSTG - 1);
        else cp_commit();
        const __half* As = AsBase + cur * HA_SZ;
        const __half* Bs = BsBase + cur * HA_SZ;
#pragma unroll
        for (int kk = 0; kk < 32; kk += 16) {
            uint32_t af[2][4], bf[8][2];
#pragma unroll
            for (int i = 0; i < 2; i++) {
                int r0 = wm * 32 + i * 16 + gr;
                af[i][0] = *(const uint32_t*)&As[r0 * HAS + kk + 2 * gc];
                af[i][1] = *(const uint32_t*)&As[(r0 + 8) * HAS + kk + 2 * gc];
                af[i][2] = *(const uint32_t*)&As[r0 * HAS + kk + 8 + 2 * gc];
                af[i][3] = *(const uint32_t*)&As[(r0 + 8) * HAS + kk + 8 + 2 * gc];
            }
#pragma unroll
            for (int j = 0; j < 8; j++) {
                int cn = wn * 64 + j * 8 + gr;
                bf[j][0] = *(const uint32_t*)&Bs[cn * HAS + kk + 2 * gc];
                bf[j][1] = *(const uint32_t*)&Bs[cn * HAS + kk + 8 + 2 * gc];
            }
#pragma unroll
            for (int i = 0; i < 2; i++)
#pragma unroll
                for (int j = 0; j < 8; j++) {
                    asm volatile(
                        "mma.sync.aligned.m16n8k16.row.col.f32.f16.f16.f32 "
                        "{%0,%1,%2,%3}, {%4,%5,%6,%7}, {%8,%9}, {%0,%1,%2,%3};\n"
                        : "+f"(c_[i][j][0]), "+f"(c_[i][j][1]),
                          "+f"(c_[i][j][2]), "+f"(c_[i][j][3])
                        : "r"(af[i][0]), "r"(af[i][1]), "r"(af[i][2]), "r"(af[i][3]),
                          "r"(bf[j][0]), "r"(bf[j][1]));
                }
        }
        __syncthreads();
    }

    // epilogue
#pragma unroll
    for (int i = 0; i < 2; i++) {
        int rr0 = rowBase + wm * 32 + i * 16 + gr;
#pragma unroll
        for (int half = 0; half < 2; half++) {
            int r = rr0 + half * 8;
            if (r >= M) continue;
            float sc = (ACT == 2) ? rowscale[r] : 1.0f;
            size_t ab = 0;
            if (FUSE_AGG) {
                int cc = el[3 * r + 1], rl = el[3 * r + 2];
                ab = ((size_t)cc * RR + rl) * 256;
            }
#pragma unroll
            for (int j = 0; j < 8; j++) {
                int cn = colBase + wn * 64 + j * 8 + gc * 2;
                float b0 = bias ? bias[cn] : 0.f;
                float b1 = bias ? bias[cn + 1] : 0.f;
                float v0 = c_[i][j][half * 2 + 0] + b0;
                float v1 = c_[i][j][half * 2 + 1] + b1;
                if (ACT >= 1) { v0 = silu_f(v0); v1 = silu_f(v1); }
                if (ACT == 2) { v0 *= sc; v1 *= sc; }
                if (OUT_HALF) {
                    *(__half2*)&((__half*)Cv)[(size_t)r * Nc + cn] = __floats2half2_rn(v0, v1);
                } else {
                    *(float2*)&((float*)Cv)[(size_t)r * Nc + cn] = make_float2(v0, v1);
                }
                if (FUSE_AGG) red_add_v2(&agg[ab + cn], v0, v1);
            }
        }
    }
}

// ---------------- fused Wc1 fp16 GEMM + phi + x-scatter ----------------
__global__ __launch_bounds__(256) void gemm_phix_kernel(
    const __half* __restrict__ A,           // m half, E x 256
    const __half* __restrict__ B,           // Wc1T half [256][256]
    const float* __restrict__ bc1,
    const float* __restrict__ Wc2,          // [256,16] fp32
    const float* __restrict__ x, const int* __restrict__ el,
    float* __restrict__ xacc)
{
    extern __shared__ __half hsm[];
    __half* AsBase = hsm;
    __half* BsBase = hsm + HNSTG * HA_SZ;
    uint32_t su = (uint32_t)__cvta_generic_to_shared(hsm);

    int tid = threadIdx.x;
    int rowBase = blockIdx.y * 128, colBase = blockIdx.x * 128;
    int warp = tid >> 5, lane = tid & 31;
    int wm = warp >> 1, wn = warp & 1;
    int gr = lane >> 2, gc = lane & 3;

    float c_[2][8][4];
#pragma unroll
    for (int i = 0; i < 2; i++)
#pragma unroll
        for (int j = 0; j < 8; j++)
#pragma unroll
            for (int q = 0; q < 4; q++) c_[i][j][q] = 0.0f;

    const int nt = 8;   // K=256

    auto load_stage = [&](int s, int t) {
        int k0 = t << 5;
#pragma unroll
        for (int c = 0; c < 2; c++) {
            int L = tid + c * 256;
            int arow = L >> 2, ach = (L & 3) * 8;
            cp_async16(su + (uint32_t)(s * HA_SZ + arow * HAS + ach) * 2,
                       A + (size_t)(rowBase + arow) * 256 + k0 + ach, true);
        }
#pragma unroll
        for (int c = 0; c < 2; c++) {
            int L = tid + c * 256;
            int nrow = L >> 2, bch = (L & 3) * 8;
            cp_async16(su + (uint32_t)(HNSTG * HA_SZ + s * HA_SZ + nrow * HAS + bch) * 2,
                       B + (size_t)(colBase + nrow) * 256 + k0 + bch, true);
        }
        cp_commit();
    };

#pragma unroll
    for (int s = 0; s < HNSTG - 1; s++) load_stage(s, s);

    for (int t = 0; t < nt; t++) {
        cp_wait<HNSTG - 2>();
        __syncthreads();
        int cur = t % HNSTG;
        if (t + HNSTG - 1 < nt) load_stage((t + HNSTG - 1) % HNSTG, t + HNSTG - 1);
        else cp_commit();
        const __half* As = AsBase + cur * HA_SZ;
        const __half* Bs = BsBase + cur * HA_SZ;
#pragma unroll
        for (int kk = 0; kk < 32; kk += 16) {
            uint32_t af[2][4], bf[8][2];
#pragma unroll
            for (int i = 0; i < 2; i++) {
                int r0 = wm * 32 + i * 16 + gr;
                af[i][0] = *(const uint32_t*)&As[r0 * HAS + kk + 2 * gc];
                af[i][1] = *(const uint32_t*)&As[(r0 + 8) * HAS + kk + 2 * gc];
                af[i][2] = *(const uint32_t*)&As[r0 * HAS + kk + 8 + 2 * gc];
                af[i][3] = *(const uint32_t*)&As[(r0 + 8) * HAS + kk + 8 + 2 * gc];
            }
#pragma unroll
            for (int j = 0; j < 8; j++) {
                int cn = wn * 64 + j * 8 + gr;
                bf[j][0] = *(const uint32_t*)&Bs[cn * HAS + kk + 2 * gc];
                bf[j][1] = *(const uint32_t*)&Bs[cn * HAS + kk + 8 + 2 * gc];
            }
#pragma unroll
            for (int i = 0; i < 2; i++)
#pragma unroll
                for (int j = 0; j < 8; j++) {
                    asm volatile(
                        "mma.sync.aligned.m16n8k16.row.col.f32.f16.f16.f32 "
                        "{%0,%1,%2,%3}, {%4,%5,%6,%7}, {%8,%9}, {%0,%1,%2,%3};\n"
                        : "+f"(c_[i][j][0]), "+f"(c_[i][j][1]),
                          "+f"(c_[i][j][2]), "+f"(c_[i][j][3])
                        : "r"(af[i][0]), "r"(af[i][1]), "r"(af[i][2]), "r"(af[i][3]),
                          "r"(bf[j][0]), "r"(bf[j][1]));
                }
        }
        __syncthreads();
    }

    // ---- epilogue: phi partial over this CTA's 128 cols (fp32) ----
    float* sT  = (float*)hsm;             // [128][36]
    float* sW2 = (float*)hsm + 128 * 36;  // [128][17]
    float* sB1 = sW2 + 128 * 17;          // [128]

    if (tid < 128) sB1[tid] = bc1[colBase + tid];
    for (int idx = tid; idx < 128 * 16; idx += 256) {
        int rr = idx >> 4, n = idx & 15;
        sW2[rr * 17 + n] = Wc2[(size_t)(colBase + rr) * 16 + n];
    }

    float p[8];
#pragma unroll
    for (int n = 0; n < 8; n++) p[n] = 0.0f;
    int pr = tid >> 1;
    int pn0 = (tid & 1) * 8;

#pragma unroll 1
    for (int ch = 0; ch < 4; ch++) {
        __syncthreads();
        if (wn == (ch >> 1)) {
            int jb = (ch & 1) * 4;
#pragma unroll
            for (int jj = 0; jj < 4; jj++) {
                int j = jb + jj;
                int lcol = j * 8 + gc * 2 - (ch & 1) * 32;
                float bb0 = sB1[wn * 64 + j * 8 + gc * 2];
                float bb1 = sB1[wn * 64 + j * 8 + gc * 2 + 1];
#pragma unroll
                for (int i = 0; i < 2; i++)
#pragma unroll
                    for (int half = 0; half < 2; half++) {
                        int lr = wm * 32 + i * 16 + half * 8 + gr;
                        float v0 = silu_f(c_[i][j][half * 2 + 0] + bb0);
                        float v1 = silu_f(c_[i][j][half * 2 + 1] + bb1);
                        *(float2*)&sT[lr * 36 + lcol] = make_float2(v0, v1);
                    }
            }
        }
        __syncthreads();
#pragma unroll
        for (int cb = 0; cb < 8; cb++) {
            float4 t4 = *(const float4*)&sT[pr * 36 + cb * 4];
#pragma unroll
            for (int k = 0; k < 4; k++) {
                float tv = (&t4.x)[k];
                int wr = ch * 32 + cb * 4 + k;
#pragma unroll
                for (int n = 0; n < 8; n++)
                    p[n] = fmaf(tv, sW2[wr * 17 + pn0 + n], p[n]);
            }
        }
    }

    float q[8];
#pragma unroll
    for (int n = 0; n < 8; n++) q[n] = __shfl_xor_sync(0xFFFFFFFFu, p[n], 1);

    if ((tid & 1) == 0) {
        float phi[16];
#pragma unroll
        for (int n = 0; n < 8; n++) { phi[n] = p[n]; phi[8 + n] = q[n]; }
        int e = rowBase + pr;
        int rw = el[3 * e], cl = el[3 * e + 1];
        float xr[12], xc[12];
#pragma unroll
        for (int d = 0; d < 12; d++) { xr[d] = x[rw * 12 + d]; xc[d] = x[cl * 12 + d]; }
#pragma unroll
        for (int i2 = 0; i2 < 4; i2++)
#pragma unroll
            for (int d = 0; d < 3; d++) {
                float s = 0.0f;
#pragma unroll
                for (int j2 = 0; j2 < 4; j2++)
                    s = fmaf(xr[i2 * 3 + d] - xc[j2 * 3 + d], phi[i2 * 4 + j2], s);
                atomicAdd(&xacc[rw * 12 + i2 * 3 + d], 0.25f * s);
            }
    }
}

// ---------------- edge fuse (half out) ----------------
__global__ __launch_bounds__(256) void edge_fuse_kernel(
    const float* __restrict__ PQ,
    const float* __restrict__ x, const int* __restrict__ el,
    const float* __restrict__ cw,
    const float* __restrict__ Wrad, const float* __restrict__ brad,
    const float* __restrict__ W1c, const float* __restrict__ be1,
    __half* __restrict__ m1)
{
    __shared__ __align__(16) float sW1c[16][256];
    __shared__ float sWrad[16][16];
    __shared__ float sbrad[16];
    __shared__ __align__(16) float sbe1[256];
    __shared__ float srad[8][16];
    __shared__ float srf[8][16];
    int tid = threadIdx.x;
    for (int i = tid; i < 16 * 256; i += 256) sW1c[i >> 8][i & 255] = W1c[i];
    sbe1[tid] = be1[tid];
    { int r = tid >> 4, c = tid & 15; sWrad[r][c] = Wrad[tid]; }
    if (tid < 16) sbrad[tid] = brad[tid];
    __syncthreads();

    int warp = tid >> 5, lane = tid & 31;
#pragma unroll 1
    for (int ei = 0; ei < 8; ei++) {
        int e = blockIdx.x * 64 + warp * 8 + ei;
        int row = el[3*e], col = el[3*e+1];

        if (lane < 16) {
            int i = lane >> 2, j = lane & 3;
            float dx = x[row*12 + i*3 + 0] - x[col*12 + j*3 + 0];
            float dy = x[row*12 + i*3 + 1] - x[col*12 + j*3 + 1];
            float dz = x[row*12 + i*3 + 2] - x[col*12 + j*3 + 2];
            srad[warp][lane] = (dx*dx + dy*dy + dz*dz) * cw[row*4 + i] * cw[col*4 + j];
        }
        __syncwarp();
        if (lane < 16) {
            float acc = sbrad[lane];
#pragma unroll
            for (int k = 0; k < 16; k++) acc = fmaf(srad[warp][k], sWrad[k][lane], acc);
            srf[warp][lane] = silu_f(acc);
        }
        __syncwarp();

        const float4* Pr = (const float4*)(PQ + (size_t)row * 512);
        const float4* Qc = (const float4*)(PQ + (size_t)col * 512 + 256);
        __half* Om = m1 + (size_t)e * 256;
#pragma unroll
        for (int half = 0; half < 2; half++) {
            int o4 = lane * 2 + half;
            float4 pv = Pr[o4], qv = Qc[o4];
            float4 b = ((const float4*)sbe1)[o4];
            float4 s = make_float4(pv.x + qv.x + b.x, pv.y + qv.y + b.y,
                                   pv.z + qv.z + b.z, pv.w + qv.w + b.w);
#pragma unroll
            for (int k = 0; k < 16; k++) {
                float rk = srf[warp][k];
                float4 w = ((const float4*)&sW1c[k][0])[o4];
                s.x = fmaf(rk, w.x, s.x); s.y = fmaf(rk, w.y, s.y);
                s.z = fmaf(rk, w.z, s.z); s.w = fmaf(rk, w.w, s.w);
            }
            *(__half2*)&Om[o4 * 4]     = __floats2half2_rn(silu_f(s.x), silu_f(s.y));
            *(__half2*)&Om[o4 * 4 + 2] = __floats2half2_rn(silu_f(s.z), silu_f(s.w));
        }
        __syncwarp();
    }
}

// ---------------- layernorm ----------------
__global__ void ln_kernel(const float* __restrict__ h2, const float* __restrict__ g,
                          const float* __restrict__ b, float* __restrict__ out) {
    int n = blockIdx.x;
    int t = threadIdx.x;
    float v = h2[(size_t)n * 256 + t];
    float a = v, sq = v * v;
#pragma unroll
    for (int o = 16; o > 0; o >>= 1) {
        a  += __shfl_down_sync(0xFFFFFFFFu, a, o);
        sq += __shfl_down_sync(0xFFFFFFFFu, sq, o);
    }
    __shared__ float s1[8], s2[8];
    if ((t & 31) == 0) { s1[t >> 5] = a; s2[t >> 5] = sq; }
    __syncthreads();
    __shared__ float mu, rs;
    if (t == 0) {
        float A = 0.f, B = 0.f;
#pragma unroll
        for (int i = 0; i < 8; i++) { A += s1[i]; B += s2[i]; }
        float m = A * (1.0f / 256.0f);
        mu = m;
        rs = rsqrtf(B * (1.0f / 256.0f) - m * m + EPSV);
    }
    __syncthreads();
    out[(size_t)n * 256 + t] = (v - mu) * rs * g[t] + b[t];
}

__global__ void x_final_kernel(const float* __restrict__ xin, const float* __restrict__ xacc,
                               const float* __restrict__ cnt, float* __restrict__ xout) {
    int i = blockIdx.x * blockDim.x + threadIdx.x;
    if (i >= NN * 12) return;
    int n = i / 12;
    xout[i] = xin[i] + xacc[i] / fmaxf(cnt[n], 1.0f);
}

// ---------------- host ----------------
extern "C" void kernel_launch(void* const* d_in, const int* in_sizes, int n_in,
                              void* d_out, int out_size) {
    const float* input  = nullptr;
    const float* coords = nullptr;
    const float* attr   = nullptr;
    const float* cw     = nullptr;
    const float* ew     = nullptr;
    const int*   el     = nullptr;
    for (int i = 0; i < 6; i++) {
        switch (in_sizes[i]) {
            case NN * HH:     input  = (const float*)d_in[i]; break;
            case NN * 4 * 3:  coords = (const float*)d_in[i]; break;
            case NN * 4 * 16: attr   = (const float*)d_in[i]; break;
            case NN * 4:      cw     = (const float*)d_in[i]; break;
            case EE:          ew     = (const float*)d_in[i]; break;
            case EE * 3:      el     = (const int*)  d_in[i]; break;
        }
    }
    const float* W_rad = (const float*)d_in[6];
    const float* b_rad = (const float*)d_in[7];
    const float* W_e1  = (const float*)d_in[8];
    const float* b_e1  = (const float*)d_in[9];
    const float* W_e2  = (const float*)d_in[10];
    const float* b_e2  = (const float*)d_in[11];
    const float* W_c1  = (const float*)d_in[12];
    const float* b_c1  = (const float*)d_in[13];
    const float* W_c2  = (const float*)d_in[14];
    const float* W_n1  = (const float*)d_in[15];
    const float* b_n1  = (const float*)d_in[16];
    const float* W_n2  = (const float*)d_in[17];
    const float* b_n2  = (const float*)d_in[18];
    const float* ln_g  = (const float*)d_in[19];
    const float* ln_b  = (const float*)d_in[20];

    float* buf = nullptr;
    cudaGetSymbolAddress((void**)&buf, g_buf);

    float*  g_ca   = buf + OFF_CA;
    float*  g_pq   = buf + OFF_PQ;
    __half* g_hcah = (__half*)(buf + OFF_HCAH);
    __half* g_m1h  = (__half*)(buf + OFF_M1H);
    __half* g_mh   = (__half*)(buf + OFF_MH);
    float*  g_agg  = buf + OFF_AGG;
    __half* g_ninh = (__half*)(buf + OFF_NINH);
    __half* g_h1h  = (__half*)(buf + OFF_H1H);
    float*  g_hbuf = buf + OFF_HBUF;
    float*  g_xbuf = buf + OFF_XBUF;
    float*  g_xacc = buf + OFF_XACC;
    float*  g_cnt  = buf + OFF_CNT;
    __half* g_wpqt = (__half*)(buf + OFF_WPQT);
    __half* g_we2t = (__half*)(buf + OFF_WE2T);
    __half* g_wc1t = (__half*)(buf + OFF_WC1T);
    __half* g_wn2t = (__half*)(buf + OFF_WN2T);
    __half* g_wn1t = (__half*)(buf + OFF_WN1T);

    cudaFuncSetAttribute((const void*)hgemm_kernel<0, false, false>,
                         cudaFuncAttributeMaxDynamicSharedMemorySize, HSMEM_BYTES);
    cudaFuncSetAttribute((const void*)hgemm_kernel<2, true, true>,
                         cudaFuncAttributeMaxDynamicSharedMemorySize, HSMEM_BYTES);
    cudaFuncSetAttribute((const void*)hgemm_kernel<1, false, true>,
                         cudaFuncAttributeMaxDynamicSharedMemorySize, HSMEM_BYTES);
    cudaFuncSetAttribute((const void*)gemm_phix_kernel,
                         cudaFuncAttributeMaxDynamicSharedMemorySize, HSMEM_BYTES);

    // launch 0
    ca_kernel<<<(NN + 255) / 256, 256>>>(attr, cw, g_ca);

    for (int l = 0; l < LL; l++) {
        const float* h_in = (l == 0) ? input  : g_hbuf;
        const float* x_in = (l == 0) ? coords : g_xbuf;
        float* h_out = (l == LL - 1) ? (float*)d_out : g_hbuf;
        float* x_out = (l == LL - 1) ? ((float*)d_out + (size_t)NN * HH) : g_xbuf;

        const float* Wr  = W_rad + (size_t)l * 256;
        const float* br  = b_rad + (size_t)l * 16;
        const float* We1 = W_e1 + (size_t)l * 560 * 256;
        const float* be1 = b_e1 + (size_t)l * 256;
        const float* We2 = W_e2 + (size_t)l * 256 * 256;
        const float* be2 = b_e2 + (size_t)l * 256;
        const float* Wc1 = W_c1 + (size_t)l * 256 * 256;
        const float* bc1 = b_c1 + (size_t)l * 256;
        const float* Wc2 = W_c2 + (size_t)l * 256 * 16;
        const float* Wn1 = W_n1 + (size_t)l * 2048 * 256;
        const float* bn1 = b_n1 + (size_t)l * 256;
        const float* Wn2 = W_n2 + (size_t)l * 256 * 256;
        const float* bn2 = b_n2 + (size_t)l * 256;
        const float* lg  = ln_g + (size_t)l * 256;
        const float* lb  = ln_b + (size_t)l * 256;

        // 1: weight prep (transpose + half)
        wprep_all<<<1280, 256>>>(We2, Wc1, Wn2, Wn1, We1,
                                 g_we2t, g_wc1t, g_wn2t, g_wn1t, g_wpqt);
        // 2: hca pack + zero agg/xacc/cnt
        hca_pack_zero<<<(HPZ_TOT + 255) / 256, 256>>>(
            h_in, g_ca, (__half2*)g_hcah, (float4*)g_agg, (float4*)g_xacc, (float4*)g_cnt);
        // 3: PQ = hca @ WpqT^T  (fp32 out)
        hgemm_kernel<0, false, false><<<dim3(4, (NN + 127) / 128), 256, HSMEM_BYTES>>>(
            g_hcah, 288, g_wpqt, nullptr, nullptr, g_pq, nullptr, nullptr, NN, 512, 288);
        // 4: m1 = half(silu(P[row]+Q[col]+rad_feat@W1c+be1))
        edge_fuse_kernel<<<EE / 64, 256>>>(g_pq, x_in, el, cw,
                                           Wr, br, We1 + (size_t)512 * 256, be1, g_m1h);
        // 5 (ncu target): m = half(silu(m1@We2+be2)*ew) + fp32 agg scatter
        hgemm_kernel<2, true, true><<<dim3(2, EE / 128), 256, HSMEM_BYTES>>>(
            g_m1h, 256, g_we2t, be2, ew, g_mh, el, g_agg, EE, 256, 256);
        // 6: cnt (cnt zeroed in hca_pack_zero)
        cnt_kernel<<<(EE + 255) / 256, 256>>>(el, g_cnt);
        // fused Wc1 GEMM + phi + x scatter
        gemm_phix_kernel<<<dim3(2, EE / 128), 256, HSMEM_BYTES>>>(
            g_mh, g_wc1t, bc1, Wc2, x_in, el, g_xacc);
        // nin pack (agg fp32 + h fp32 -> half)
        nin_pack<<<(NN * 1024 + 255) / 256, 256>>>(g_agg, h_in, (__half2*)g_ninh);
        // h1 = half(silu(nin@Wn1+bn1))
        hgemm_kernel<1, false, true><<<dim3(2, (NN + 127) / 128), 256, HSMEM_BYTES>>>(
            g_ninh, 2048, g_wn1t, bn1, nullptr, g_h1h, nullptr, nullptr, NN, 256, 2048);
        // h2 = h1@Wn2+bn2 (fp32 out)
        hgemm_kernel<0, false, false><<<dim3(2, (NN + 127) / 128), 256, HSMEM_BYTES>>>(
            g_h1h, 256, g_wn2t, bn2, nullptr, g_pq, nullptr, nullptr, NN, 256, 256);

        ln_kernel<<<NN, 256>>>(g_pq, lg, lb, h_out);
        x_final_kernel<<<(NN * 12 + 255) / 256, 256>>>(x_in, g_xacc, g_cnt, x_out);
    }
}

// round 10
// speedup vs baseline: 4.3349x; 1.0432x over previous
#include <cuda_runtime.h>
#include <cuda_fp16.h>
#include <cstddef>
#include <cstdint>

#define NN 10000
#define EE 160000
#define RR 7
#define HH 256
#define LL 2
#define EPSV 1e-5f

// ---------------- scratch (float units) ----------------
#define OFF_CA    ((size_t)0)                          // N*16
#define OFF_PQ    (OFF_CA   + (size_t)160000)          // N*512
#define OFF_HCAH  (OFF_PQ   + (size_t)5120000)         // N*288 half
#define OFF_M1H   (OFF_HCAH + (size_t)1440000)         // E*256 half
#define OFF_MH    (OFF_M1H  + (size_t)20480000)        // E*256 half
#define OFF_AGG   (OFF_MH   + (size_t)20480000)        // N*1792 f32
#define OFF_NINH  (OFF_AGG  + (size_t)17920000)        // N*2048 half
#define OFF_H1H   (OFF_NINH + (size_t)10240000)        // N*256 half
#define OFF_HBUF  (OFF_H1H  + (size_t)1280000)         // N*256 f32
#define OFF_XBUF  (OFF_HBUF + (size_t)2560000)         // N*12
#define OFF_XACC  (OFF_XBUF + (size_t)120000)          // N*12
#define OFF_CNT   (OFF_XACC + (size_t)120000)          // N
#define OFF_WPQT  (OFF_CNT  + (size_t)10000)           // 512*288 half
#define OFF_WE2T  (OFF_WPQT + (size_t)73728)           // 256*256 half
#define OFF_WC1T  (OFF_WE2T + (size_t)32768)
#define OFF_WN2T  (OFF_WC1T + (size_t)32768)
#define OFF_WN1T  (OFF_WN2T + (size_t)32768)           // 256*2048 half
#define TOTAL_F   (OFF_WN1T + (size_t)262144)

__device__ float g_buf[TOTAL_F];

__device__ __forceinline__ float silu_f(float v) { return v / (1.0f + __expf(-v)); }

__device__ __forceinline__ void cp_async16(uint32_t dst, const void* src, bool p) {
    asm volatile("cp.async.cg.shared.global [%0], [%1], 16, %2;\n"
                 :: "r"(dst), "l"(src), "r"(p ? 16 : 0));
}
__device__ __forceinline__ void cp_commit() {
    asm volatile("cp.async.commit_group;\n");
}
template <int Np> __device__ __forceinline__ void cp_wait() {
    asm volatile("cp.async.wait_group %0;\n" :: "n"(Np));
}
__device__ __forceinline__ void red_add_v2(float* addr, float a, float b) {
    asm volatile("red.global.add.v2.f32 [%0], {%1, %2};"
                 :: "l"(addr), "f"(a), "f"(b) : "memory");
}

// ---------------- small kernels ----------------
__global__ void ca_kernel(const float* __restrict__ attr, const float* __restrict__ cw,
                          float* __restrict__ ca) {
    int n = blockIdx.x * blockDim.x + threadIdx.x;
    if (n >= NN) return;
    float w0 = cw[n*4+0], w1 = cw[n*4+1], w2 = cw[n*4+2], w3 = cw[n*4+3];
    float inv = 1.0f / (w0 + w1 + w2 + w3);
    const float* a = attr + (size_t)n * 64;
#pragma unroll
    for (int f = 0; f < 16; f++)
        ca[n*16+f] = (a[f]*w0 + a[16+f]*w1 + a[32+f]*w2 + a[48+f]*w3) * inv;
}

__global__ void cnt_kernel(const int* __restrict__ el, float* __restrict__ cnt) {
    int e = blockIdx.x * blockDim.x + threadIdx.x;
    if (e >= EE) return;
    atomicAdd(&cnt[el[3*e]], 1.0f);
}

// 32x32 tile transpose: W [K][256] f32 -> WT [256][K] half
__device__ __forceinline__ void transpose_tile(const float* __restrict__ W,
                                               __half* __restrict__ WT,
                                               int kb, int nb, int K) {
    __shared__ float t[32][33];
    int tx = threadIdx.x & 31, ty = threadIdx.x >> 5;
#pragma unroll
    for (int d = 0; d < 32; d += 8)
        t[ty + d][tx] = W[(size_t)(kb + ty + d) * 256 + nb + tx];
    __syncthreads();
#pragma unroll
    for (int d = 0; d < 32; d += 8)
        WT[(size_t)(nb + ty + d) * K + kb + tx] = __float2half_rn(t[tx][ty + d]);
}

// merged weight prep: 1280 blocks
__global__ void wprep_all(const float* __restrict__ We2, const float* __restrict__ Wc1,
                          const float* __restrict__ Wn2, const float* __restrict__ Wn1,
                          const float* __restrict__ We1,
                          __half* __restrict__ We2T, __half* __restrict__ Wc1T,
                          __half* __restrict__ Wn2T, __half* __restrict__ Wn1T,
                          __half* __restrict__ WpqT) {
    int bid = blockIdx.x;
    if (bid < 192) {
        int w = bid >> 6;
        const float* W = (w == 0) ? We2 : (w == 1) ? Wc1 : Wn2;
        __half* O = (w == 0) ? We2T : (w == 1) ? Wc1T : Wn2T;
        int t = bid & 63;
        transpose_tile(W, O, (t >> 3) * 32, (t & 7) * 32, 256);
    } else if (bid < 704) {
        int t = bid - 192;
        transpose_tile(Wn1, Wn1T, (t >> 3) * 32, (t & 7) * 32, 2048);
    } else {
        int i = (bid - 704) * 256 + threadIdx.x;   // over 512*288
        int n = i / 288, k = i % 288;
        float v = 0.f;
        if (k < 272) {
            int j = (n < 256) ? n : n - 256;
            int kk = (n < 256) ? ((k < 256) ? k : 528 + (k - 256))
                               : ((k < 256) ? 256 + k : 544 + (k - 256));
            v = We1[(size_t)kk * 256 + j];
        }
        WpqT[i] = __float2half_rn(v);
    }
}

// hca pack (half) + zero agg/xacc/cnt
#define HPZ_HCA   1440000u
#define HPZ_AGG   (HPZ_HCA + 4480000u)
#define HPZ_XACC  (HPZ_AGG + 30000u)
#define HPZ_TOT   (HPZ_XACC + 2500u)
__global__ void hca_pack_zero(const float* __restrict__ h, const float* __restrict__ ca,
                              __half2* __restrict__ hca2,
                              float4* __restrict__ agg4, float4* __restrict__ xacc4,
                              float4* __restrict__ cnt4) {
    unsigned i = blockIdx.x * 256 + threadIdx.x;
    const float4 z4 = make_float4(0.f, 0.f, 0.f, 0.f);
    if (i < HPZ_HCA) {
        int n = i / 144, c2 = (int)(i % 144) * 2;
        float v0 = 0.f, v1 = 0.f;
        if (c2 < 256)      { v0 = h[n*256 + c2];      v1 = h[n*256 + c2 + 1]; }
        else if (c2 < 272) { v0 = ca[n*16 + c2 - 256]; v1 = ca[n*16 + c2 - 255]; }
        hca2[i] = __floats2half2_rn(v0, v1);
    } else if (i < HPZ_AGG)  agg4[i - HPZ_HCA] = z4;
    else if (i < HPZ_XACC)   xacc4[i - HPZ_AGG] = z4;
    else if (i < HPZ_TOT)    cnt4[i - HPZ_XACC] = z4;
}

// nin pack: [agg(1792) | h(256)] -> half
__global__ void nin_pack(const float* __restrict__ agg, const float* __restrict__ h,
                         __half2* __restrict__ nin2) {
    unsigned i = blockIdx.x * 256 + threadIdx.x;
    if (i >= (unsigned)NN * 1024) return;
    int n = i >> 10, c2 = (int)(i & 1023) * 2;
    float v0, v1;
    if (c2 < 1792) { v0 = agg[(size_t)n*1792 + c2]; v1 = agg[(size_t)n*1792 + c2 + 1]; }
    else           { v0 = h[(size_t)n*256 + c2 - 1792]; v1 = h[(size_t)n*256 + c2 - 1791]; }
    nin2[i] = __floats2half2_rn(v0, v1);
}

// ---------------- fp16 GEMM (m16n8k16), 512 threads, warp tile 32x32 ----------------
#define HAS 56
#define HA_SZ (128 * HAS)
#define HNSTG 3
#define HSMEM_BYTES (HNSTG * 2 * HA_SZ * 2)

template <int ACT, bool FUSE_AGG, bool OUT_HALF>
__global__ __launch_bounds__(512, 2) void hgemm_kernel(
    const __half* __restrict__ A, int lda,
    const __half* __restrict__ B,
    const float* __restrict__ bias, const float* __restrict__ rowscale,
    void* __restrict__ Cv,
    const int* __restrict__ el, float* __restrict__ agg,
    int M, int Nc, int K)
{
    extern __shared__ __half hsm[];
    __half* AsBase = hsm;
    __half* BsBase = hsm + HNSTG * HA_SZ;
    uint32_t su = (uint32_t)__cvta_generic_to_shared(hsm);

    int tid = threadIdx.x;
    int rowBase = blockIdx.y * 128, colBase = blockIdx.x * 128;
    int warp = tid >> 5, lane = tid & 31;
    int wm = warp >> 2, wn = warp & 3;
    int gr = lane >> 2, gc = lane & 3;

    float c_[2][4][4];
#pragma unroll
    for (int i = 0; i < 2; i++)
#pragma unroll
        for (int j = 0; j < 4; j++)
#pragma unroll
            for (int q = 0; q < 4; q++) c_[i][j][q] = 0.0f;

    int nt = K >> 5;

    auto load_stage = [&](int s, int t) {
        int k0 = t << 5;
        {
            int arow = tid >> 2, ach = (tid & 3) * 8;
            int r = rowBase + arow;
            cp_async16(su + (uint32_t)(s * HA_SZ + arow * HAS + ach) * 2,
                       A + (size_t)r * lda + k0 + ach, r < M);
        }
        {
            int nrow = tid >> 2, bch = (tid & 3) * 8;
            cp_async16(su + (uint32_t)(HNSTG * HA_SZ + s * HA_SZ + nrow * HAS + bch) * 2,
                       B + (size_t)(colBase + nrow) * K + k0 + bch, true);
        }
        cp_commit();
    };

#pragma unroll
    for (int s = 0; s < HNSTG - 1; s++) {
        if (s < nt) load_stage(s, s); else cp_commit();
    }

    for (int t = 0; t < nt; t++) {
        cp_wait<HNSTG - 2>();
        __syncthreads();
        int cur = t % HNSTG;
        if (t + HNSTG - 1 < nt) load_stage((t + HNSTG - 1) % HNSTG, t + HNSTG - 1);
        else cp_commit();
        const __half* As = AsBase + cur * HA_SZ;
        const __half* Bs = BsBase + cur * HA_SZ;
#pragma unroll
        for (int kk = 0; kk < 32; kk += 16) {
            uint32_t af[2][4], bf[4][2];
#pragma unroll
            for (int i = 0; i < 2; i++) {
                int r0 = wm * 32 + i * 16 + gr;
                af[i][0] = *(const uint32_t*)&As[r0 * HAS + kk + 2 * gc];
                af[i][1] = *(const uint32_t*)&As[(r0 + 8) * HAS + kk + 2 * gc];
                af[i][2] = *(const uint32_t*)&As[r0 * HAS + kk + 8 + 2 * gc];
                af[i][3] = *(const uint32_t*)&As[(r0 + 8) * HAS + kk + 8 + 2 * gc];
            }
#pragma unroll
            for (int j = 0; j < 4; j++) {
                int cn = wn * 32 + j * 8 + gr;
                bf[j][0] = *(const uint32_t*)&Bs[cn * HAS + kk + 2 * gc];
                bf[j][1] = *(const uint32_t*)&Bs[cn * HAS + kk + 8 + 2 * gc];
            }
#pragma unroll
            for (int i = 0; i < 2; i++)
#pragma unroll
                for (int j = 0; j < 4; j++) {
                    asm volatile(
                        "mma.sync.aligned.m16n8k16.row.col.f32.f16.f16.f32 "
                        "{%0,%1,%2,%3}, {%4,%5,%6,%7}, {%8,%9}, {%0,%1,%2,%3};\n"
                        : "+f"(c_[i][j][0]), "+f"(c_[i][j][1]),
                          "+f"(c_[i][j][2]), "+f"(c_[i][j][3])
                        : "r"(af[i][0]), "r"(af[i][1]), "r"(af[i][2]), "r"(af[i][3]),
                          "r"(bf[j][0]), "r"(bf[j][1]));
                }
        }
        __syncthreads();
    }

    // epilogue
#pragma unroll
    for (int i = 0; i < 2; i++) {
        int rr0 = rowBase + wm * 32 + i * 16 + gr;
#pragma unroll
        for (int half = 0; half < 2; half++) {
            int r = rr0 + half * 8;
            if (r >= M) continue;
            float sc = (ACT == 2) ? rowscale[r] : 1.0f;
            size_t ab = 0;
            if (FUSE_AGG) {
                int cc = el[3 * r + 1], rl = el[3 * r + 2];
                ab = ((size_t)cc * RR + rl) * 256;
            }
#pragma unroll
            for (int j = 0; j < 4; j++) {
                int cn = colBase + wn * 32 + j * 8 + gc * 2;
                float b0 = bias ? bias[cn] : 0.f;
                float b1 = bias ? bias[cn + 1] : 0.f;
                float v0 = c_[i][j][half * 2 + 0] + b0;
                float v1 = c_[i][j][half * 2 + 1] + b1;
                if (ACT >= 1) { v0 = silu_f(v0); v1 = silu_f(v1); }
                if (ACT == 2) { v0 *= sc; v1 *= sc; }
                if (OUT_HALF) {
                    *(__half2*)&((__half*)Cv)[(size_t)r * Nc + cn] = __floats2half2_rn(v0, v1);
                } else {
                    *(float2*)&((float*)Cv)[(size_t)r * Nc + cn] = make_float2(v0, v1);
                }
                if (FUSE_AGG) red_add_v2(&agg[ab + cn], v0, v1);
            }
        }
    }
}

// ---------------- fused Wc1 fp16 GEMM + phi + x-scatter (512 threads) ----------------
__global__ __launch_bounds__(512, 2) void gemm_phix_kernel(
    const __half* __restrict__ A,           // m half, E x 256
    const __half* __restrict__ B,           // Wc1T half [256][256]
    const float* __restrict__ bc1,
    const float* __restrict__ Wc2,          // [256,16] fp32
    const float* __restrict__ x, const int* __restrict__ el,
    float* __restrict__ xacc)
{
    extern __shared__ __half hsm[];
    __half* AsBase = hsm;
    __half* BsBase = hsm + HNSTG * HA_SZ;
    uint32_t su = (uint32_t)__cvta_generic_to_shared(hsm);

    int tid = threadIdx.x;
    int rowBase = blockIdx.y * 128, colBase = blockIdx.x * 128;
    int warp = tid >> 5, lane = tid & 31;
    int wm = warp >> 2, wn = warp & 3;
    int gr = lane >> 2, gc = lane & 3;

    float c_[2][4][4];
#pragma unroll
    for (int i = 0; i < 2; i++)
#pragma unroll
        for (int j = 0; j < 4; j++)
#pragma unroll
            for (int q = 0; q < 4; q++) c_[i][j][q] = 0.0f;

    const int nt = 8;   // K=256

    auto load_stage = [&](int s, int t) {
        int k0 = t << 5;
        {
            int arow = tid >> 2, ach = (tid & 3) * 8;
            cp_async16(su + (uint32_t)(s * HA_SZ + arow * HAS + ach) * 2,
                       A + (size_t)(rowBase + arow) * 256 + k0 + ach, true);
        }
        {
            int nrow = tid >> 2, bch = (tid & 3) * 8;
            cp_async16(su + (uint32_t)(HNSTG * HA_SZ + s * HA_SZ + nrow * HAS + bch) * 2,
                       B + (size_t)(colBase + nrow) * 256 + k0 + bch, true);
        }
        cp_commit();
    };

#pragma unroll
    for (int s = 0; s < HNSTG - 1; s++) load_stage(s, s);

    for (int t = 0; t < nt; t++) {
        cp_wait<HNSTG - 2>();
        __syncthreads();
        int cur = t % HNSTG;
        if (t + HNSTG - 1 < nt) load_stage((t + HNSTG - 1) % HNSTG, t + HNSTG - 1);
        else cp_commit();
        const __half* As = AsBase + cur * HA_SZ;
        const __half* Bs = BsBase + cur * HA_SZ;
#pragma unroll
        for (int kk = 0; kk < 32; kk += 16) {
            uint32_t af[2][4], bf[4][2];
#pragma unroll
            for (int i = 0; i < 2; i++) {
                int r0 = wm * 32 + i * 16 + gr;
                af[i][0] = *(const uint32_t*)&As[r0 * HAS + kk + 2 * gc];
                af[i][1] = *(const uint32_t*)&As[(r0 + 8) * HAS + kk + 2 * gc];
                af[i][2] = *(const uint32_t*)&As[r0 * HAS + kk + 8 + 2 * gc];
                af[i][3] = *(const uint32_t*)&As[(r0 + 8) * HAS + kk + 8 + 2 * gc];
            }
#pragma unroll
            for (int j = 0; j < 4; j++) {
                int cn = wn * 32 + j * 8 + gr;
                bf[j][0] = *(const uint32_t*)&Bs[cn * HAS + kk + 2 * gc];
                bf[j][1] = *(const uint32_t*)&Bs[cn * HAS + kk + 8 + 2 * gc];
            }
#pragma unroll
            for (int i = 0; i < 2; i++)
#pragma unroll
                for (int j = 0; j < 4; j++) {
                    asm volatile(
                        "mma.sync.aligned.m16n8k16.row.col.f32.f16.f16.f32 "
                        "{%0,%1,%2,%3}, {%4,%5,%6,%7}, {%8,%9}, {%0,%1,%2,%3};\n"
                        : "+f"(c_[i][j][0]), "+f"(c_[i][j][1]),
                          "+f"(c_[i][j][2]), "+f"(c_[i][j][3])
                        : "r"(af[i][0]), "r"(af[i][1]), "r"(af[i][2]), "r"(af[i][3]),
                          "r"(bf[j][0]), "r"(bf[j][1]));
                }
        }
        __syncthreads();
    }

    // ---- epilogue: phi partial over this CTA's 128 cols ----
    float* sT  = (float*)hsm;             // [128][36]
    float* sW2 = (float*)hsm + 128 * 36;  // [128][17]
    float* sB1 = sW2 + 128 * 17;          // [128]

    if (tid < 128) sB1[tid] = bc1[colBase + tid];
    for (int idx = tid; idx < 128 * 16; idx += 512) {
        int rr = idx >> 4, n = idx & 15;
        sW2[rr * 17 + n] = Wc2[(size_t)(colBase + rr) * 16 + n];
    }

    float p[4];
#pragma unroll
    for (int n = 0; n < 4; n++) p[n] = 0.0f;
    int pr = tid >> 2;            // row 0..127
    int pn0 = (tid & 3) * 4;      // phi col group = channel i2

#pragma unroll 1
    for (int ch = 0; ch < 4; ch++) {
        __syncthreads();
        if (wn == ch) {
#pragma unroll
            for (int j = 0; j < 4; j++) {
                int lcol = j * 8 + gc * 2;
                float bb0 = sB1[ch * 32 + lcol];
                float bb1 = sB1[ch * 32 + lcol + 1];
#pragma unroll
                for (int i = 0; i < 2; i++)
#pragma unroll
                    for (int half = 0; half < 2; half++) {
                        int lr = wm * 32 + i * 16 + half * 8 + gr;
                        float v0 = silu_f(c_[i][j][half * 2 + 0] + bb0);
                        float v1 = silu_f(c_[i][j][half * 2 + 1] + bb1);
                        *(float2*)&sT[lr * 36 + lcol] = make_float2(v0, v1);
                    }
            }
        }
        __syncthreads();
#pragma unroll
        for (int cb = 0; cb < 8; cb++) {
            float4 t4 = *(const float4*)&sT[pr * 36 + cb * 4];
#pragma unroll
            for (int k = 0; k < 4; k++) {
                float tv = (&t4.x)[k];
                int wr = ch * 32 + cb * 4 + k;
#pragma unroll
                for (int n = 0; n < 4; n++)
                    p[n] = fmaf(tv, sW2[wr * 17 + pn0 + n], p[n]);
            }
        }
    }

    // thread (tid&3) == channel i2 holds phi[i2*4 + 0..3] for row pr.
    {
        int i2 = tid & 3;
        int e = rowBase + pr;
        int rw = el[3 * e], cl = el[3 * e + 1];
        float xr0 = x[rw * 12 + i2 * 3 + 0];
        float xr1 = x[rw * 12 + i2 * 3 + 1];
        float xr2 = x[rw * 12 + i2 * 3 + 2];
        float s0 = 0.f, s1 = 0.f, s2 = 0.f;
#pragma unroll
        for (int j2 = 0; j2 < 4; j2++) {
            float ph = p[j2];
            s0 = fmaf(xr0 - x[cl * 12 + j2 * 3 + 0], ph, s0);
            s1 = fmaf(xr1 - x[cl * 12 + j2 * 3 + 1], ph, s1);
            s2 = fmaf(xr2 - x[cl * 12 + j2 * 3 + 2], ph, s2);
        }
        atomicAdd(&xacc[rw * 12 + i2 * 3 + 0], 0.25f * s0);
        atomicAdd(&xacc[rw * 12 + i2 * 3 + 1], 0.25f * s1);
        atomicAdd(&xacc[rw * 12 + i2 * 3 + 2], 0.25f * s2);
    }
}

// ---------------- edge fuse (half out) ----------------
__global__ __launch_bounds__(256) void edge_fuse_kernel(
    const float* __restrict__ PQ,
    const float* __restrict__ x, const int* __restrict__ el,
    const float* __restrict__ cw,
    const float* __restrict__ Wrad, const float* __restrict__ brad,
    const float* __restrict__ W1c, const float* __restrict__ be1,
    __half* __restrict__ m1)
{
    __shared__ __align__(16) float sW1c[16][256];
    __shared__ float sWrad[16][16];
    __shared__ float sbrad[16];
    __shared__ __align__(16) float sbe1[256];
    __shared__ float srad[8][16];
    __shared__ float srf[8][16];
    int tid = threadIdx.x;
    for (int i = tid; i < 16 * 256; i += 256) sW1c[i >> 8][i & 255] = W1c[i];
    sbe1[tid] = be1[tid];
    { int r = tid >> 4, c = tid & 15; sWrad[r][c] = Wrad[tid]; }
    if (tid < 16) sbrad[tid] = brad[tid];
    __syncthreads();

    int warp = tid >> 5, lane = tid & 31;
#pragma unroll 1
    for (int ei = 0; ei < 8; ei++) {
        int e = blockIdx.x * 64 + warp * 8 + ei;
        int row = el[3*e], col = el[3*e+1];

        if (lane < 16) {
            int i = lane >> 2, j = lane & 3;
            float dx = x[row*12 + i*3 + 0] - x[col*12 + j*3 + 0];
            float dy = x[row*12 + i*3 + 1] - x[col*12 + j*3 + 1];
            float dz = x[row*12 + i*3 + 2] - x[col*12 + j*3 + 2];
            srad[warp][lane] = (dx*dx + dy*dy + dz*dz) * cw[row*4 + i] * cw[col*4 + j];
        }
        __syncwarp();
        if (lane < 16) {
            float acc = sbrad[lane];
#pragma unroll
            for (int k = 0; k < 16; k++) acc = fmaf(srad[warp][k], sWrad[k][lane], acc);
            srf[warp][lane] = silu_f(acc);
        }
        __syncwarp();

        const float4* Pr = (const float4*)(PQ + (size_t)row * 512);
        const float4* Qc = (const float4*)(PQ + (size_t)col * 512 + 256);
        __half* Om = m1 + (size_t)e * 256;
#pragma unroll
        for (int half = 0; half < 2; half++) {
            int o4 = lane * 2 + half;
            float4 pv = Pr[o4], qv = Qc[o4];
            float4 b = ((const float4*)sbe1)[o4];
            float4 s = make_float4(pv.x + qv.x + b.x, pv.y + qv.y + b.y,
                                   pv.z + qv.z + b.z, pv.w + qv.w + b.w);
#pragma unroll
            for (int k = 0; k < 16; k++) {
                float rk = srf[warp][k];
                float4 w = ((const float4*)&sW1c[k][0])[o4];
                s.x = fmaf(rk, w.x, s.x); s.y = fmaf(rk, w.y, s.y);
                s.z = fmaf(rk, w.z, s.z); s.w = fmaf(rk, w.w, s.w);
            }
            *(__half2*)&Om[o4 * 4]     = __floats2half2_rn(silu_f(s.x), silu_f(s.y));
            *(__half2*)&Om[o4 * 4 + 2] = __floats2half2_rn(silu_f(s.z), silu_f(s.w));
        }
        __syncwarp();
    }
}

// ---------------- layernorm ----------------
__global__ void ln_kernel(const float* __restrict__ h2, const float* __restrict__ g,
                          const float* __restrict__ b, float* __restrict__ out) {
    int n = blockIdx.x;
    int t = threadIdx.x;
    float v = h2[(size_t)n * 256 + t];
    float a = v, sq = v * v;
#pragma unroll
    for (int o = 16; o > 0; o >>= 1) {
        a  += __shfl_down_sync(0xFFFFFFFFu, a, o);
        sq += __shfl_down_sync(0xFFFFFFFFu, sq, o);
    }
    __shared__ float s1[8], s2[8];
    if ((t & 31) == 0) { s1[t >> 5] = a; s2[t >> 5] = sq; }
    __syncthreads();
    __shared__ float mu, rs;
    if (t == 0) {
        float A = 0.f, B = 0.f;
#pragma unroll
        for (int i = 0; i < 8; i++) { A += s1[i]; B += s2[i]; }
        float m = A * (1.0f / 256.0f);
        mu = m;
        rs = rsqrtf(B * (1.0f / 256.0f) - m * m + EPSV);
    }
    __syncthreads();
    out[(size_t)n * 256 + t] = (v - mu) * rs * g[t] + b[t];
}

__global__ void x_final_kernel(const float* __restrict__ xin, const float* __restrict__ xacc,
                               const float* __restrict__ cnt, float* __restrict__ xout) {
    int i = blockIdx.x * blockDim.x + threadIdx.x;
    if (i >= NN * 12) return;
    int n = i / 12;
    xout[i] = xin[i] + xacc[i] / fmaxf(cnt[n], 1.0f);
}

// ---------------- host ----------------
extern "C" void kernel_launch(void* const* d_in, const int* in_sizes, int n_in,
                              void* d_out, int out_size) {
    const float* input  = nullptr;
    const float* coords = nullptr;
    const float* attr   = nullptr;
    const float* cw     = nullptr;
    const float* ew     = nullptr;
    const int*   el     = nullptr;
    for (int i = 0; i < 6; i++) {
        switch (in_sizes[i]) {
            case NN * HH:     input  = (const float*)d_in[i]; break;
            case NN * 4 * 3:  coords = (const float*)d_in[i]; break;
            case NN * 4 * 16: attr   = (const float*)d_in[i]; break;
            case NN * 4:      cw     = (const float*)d_in[i]; break;
            case EE:          ew     = (const float*)d_in[i]; break;
            case EE * 3:      el     = (const int*)  d_in[i]; break;
        }
    }
    const float* W_rad = (const float*)d_in[6];
    const float* b_rad = (const float*)d_in[7];
    const float* W_e1  = (const float*)d_in[8];
    const float* b_e1  = (const float*)d_in[9];
    const float* W_e2  = (const float*)d_in[10];
    const float* b_e2  = (const float*)d_in[11];
    const float* W_c1  = (const float*)d_in[12];
    const float* b_c1  = (const float*)d_in[13];
    const float* W_c2  = (const float*)d_in[14];
    const float* W_n1  = (const float*)d_in[15];
    const float* b_n1  = (const float*)d_in[16];
    const float* W_n2  = (const float*)d_in[17];
    const float* b_n2  = (const float*)d_in[18];
    const float* ln_g  = (const float*)d_in[19];
    const float* ln_b  = (const float*)d_in[20];

    float* buf = nullptr;
    cudaGetSymbolAddress((void**)&buf, g_buf);

    float*  g_ca   = buf + OFF_CA;
    float*  g_pq   = buf + OFF_PQ;
    __half* g_hcah = (__half*)(buf + OFF_HCAH);
    __half* g_m1h  = (__half*)(buf + OFF_M1H);
    __half* g_mh   = (__half*)(buf + OFF_MH);
    float*  g_agg  = buf + OFF_AGG;
    __half* g_ninh = (__half*)(buf + OFF_NINH);
    __half* g_h1h  = (__half*)(buf + OFF_H1H);
    float*  g_hbuf = buf + OFF_HBUF;
    float*  g_xbuf = buf + OFF_XBUF;
    float*  g_xacc = buf + OFF_XACC;
    float*  g_cnt  = buf + OFF_CNT;
    __half* g_wpqt = (__half*)(buf + OFF_WPQT);
    __half* g_we2t = (__half*)(buf + OFF_WE2T);
    __half* g_wc1t = (__half*)(buf + OFF_WC1T);
    __half* g_wn2t = (__half*)(buf + OFF_WN2T);
    __half* g_wn1t = (__half*)(buf + OFF_WN1T);

    cudaFuncSetAttribute((const void*)hgemm_kernel<0, false, false>,
                         cudaFuncAttributeMaxDynamicSharedMemorySize, HSMEM_BYTES);
    cudaFuncSetAttribute((const void*)hgemm_kernel<2, true, true>,
                         cudaFuncAttributeMaxDynamicSharedMemorySize, HSMEM_BYTES);
    cudaFuncSetAttribute((const void*)hgemm_kernel<1, false, true>,
                         cudaFuncAttributeMaxDynamicSharedMemorySize, HSMEM_BYTES);
    cudaFuncSetAttribute((const void*)gemm_phix_kernel,
                         cudaFuncAttributeMaxDynamicSharedMemorySize, HSMEM_BYTES);

    // launch 0
    ca_kernel<<<(NN + 255) / 256, 256>>>(attr, cw, g_ca);

    for (int l = 0; l < LL; l++) {
        const float* h_in = (l == 0) ? input  : g_hbuf;
        const float* x_in = (l == 0) ? coords : g_xbuf;
        float* h_out = (l == LL - 1) ? (float*)d_out : g_hbuf;
        float* x_out = (l == LL - 1) ? ((float*)d_out + (size_t)NN * HH) : g_xbuf;

        const float* Wr  = W_rad + (size_t)l * 256;
        const float* br  = b_rad + (size_t)l * 16;
        const float* We1 = W_e1 + (size_t)l * 560 * 256;
        const float* be1 = b_e1 + (size_t)l * 256;
        const float* We2 = W_e2 + (size_t)l * 256 * 256;
        const float* be2 = b_e2 + (size_t)l * 256;
        const float* Wc1 = W_c1 + (size_t)l * 256 * 256;
        const float* bc1 = b_c1 + (size_t)l * 256;
        const float* Wc2 = W_c2 + (size_t)l * 256 * 16;
        const float* Wn1 = W_n1 + (size_t)l * 2048 * 256;
        const float* bn1 = b_n1 + (size_t)l * 256;
        const float* Wn2 = W_n2 + (size_t)l * 256 * 256;
        const float* bn2 = b_n2 + (size_t)l * 256;
        const float* lg  = ln_g + (size_t)l * 256;
        const float* lb  = ln_b + (size_t)l * 256;

        // 1: weight prep
        wprep_all<<<1280, 256>>>(We2, Wc1, Wn2, Wn1, We1,
                                 g_we2t, g_wc1t, g_wn2t, g_wn1t, g_wpqt);
        // 2: hca pack + zero agg/xacc/cnt
        hca_pack_zero<<<(HPZ_TOT + 255) / 256, 256>>>(
            h_in, g_ca, (__half2*)g_hcah, (float4*)g_agg, (float4*)g_xacc, (float4*)g_cnt);
        // 3: PQ = hca @ WpqT^T  (fp32 out)
        hgemm_kernel<0, false, false><<<dim3(4, (NN + 127) / 128), 512, HSMEM_BYTES>>>(
            g_hcah, 288, g_wpqt, nullptr, nullptr, g_pq, nullptr, nullptr, NN, 512, 288);
        // 4: m1 = half(silu(P[row]+Q[col]+rad_feat@W1c+be1))
        edge_fuse_kernel<<<EE / 64, 256>>>(g_pq, x_in, el, cw,
                                           Wr, br, We1 + (size_t)512 * 256, be1, g_m1h);
        // 5 (ncu target): m = half(silu(m1@We2+be2)*ew) + fp32 agg scatter
        hgemm_kernel<2, true, true><<<dim3(2, EE / 128), 512, HSMEM_BYTES>>>(
            g_m1h, 256, g_we2t, be2, ew, g_mh, el, g_agg, EE, 256, 256);
        // 6: cnt
        cnt_kernel<<<(EE + 255) / 256, 256>>>(el, g_cnt);
        // fused Wc1 GEMM + phi + x scatter
        gemm_phix_kernel<<<dim3(2, EE / 128), 512, HSMEM_BYTES>>>(
            g_mh, g_wc1t, bc1, Wc2, x_in, el, g_xacc);
        // nin pack
        nin_pack<<<(NN * 1024 + 255) / 256, 256>>>(g_agg, h_in, (__half2*)g_ninh);
        // h1 = half(silu(nin@Wn1+bn1))
        hgemm_kernel<1, false, true><<<dim3(2, (NN + 127) / 128), 512, HSMEM_BYTES>>>(
            g_ninh, 2048, g_wn1t, bn1, nullptr, g_h1h, nullptr, nullptr, NN, 256, 2048);
        // h2 = h1@Wn2+bn2 (fp32 out)
        hgemm_kernel<0, false, false><<<dim3(2, (NN + 127) / 128), 512, HSMEM_BYTES>>>(
            g_h1h, 256, g_wn2t, bn2, nullptr, g_pq, nullptr, nullptr, NN, 256, 256);

        ln_kernel<<<NN, 256>>>(g_pq, lg, lb, h_out);
        x_final_kernel<<<(NN * 12 + 255) / 256, 256>>>(x_in, g_xacc, g_cnt, x_out);
    }
}

// round 12
// speedup vs baseline: 4.5322x; 1.0455x over previous
#include <cuda_runtime.h>
#include <cuda_fp16.h>
#include <cstddef>
#include <cstdint>

#define NN 10000
#define EE 160000
#define RR 7
#define HH 256
#define LL 2
#define EPSV 1e-5f

// ---------------- scratch (float units) ----------------
#define OFF_CA    ((size_t)0)                          // N*16
#define OFF_PQ    (OFF_CA   + (size_t)160000)          // N*512
#define OFF_HCAH  (OFF_PQ   + (size_t)5120000)         // N*288 half
#define OFF_M1H   (OFF_HCAH + (size_t)1440000)         // E*256 half
#define OFF_MH    (OFF_M1H  + (size_t)20480000)        // E*256 half
#define OFF_AGG   (OFF_MH   + (size_t)20480000)        // N*1792 f32
#define OFF_NINH  (OFF_AGG  + (size_t)17920000)        // N*2048 half
#define OFF_H1H   (OFF_NINH + (size_t)10240000)        // N*256 half
#define OFF_HBUF  (OFF_H1H  + (size_t)1280000)         // N*256 f32
#define OFF_XBUF  (OFF_HBUF + (size_t)2560000)         // N*12
#define OFF_XACC  (OFF_XBUF + (size_t)120000)          // N*12
#define OFF_CNT   (OFF_XACC + (size_t)120000)          // N
#define OFF_WPQT  (OFF_CNT  + (size_t)10000)           // 512*288 half
#define OFF_WE2T  (OFF_WPQT + (size_t)73728)           // 256*256 half
#define OFF_WC1T  (OFF_WE2T + (size_t)32768)
#define OFF_WN2T  (OFF_WC1T + (size_t)32768)
#define OFF_WN1T  (OFF_WN2T + (size_t)32768)           // 256*2048 half
#define TOTAL_F   (OFF_WN1T + (size_t)262144)

__device__ float g_buf[TOTAL_F];

__device__ __forceinline__ float silu_f(float v) { return v / (1.0f + __expf(-v)); }

__device__ __forceinline__ void cp_async16(uint32_t dst, const void* src, bool p) {
    asm volatile("cp.async.cg.shared.global [%0], [%1], 16, %2;\n"
                 :: "r"(dst), "l"(src), "r"(p ? 16 : 0));
}
__device__ __forceinline__ void cp_commit() {
    asm volatile("cp.async.commit_group;\n");
}
template <int Np> __device__ __forceinline__ void cp_wait() {
    asm volatile("cp.async.wait_group %0;\n" :: "n"(Np));
}
__device__ __forceinline__ void red_add_v2(float* addr, float a, float b) {
    asm volatile("red.global.add.v2.f32 [%0], {%1, %2};"
                 :: "l"(addr), "f"(a), "f"(b) : "memory");
}
#define LDSM_X4(r0, r1, r2, r3, addr) \
    asm volatile("ldmatrix.sync.aligned.m8n8.x4.shared.b16 {%0,%1,%2,%3}, [%4];" \
                 : "=r"(r0), "=r"(r1), "=r"(r2), "=r"(r3) : "r"(addr))

// ---------------- small kernels ----------------
__global__ void zero4_kernel(float4* __restrict__ p, size_t n4) {
    size_t i = (size_t)blockIdx.x * blockDim.x + threadIdx.x;
    if (i < n4) p[i] = make_float4(0.f, 0.f, 0.f, 0.f);
}

__global__ void ca_kernel(const float* __restrict__ attr, const float* __restrict__ cw,
                          float* __restrict__ ca) {
    int n = blockIdx.x * blockDim.x + threadIdx.x;
    if (n >= NN) return;
    float w0 = cw[n*4+0], w1 = cw[n*4+1], w2 = cw[n*4+2], w3 = cw[n*4+3];
    float inv = 1.0f / (w0 + w1 + w2 + w3);
    const float* a = attr + (size_t)n * 64;
#pragma unroll
    for (int f = 0; f < 16; f++)
        ca[n*16+f] = (a[f]*w0 + a[16+f]*w1 + a[32+f]*w2 + a[48+f]*w3) * inv;
}

__global__ void cnt_kernel(const int* __restrict__ el, float* __restrict__ cnt) {
    int e = blockIdx.x * blockDim.x + threadIdx.x;
    if (e >= EE) return;
    atomicAdd(&cnt[el[3*e]], 1.0f);
}

// 32x32 tile transpose: W [K][256] f32 -> WT [256][K] half
__device__ __forceinline__ void transpose_tile(const float* __restrict__ W,
                                               __half* __restrict__ WT,
                                               int kb, int nb, int K) {
    __shared__ float t[32][33];
    int tx = threadIdx.x & 31, ty = threadIdx.x >> 5;
#pragma unroll
    for (int d = 0; d < 32; d += 8)
        t[ty + d][tx] = W[(size_t)(kb + ty + d) * 256 + nb + tx];
    __syncthreads();
#pragma unroll
    for (int d = 0; d < 32; d += 8)
        WT[(size_t)(nb + ty + d) * K + kb + tx] = __float2half_rn(t[tx][ty + d]);
}

// merged weight prep: 1280 blocks
__global__ void wprep_all(const float* __restrict__ We2, const float* __restrict__ Wc1,
                          const float* __restrict__ Wn2, const float* __restrict__ Wn1,
                          const float* __restrict__ We1,
                          __half* __restrict__ We2T, __half* __restrict__ Wc1T,
                          __half* __restrict__ Wn2T, __half* __restrict__ Wn1T,
                          __half* __restrict__ WpqT) {
    int bid = blockIdx.x;
    if (bid < 192) {
        int w = bid >> 6;
        const float* W = (w == 0) ? We2 : (w == 1) ? Wc1 : Wn2;
        __half* O = (w == 0) ? We2T : (w == 1) ? Wc1T : Wn2T;
        int t = bid & 63;
        transpose_tile(W, O, (t >> 3) * 32, (t & 7) * 32, 256);
    } else if (bid < 704) {
        int t = bid - 192;
        transpose_tile(Wn1, Wn1T, (t >> 3) * 32, (t & 7) * 32, 2048);
    } else {
        int i = (bid - 704) * 256 + threadIdx.x;   // over 512*288
        int n = i / 288, k = i % 288;
        float v = 0.f;
        if (k < 272) {
            int j = (n < 256) ? n : n - 256;
            int kk = (n < 256) ? ((k < 256) ? k : 528 + (k - 256))
                               : ((k < 256) ? 256 + k : 544 + (k - 256));
            v = We1[(size_t)kk * 256 + j];
        }
        WpqT[i] = __float2half_rn(v);
    }
}

// hca pack (half) + zero agg/xacc
#define HPZ_HCA   1440000u
#define HPZ_AGG   (HPZ_HCA + 4480000u)
#define HPZ_TOT   (HPZ_AGG + 30000u)
__global__ void hca_pack_zero(const float* __restrict__ h, const float* __restrict__ ca,
                              __half2* __restrict__ hca2,
                              float4* __restrict__ agg4, float4* __restrict__ xacc4) {
    unsigned i = blockIdx.x * 256 + threadIdx.x;
    const float4 z4 = make_float4(0.f, 0.f, 0.f, 0.f);
    if (i < HPZ_HCA) {
        int n = i / 144, c2 = (int)(i % 144) * 2;
        float v0 = 0.f, v1 = 0.f;
        if (c2 < 256)      { v0 = h[n*256 + c2];      v1 = h[n*256 + c2 + 1]; }
        else if (c2 < 272) { v0 = ca[n*16 + c2 - 256]; v1 = ca[n*16 + c2 - 255]; }
        hca2[i] = __floats2half2_rn(v0, v1);
    } else if (i < HPZ_AGG)  agg4[i - HPZ_HCA] = z4;
    else if (i < HPZ_TOT)    xacc4[i - HPZ_AGG] = z4;
}

// nin pack: [agg(1792) | h(256)] -> half
__global__ void nin_pack(const float* __restrict__ agg, const float* __restrict__ h,
                         __half2* __restrict__ nin2) {
    unsigned i = blockIdx.x * 256 + threadIdx.x;
    if (i >= (unsigned)NN * 1024) return;
    int n = i >> 10, c2 = (int)(i & 1023) * 2;
    float v0, v1;
    if (c2 < 1792) { v0 = agg[(size_t)n*1792 + c2]; v1 = agg[(size_t)n*1792 + c2 + 1]; }
    else           { v0 = h[(size_t)n*256 + c2 - 1792]; v1 = h[(size_t)n*256 + c2 - 1791]; }
    nin2[i] = __floats2half2_rn(v0, v1);
}

// ---------------- fp16 GEMM (m16n8k16 + ldmatrix), 512 threads, warp tile 32x32 ----------------
#define HAS 56
#define HA_SZ (128 * HAS)
#define HNSTG 3
#define HSMEM_BYTES (HNSTG * 2 * HA_SZ * 2)

template <int ACT, bool FUSE_AGG, bool OUT_HALF>
__global__ __launch_bounds__(512, 2) void hgemm_kernel(
    const __half* __restrict__ A, int lda,
    const __half* __restrict__ B,
    const float* __restrict__ bias, const float* __restrict__ rowscale,
    void* __restrict__ Cv,
    const int* __restrict__ el, float* __restrict__ agg,
    int M, int Nc, int K)
{
    extern __shared__ __half hsm[];
    uint32_t su = (uint32_t)__cvta_generic_to_shared(hsm);

    int tid = threadIdx.x;
    int rowBase = blockIdx.y * 128, colBase = blockIdx.x * 128;
    int warp = tid >> 5, lane = tid & 31;
    int wm = warp >> 2, wn = warp & 3;
    int gr = lane >> 2, gc = lane & 3;

    // ldmatrix per-lane address offsets (halves)
    uint32_t aoff = (uint32_t)((wm * 32 + ((lane >> 3) & 1) * 8 + (lane & 7)) * HAS
                               + (lane >> 4) * 8);
    uint32_t boff = (uint32_t)((wn * 32 + (lane >> 4) * 8 + (lane & 7)) * HAS
                               + ((lane >> 3) & 1) * 8);
    uint32_t aBase = su + aoff * 2;
    uint32_t bBase = su + (uint32_t)(HNSTG * HA_SZ) * 2 + boff * 2;

    float c_[2][4][4];
#pragma unroll
    for (int i = 0; i < 2; i++)
#pragma unroll
        for (int j = 0; j < 4; j++)
#pragma unroll
            for (int q = 0; q < 4; q++) c_[i][j][q] = 0.0f;

    int nt = K >> 5;

    auto load_stage = [&](int s, int t) {
        int k0 = t << 5;
        {
            int arow = tid >> 2, ach = (tid & 3) * 8;
            int r = rowBase + arow;
            cp_async16(su + (uint32_t)(s * HA_SZ + arow * HAS + ach) * 2,
                       A + (size_t)r * lda + k0 + ach, r < M);
        }
        {
            int nrow = tid >> 2, bch = (tid & 3) * 8;
            cp_async16(su + (uint32_t)(HNSTG * HA_SZ + s * HA_SZ + nrow * HAS + bch) * 2,
                       B + (size_t)(colBase + nrow) * K + k0 + bch, true);
        }
        cp_commit();
    };

#pragma unroll
    for (int s = 0; s < HNSTG - 1; s++) {
        if (s < nt) load_stage(s, s); else cp_commit();
    }

    for (int t = 0; t < nt; t++) {
        cp_wait<HNSTG - 2>();
        __syncthreads();
        int cur = t % HNSTG;
        if (t + HNSTG - 1 < nt) load_stage((t + HNSTG - 1) % HNSTG, t + HNSTG - 1);
        else cp_commit();
        uint32_t aS = aBase + (uint32_t)(cur * HA_SZ) * 2;
        uint32_t bS = bBase + (uint32_t)(cur * HA_SZ) * 2;
#pragma unroll
        for (int kk = 0; kk < 32; kk += 16) {
            uint32_t af[2][4], bf[4][2];
            LDSM_X4(af[0][0], af[0][1], af[0][2], af[0][3], aS + kk * 2);
            LDSM_X4(af[1][0], af[1][1], af[1][2], af[1][3], aS + (16 * HAS + kk) * 2);
            LDSM_X4(bf[0][0], bf[0][1], bf[1][0], bf[1][1], bS + kk * 2);
            LDSM_X4(bf[2][0], bf[2][1], bf[3][0], bf[3][1], bS + (16 * HAS + kk) * 2);
#pragma unroll
            for (int i = 0; i < 2; i++)
#pragma unroll
                for (int j = 0; j < 4; j++) {
                    asm volatile(
                        "mma.sync.aligned.m16n8k16.row.col.f32.f16.f16.f32 "
                        "{%0,%1,%2,%3}, {%4,%5,%6,%7}, {%8,%9}, {%0,%1,%2,%3};\n"
                        : "+f"(c_[i][j][0]), "+f"(c_[i][j][1]),
                          "+f"(c_[i][j][2]), "+f"(c_[i][j][3])
                        : "r"(af[i][0]), "r"(af[i][1]), "r"(af[i][2]), "r"(af[i][3]),
                          "r"(bf[j][0]), "r"(bf[j][1]));
                }
        }
        __syncthreads();
    }

    // epilogue
#pragma unroll
    for (int i = 0; i < 2; i++) {
        int rr0 = rowBase + wm * 32 + i * 16 + gr;
#pragma unroll
        for (int half = 0; half < 2; half++) {
            int r = rr0 + half * 8;
            if (r >= M) continue;
            float sc = (ACT == 2) ? rowscale[r] : 1.0f;
            size_t ab = 0;
            if (FUSE_AGG) {
                int cc = el[3 * r + 1], rl = el[3 * r + 2];
                ab = ((size_t)cc * RR + rl) * 256;
            }
#pragma unroll
            for (int j = 0; j < 4; j++) {
                int cn = colBase + wn * 32 + j * 8 + gc * 2;
                float b0 = bias ? bias[cn] : 0.f;
                float b1 = bias ? bias[cn + 1] : 0.f;
                float v0 = c_[i][j][half * 2 + 0] + b0;
                float v1 = c_[i][j][half * 2 + 1] + b1;
                if (ACT >= 1) { v0 = silu_f(v0); v1 = silu_f(v1); }
                if (ACT == 2) { v0 *= sc; v1 *= sc; }
                if (OUT_HALF) {
                    *(__half2*)&((__half*)Cv)[(size_t)r * Nc + cn] = __floats2half2_rn(v0, v1);
                } else {
                    *(float2*)&((float*)Cv)[(size_t)r * Nc + cn] = make_float2(v0, v1);
                }
                if (FUSE_AGG) red_add_v2(&agg[ab + cn], v0, v1);
            }
        }
    }
}

// ---------------- fused Wc1 fp16 GEMM + phi + x-scatter (512 threads, ldmatrix) ----------------
__global__ __launch_bounds__(512, 2) void gemm_phix_kernel(
    const __half* __restrict__ A,           // m half, E x 256
    const __half* __restrict__ B,           // Wc1T half [256][256]
    const float* __restrict__ bc1,
    const float* __restrict__ Wc2,          // [256,16] fp32
    const float* __restrict__ x, const int* __restrict__ el,
    float* __restrict__ xacc)
{
    extern __shared__ __half hsm[];
    uint32_t su = (uint32_t)__cvta_generic_to_shared(hsm);

    int tid = threadIdx.x;
    int rowBase = blockIdx.y * 128, colBase = blockIdx.x * 128;
    int warp = tid >> 5, lane = tid & 31;
    int wm = warp >> 2, wn = warp & 3;
    int gr = lane >> 2, gc = lane & 3;

    uint32_t aoff = (uint32_t)((wm * 32 + ((lane >> 3) & 1) * 8 + (lane & 7)) * HAS
                               + (lane >> 4) * 8);
    uint32_t boff = (uint32_t)((wn * 32 + (lane >> 4) * 8 + (lane & 7)) * HAS
                               + ((lane >> 3) & 1) * 8);
    uint32_t aBase = su + aoff * 2;
    uint32_t bBase = su + (uint32_t)(HNSTG * HA_SZ) * 2 + boff * 2;

    float c_[2][4][4];
#pragma unroll
    for (int i = 0; i < 2; i++)
#pragma unroll
        for (int j = 0; j < 4; j++)
#pragma unroll
            for (int q = 0; q < 4; q++) c_[i][j][q] = 0.0f;

    const int nt = 8;   // K=256

    auto load_stage = [&](int s, int t) {
        int k0 = t << 5;
        {
            int arow = tid >> 2, ach = (tid & 3) * 8;
            cp_async16(su + (uint32_t)(s * HA_SZ + arow * HAS + ach) * 2,
                       A + (size_t)(rowBase + arow) * 256 + k0 + ach, true);
        }
        {
            int nrow = tid >> 2, bch = (tid & 3) * 8;
            cp_async16(su + (uint32_t)(HNSTG * HA_SZ + s * HA_SZ + nrow * HAS + bch) * 2,
                       B + (size_t)(colBase + nrow) * 256 + k0 + bch, true);
        }
        cp_commit();
    };

#pragma unroll
    for (int s = 0; s < HNSTG - 1; s++) load_stage(s, s);

    for (int t = 0; t < nt; t++) {
        cp_wait<HNSTG - 2>();
        __syncthreads();
        int cur = t % HNSTG;
        if (t + HNSTG - 1 < nt) load_stage((t + HNSTG - 1) % HNSTG, t + HNSTG - 1);
        else cp_commit();
        uint32_t aS = aBase + (uint32_t)(cur * HA_SZ) * 2;
        uint32_t bS = bBase + (uint32_t)(cur * HA_SZ) * 2;
#pragma unroll
        for (int kk = 0; kk < 32; kk += 16) {
            uint32_t af[2][4], bf[4][2];
            LDSM_X4(af[0][0], af[0][1], af[0][2], af[0][3], aS + kk * 2);
            LDSM_X4(af[1][0], af[1][1], af[1][2], af[1][3], aS + (16 * HAS + kk) * 2);
            LDSM_X4(bf[0][0], bf[0][1], bf[1][0], bf[1][1], bS + kk * 2);
            LDSM_X4(bf[2][0], bf[2][1], bf[3][0], bf[3][1], bS + (16 * HAS + kk) * 2);
#pragma unroll
            for (int i = 0; i < 2; i++)
#pragma unroll
                for (int j = 0; j < 4; j++) {
                    asm volatile(
                        "mma.sync.aligned.m16n8k16.row.col.f32.f16.f16.f32 "
                        "{%0,%1,%2,%3}, {%4,%5,%6,%7}, {%8,%9}, {%0,%1,%2,%3};\n"
                        : "+f"(c_[i][j][0]), "+f"(c_[i][j][1]),
                          "+f"(c_[i][j][2]), "+f"(c_[i][j][3])
                        : "r"(af[i][0]), "r"(af[i][1]), "r"(af[i][2]), "r"(af[i][3]),
                          "r"(bf[j][0]), "r"(bf[j][1]));
                }
        }
        __syncthreads();
    }

    // ---- epilogue: phi partial over this CTA's 128 cols ----
    float* sT  = (float*)hsm;             // [128][36]
    float* sW2 = (float*)hsm + 128 * 36;  // [128][17]
    float* sB1 = sW2 + 128 * 17;          // [128]

    if (tid < 128) sB1[tid] = bc1[colBase + tid];
    for (int idx = tid; idx < 128 * 16; idx += 512) {
        int rr = idx >> 4, n = idx & 15;
        sW2[rr * 17 + n] = Wc2[(size_t)(colBase + rr) * 16 + n];
    }

    float p[4];
#pragma unroll
    for (int n = 0; n < 4; n++) p[n] = 0.0f;
    int pr = tid >> 2;
    int pn0 = (tid & 3) * 4;

#pragma unroll 1
    for (int ch = 0; ch < 4; ch++) {
        __syncthreads();
        if (wn == ch) {
#pragma unroll
            for (int j = 0; j < 4; j++) {
                int lcol = j * 8 + gc * 2;
                float bb0 = sB1[ch * 32 + lcol];
                float bb1 = sB1[ch * 32 + lcol + 1];
#pragma unroll
                for (int i = 0; i < 2; i++)
#pragma unroll
                    for (int half = 0; half < 2; half++) {
                        int lr = wm * 32 + i * 16 + half * 8 + gr;
                        float v0 = silu_f(c_[i][j][half * 2 + 0] + bb0);
                        float v1 = silu_f(c_[i][j][half * 2 + 1] + bb1);
                        *(float2*)&sT[lr * 36 + lcol] = make_float2(v0, v1);
                    }
            }
        }
        __syncthreads();
#pragma unroll
        for (int cb = 0; cb < 8; cb++) {
            float4 t4 = *(const float4*)&sT[pr * 36 + cb * 4];
#pragma unroll
            for (int k = 0; k < 4; k++) {
                float tv = (&t4.x)[k];
                int wr = ch * 32 + cb * 4 + k;
#pragma unroll
                for (int n = 0; n < 4; n++)
                    p[n] = fmaf(tv, sW2[wr * 17 + pn0 + n], p[n]);
            }
        }
    }

    // thread (tid&3) == channel i2 holds phi[i2*4 + 0..3] for row pr.
    {
        int i2 = tid & 3;
        int e = rowBase + pr;
        int rw = el[3 * e], cl = el[3 * e + 1];
        float xr0 = x[rw * 12 + i2 * 3 + 0];
        float xr1 = x[rw * 12 + i2 * 3 + 1];
        float xr2 = x[rw * 12 + i2 * 3 + 2];
        float s0 = 0.f, s1 = 0.f, s2 = 0.f;
#pragma unroll
        for (int j2 = 0; j2 < 4; j2++) {
            float ph = p[j2];
            s0 = fmaf(xr0 - x[cl * 12 + j2 * 3 + 0], ph, s0);
            s1 = fmaf(xr1 - x[cl * 12 + j2 * 3 + 1], ph, s1);
            s2 = fmaf(xr2 - x[cl * 12 + j2 * 3 + 2], ph, s2);
        }
        atomicAdd(&xacc[rw * 12 + i2 * 3 + 0], 0.25f * s0);
        atomicAdd(&xacc[rw * 12 + i2 * 3 + 1], 0.25f * s1);
        atomicAdd(&xacc[rw * 12 + i2 * 3 + 2], 0.25f * s2);
    }
}

// ---------------- edge fuse (half out) ----------------
__global__ __launch_bounds__(256) void edge_fuse_kernel(
    const float* __restrict__ PQ,
    const float* __restrict__ x, const int* __restrict__ el,
    const float* __restrict__ cw,
    const float* __restrict__ Wrad, const float* __restrict__ brad,
    const float* __restrict__ W1c, const float* __restrict__ be1,
    __half* __restrict__ m1)
{
    __shared__ __align__(16) float sW1c[16][256];
    __shared__ float sWrad[16][16];
    __shared__ float sbrad[16];
    __shared__ __align__(16) float sbe1[256];
    __shared__ float srad[8][16];
    __shared__ float srf[8][16];
    int tid = threadIdx.x;
    for (int i = tid; i < 16 * 256; i += 256) sW1c[i >> 8][i & 255] = W1c[i];
    sbe1[tid] = be1[tid];
    { int r = tid >> 4, c = tid & 15; sWrad[r][c] = Wrad[tid]; }
    if (tid < 16) sbrad[tid] = brad[tid];
    __syncthreads();

    int warp = tid >> 5, lane = tid & 31;
#pragma unroll 1
    for (int ei = 0; ei < 8; ei++) {
        int e = blockIdx.x * 64 + warp * 8 + ei;
        int row = el[3*e], col = el[3*e+1];

        if (lane < 16) {
            int i = lane >> 2, j = lane & 3;
            float dx = x[row*12 + i*3 + 0] - x[col*12 + j*3 + 0];
            float dy = x[row*12 + i*3 + 1] - x[col*12 + j*3 + 1];
            float dz = x[row*12 + i*3 + 2] - x[col*12 + j*3 + 2];
            srad[warp][lane] = (dx*dx + dy*dy + dz*dz) * cw[row*4 + i] * cw[col*4 + j];
        }
        __syncwarp();
        if (lane < 16) {
            float acc = sbrad[lane];
#pragma unroll
            for (int k = 0; k < 16; k++) acc = fmaf(srad[warp][k], sWrad[k][lane], acc);
            srf[warp][lane] = silu_f(acc);
        }
        __syncwarp();

        const float4* Pr = (const float4*)(PQ + (size_t)row * 512);
        const float4* Qc = (const float4*)(PQ + (size_t)col * 512 + 256);
        __half* Om = m1 + (size_t)e * 256;
#pragma unroll
        for (int half = 0; half < 2; half++) {
            int o4 = lane * 2 + half;
            float4 pv = Pr[o4], qv = Qc[o4];
            float4 b = ((const float4*)sbe1)[o4];
            float4 s = make_float4(pv.x + qv.x + b.x, pv.y + qv.y + b.y,
                                   pv.z + qv.z + b.z, pv.w + qv.w + b.w);
#pragma unroll
            for (int k = 0; k < 16; k++) {
                float rk = srf[warp][k];
                float4 w = ((const float4*)&sW1c[k][0])[o4];
                s.x = fmaf(rk, w.x, s.x); s.y = fmaf(rk, w.y, s.y);
                s.z = fmaf(rk, w.z, s.z); s.w = fmaf(rk, w.w, s.w);
            }
            *(__half2*)&Om[o4 * 4]     = __floats2half2_rn(silu_f(s.x), silu_f(s.y));
            *(__half2*)&Om[o4 * 4 + 2] = __floats2half2_rn(silu_f(s.z), silu_f(s.w));
        }
        __syncwarp();
    }
}

// ---------------- layernorm ----------------
__global__ void ln_kernel(const float* __restrict__ h2, const float* __restrict__ g,
                          const float* __restrict__ b, float* __restrict__ out) {
    int n = blockIdx.x;
    int t = threadIdx.x;
    float v = h2[(size_t)n * 256 + t];
    float a = v, sq = v * v;
#pragma unroll
    for (int o = 16; o > 0; o >>= 1) {
        a  += __shfl_down_sync(0xFFFFFFFFu, a, o);
        sq += __shfl_down_sync(0xFFFFFFFFu, sq, o);
    }
    __shared__ float s1[8], s2[8];
    if ((t & 31) == 0) { s1[t >> 5] = a; s2[t >> 5] = sq; }
    __syncthreads();
    __shared__ float mu, rs;
    if (t == 0) {
        float A = 0.f, B = 0.f;
#pragma unroll
        for (int i = 0; i < 8; i++) { A += s1[i]; B += s2[i]; }
        float m = A * (1.0f / 256.0f);
        mu = m;
        rs = rsqrtf(B * (1.0f / 256.0f) - m * m + EPSV);
    }
    __syncthreads();
    out[(size_t)n * 256 + t] = (v - mu) * rs * g[t] + b[t];
}

__global__ void x_final_kernel(const float* __restrict__ xin, const float* __restrict__ xacc,
                               const float* __restrict__ cnt, float* __restrict__ xout) {
    int i = blockIdx.x * blockDim.x + threadIdx.x;
    if (i >= NN * 12) return;
    int n = i / 12;
    xout[i] = xin[i] + xacc[i] / fmaxf(cnt[n], 1.0f);
}

// ---------------- host ----------------
extern "C" void kernel_launch(void* const* d_in, const int* in_sizes, int n_in,
                              void* d_out, int out_size) {
    const float* input  = nullptr;
    const float* coords = nullptr;
    const float* attr   = nullptr;
    const float* cw     = nullptr;
    const float* ew     = nullptr;
    const int*   el     = nullptr;
    for (int i = 0; i < 6; i++) {
        switch (in_sizes[i]) {
            case NN * HH:     input  = (const float*)d_in[i]; break;
            case NN * 4 * 3:  coords = (const float*)d_in[i]; break;
            case NN * 4 * 16: attr   = (const float*)d_in[i]; break;
            case NN * 4:      cw     = (const float*)d_in[i]; break;
            case EE:          ew     = (const float*)d_in[i]; break;
            case EE * 3:      el     = (const int*)  d_in[i]; break;
        }
    }
    const float* W_rad = (const float*)d_in[6];
    const float* b_rad = (const float*)d_in[7];
    const float* W_e1  = (const float*)d_in[8];
    const float* b_e1  = (const float*)d_in[9];
    const float* W_e2  = (const float*)d_in[10];
    const float* b_e2  = (const float*)d_in[11];
    const float* W_c1  = (const float*)d_in[12];
    const float* b_c1  = (const float*)d_in[13];
    const float* W_c2  = (const float*)d_in[14];
    const float* W_n1  = (const float*)d_in[15];
    const float* b_n1  = (const float*)d_in[16];
    const float* W_n2  = (const float*)d_in[17];
    const float* b_n2  = (const float*)d_in[18];
    const float* ln_g  = (const float*)d_in[19];
    const float* ln_b  = (const float*)d_in[20];

    float* buf = nullptr;
    cudaGetSymbolAddress((void**)&buf, g_buf);

    float*  g_ca   = buf + OFF_CA;
    float*  g_pq   = buf + OFF_PQ;
    __half* g_hcah = (__half*)(buf + OFF_HCAH);
    __half* g_m1h  = (__half*)(buf + OFF_M1H);
    __half* g_mh   = (__half*)(buf + OFF_MH);
    float*  g_agg  = buf + OFF_AGG;
    __half* g_ninh = (__half*)(buf + OFF_NINH);
    __half* g_h1h  = (__half*)(buf + OFF_H1H);
    float*  g_hbuf = buf + OFF_HBUF;
    float*  g_xbuf = buf + OFF_XBUF;
    float*  g_xacc = buf + OFF_XACC;
    float*  g_cnt  = buf + OFF_CNT;
    __half* g_wpqt = (__half*)(buf + OFF_WPQT);
    __half* g_we2t = (__half*)(buf + OFF_WE2T);
    __half* g_wc1t = (__half*)(buf + OFF_WC1T);
    __half* g_wn2t = (__half*)(buf + OFF_WN2T);
    __half* g_wn1t = (__half*)(buf + OFF_WN1T);

    cudaFuncSetAttribute((const void*)hgemm_kernel<0, false, false>,
                         cudaFuncAttributeMaxDynamicSharedMemorySize, HSMEM_BYTES);
    cudaFuncSetAttribute((const void*)hgemm_kernel<2, true, true>,
                         cudaFuncAttributeMaxDynamicSharedMemorySize, HSMEM_BYTES);
    cudaFuncSetAttribute((const void*)hgemm_kernel<1, false, true>,
                         cudaFuncAttributeMaxDynamicSharedMemorySize, HSMEM_BYTES);
    cudaFuncSetAttribute((const void*)gemm_phix_kernel,
                         cudaFuncAttributeMaxDynamicSharedMemorySize, HSMEM_BYTES);

    // one-time: ca, cnt
    ca_kernel<<<(NN + 255) / 256, 256>>>(attr, cw, g_ca);
    zero4_kernel<<<(NN/4 + 255) / 256, 256>>>((float4*)g_cnt, (size_t)NN / 4);
    cnt_kernel<<<(EE + 255) / 256, 256>>>(el, g_cnt);

    for (int l = 0; l < LL; l++) {
        const float* h_in = (l == 0) ? input  : g_hbuf;
        const float* x_in = (l == 0) ? coords : g_xbuf;
        float* h_out = (l == LL - 1) ? (float*)d_out : g_hbuf;
        float* x_out = (l == LL - 1) ? ((float*)d_out + (size_t)NN * HH) : g_xbuf;

        const float* Wr  = W_rad + (size_t)l * 256;
        const float* br  = b_rad + (size_t)l * 16;
        const float* We1 = W_e1 + (size_t)l * 560 * 256;
        const float* be1 = b_e1 + (size_t)l * 256;
        const float* We2 = W_e2 + (size_t)l * 256 * 256;
        const float* be2 = b_e2 + (size_t)l * 256;
        const float* Wc1 = W_c1 + (size_t)l * 256 * 256;
        const float* bc1 = b_c1 + (size_t)l * 256;
        const float* Wc2 = W_c2 + (size_t)l * 256 * 16;
        const float* Wn1 = W_n1 + (size_t)l * 2048 * 256;
        const float* bn1 = b_n1 + (size_t)l * 256;
        const float* Wn2 = W_n2 + (size_t)l * 256 * 256;
        const float* bn2 = b_n2 + (size_t)l * 256;
        const float* lg  = ln_g + (size_t)l * 256;
        const float* lb  = ln_b + (size_t)l * 256;

        wprep_all<<<1280, 256>>>(We2, Wc1, Wn2, Wn1, We1,
                                 g_we2t, g_wc1t, g_wn2t, g_wn1t, g_wpqt);
        hca_pack_zero<<<(HPZ_TOT + 255) / 256, 256>>>(
            h_in, g_ca, (__half2*)g_hcah, (float4*)g_agg, (float4*)g_xacc);
        // PQ = hca @ WpqT^T
        hgemm_kernel<0, false, false><<<dim3(4, (NN + 127) / 128), 512, HSMEM_BYTES>>>(
            g_hcah, 288, g_wpqt, nullptr, nullptr, g_pq, nullptr, nullptr, NN, 512, 288);
        // m1
        edge_fuse_kernel<<<EE / 64, 256>>>(g_pq, x_in, el, cw,
                                           Wr, br, We1 + (size_t)512 * 256, be1, g_m1h);
        // m + agg scatter
        hgemm_kernel<2, true, true><<<dim3(2, EE / 128), 512, HSMEM_BYTES>>>(
            g_m1h, 256, g_we2t, be2, ew, g_mh, el, g_agg, EE, 256, 256);
        // fused Wc1 GEMM + phi + x scatter
        gemm_phix_kernel<<<dim3(2, EE / 128), 512, HSMEM_BYTES>>>(
            g_mh, g_wc1t, bc1, Wc2, x_in, el, g_xacc);
        // nin pack
        nin_pack<<<(NN * 1024 + 255) / 256, 256>>>(g_agg, h_in, (__half2*)g_ninh);
        // h1
        hgemm_kernel<1, false, true><<<dim3(2, (NN + 127) / 128), 512, HSMEM_BYTES>>>(
            g_ninh, 2048, g_wn1t, bn1, nullptr, g_h1h, nullptr, nullptr, NN, 256, 2048);
        // h2
        hgemm_kernel<0, false, false><<<dim3(2, (NN + 127) / 128), 512, HSMEM_BYTES>>>(
            g_h1h, 256, g_wn2t, bn2, nullptr, g_pq, nullptr, nullptr, NN, 256, 256);

        ln_kernel<<<NN, 256>>>(g_pq, lg, lb, h_out);
        x_final_kernel<<<(NN * 12 + 255) / 256, 256>>>(x_in, g_xacc, g_cnt, x_out);
    }
}

// round 16
// speedup vs baseline: 4.5561x; 1.0053x over previous
#include <cuda_runtime.h>
#include <cuda_fp16.h>
#include <cstddef>
#include <cstdint>

#define NN 10000
#define EE 160000
#define RR 7
#define HH 256
#define LL 2
#define EPSV 1e-5f

// ---------------- scratch (float units) ----------------
#define OFF_CA    ((size_t)0)                          // N*16
#define OFF_PQ    (OFF_CA   + (size_t)160000)          // N*512 f32
#define OFF_M1H   (OFF_PQ   + (size_t)5120000)         // E*256 half
#define OFF_MH    (OFF_M1H  + (size_t)20480000)        // E*256 half
#define OFF_AGG   (OFF_MH   + (size_t)20480000)        // N*1792 f32
#define OFF_H1H   (OFF_AGG  + (size_t)17920000)        // N*256 half
#define OFF_HBUF  (OFF_H1H  + (size_t)1280000)         // N*256 f32
#define OFF_XBUF  (OFF_HBUF + (size_t)2560000)         // N*12
#define OFF_XACC  (OFF_XBUF + (size_t)120000)          // N*12
#define OFF_CNT   (OFF_XACC + (size_t)120000)          // N
#define OFF_WPQT  (OFF_CNT  + (size_t)10000)           // 512*288 half
#define OFF_WE2T  (OFF_WPQT + (size_t)73728)           // 256*256 half
#define OFF_WC1T  (OFF_WE2T + (size_t)32768)
#define OFF_WN2T  (OFF_WC1T + (size_t)32768)
#define OFF_WN1T  (OFF_WN2T + (size_t)32768)           // 256*2048 half
#define TOTAL_F   (OFF_WN1T + (size_t)262144)

__device__ float g_buf[TOTAL_F];

__device__ __forceinline__ float silu_f(float v) { return v / (1.0f + __expf(-v)); }

__device__ __forceinline__ uint32_t pack_h2(float lo, float hi) {
    uint32_t u;
    asm("cvt.rn.f16x2.f32 %0, %1, %2;" : "=r"(u) : "f"(hi), "f"(lo));
    return u;
}

__device__ __forceinline__ void cp_async16(uint32_t dst, const void* src, bool p) {
    asm volatile("cp.async.cg.shared.global [%0], [%1], 16, %2;\n"
                 :: "r"(dst), "l"(src), "r"(p ? 16 : 0));
}
__device__ __forceinline__ void cp_commit() {
    asm volatile("cp.async.commit_group;\n");
}
template <int Np> __device__ __forceinline__ void cp_wait() {
    asm volatile("cp.async.wait_group %0;\n" :: "n"(Np));
}
__device__ __forceinline__ void red_add_v2(float* addr, float a, float b) {
    asm volatile("red.global.add.v2.f32 [%0], {%1, %2};"
                 :: "l"(addr), "f"(a), "f"(b) : "memory");
}
#define LDSM_X4(r0, r1, r2, r3, addr) \
    asm volatile("ldmatrix.sync.aligned.m8n8.x4.shared.b16 {%0,%1,%2,%3}, [%4];" \
                 : "=r"(r0), "=r"(r1), "=r"(r2), "=r"(r3) : "r"(addr))

// ---------------- small kernels ----------------
__global__ void zero4_kernel(float4* __restrict__ p, size_t n4) {
    size_t i = (size_t)blockIdx.x * blockDim.x + threadIdx.x;
    if (i < n4) p[i] = make_float4(0.f, 0.f, 0.f, 0.f);
}

__global__ void ca_kernel(const float* __restrict__ attr, const float* __restrict__ cw,
                          float* __restrict__ ca) {
    int n = blockIdx.x * blockDim.x + threadIdx.x;
    if (n >= NN) return;
    float w0 = cw[n*4+0], w1 = cw[n*4+1], w2 = cw[n*4+2], w3 = cw[n*4+3];
    float inv = 1.0f / (w0 + w1 + w2 + w3);
    const float* a = attr + (size_t)n * 64;
#pragma unroll
    for (int f = 0; f < 16; f++)
        ca[n*16+f] = (a[f]*w0 + a[16+f]*w1 + a[32+f]*w2 + a[48+f]*w3) * inv;
}

__global__ void cnt_kernel(const int* __restrict__ el, float* __restrict__ cnt) {
    int e = blockIdx.x * blockDim.x + threadIdx.x;
    if (e >= EE) return;
    atomicAdd(&cnt[el[3*e]], 1.0f);
}

// 32x32 tile transpose: W [K][256] f32 -> WT [256][K] half
__device__ __forceinline__ void transpose_tile(const float* __restrict__ W,
                                               __half* __restrict__ WT,
                                               int kb, int nb, int K) {
    __shared__ float t[32][33];
    int tx = threadIdx.x & 31, ty = threadIdx.x >> 5;
#pragma unroll
    for (int d = 0; d < 32; d += 8)
        t[ty + d][tx] = W[(size_t)(kb + ty + d) * 256 + nb + tx];
    __syncthreads();
#pragma unroll
    for (int d = 0; d < 32; d += 8)
        WT[(size_t)(nb + ty + d) * K + kb + tx] = __float2half_rn(t[tx][ty + d]);
}

// merged weight prep: 1280 blocks
__global__ void wprep_all(const float* __restrict__ We2, const float* __restrict__ Wc1,
                          const float* __restrict__ Wn2, const float* __restrict__ Wn1,
                          const float* __restrict__ We1,
                          __half* __restrict__ We2T, __half* __restrict__ Wc1T,
                          __half* __restrict__ Wn2T, __half* __restrict__ Wn1T,
                          __half* __restrict__ WpqT) {
    int bid = blockIdx.x;
    if (bid < 192) {
        int w = bid >> 6;
        const float* W = (w == 0) ? We2 : (w == 1) ? Wc1 : Wn2;
        __half* O = (w == 0) ? We2T : (w == 1) ? Wc1T : Wn2T;
        int t = bid & 63;
        transpose_tile(W, O, (t >> 3) * 32, (t & 7) * 32, 256);
    } else if (bid < 704) {
        int t = bid - 192;
        transpose_tile(Wn1, Wn1T, (t >> 3) * 32, (t & 7) * 32, 2048);
    } else {
        int i = (bid - 704) * 256 + threadIdx.x;   // over 512*288
        int n = i / 288, k = i % 288;
        float v = 0.f;
        if (k < 272) {
            int j = (n < 256) ? n : n - 256;
            int kk = (n < 256) ? ((k < 256) ? k : 528 + (k - 256))
                               : ((k < 256) ? 256 + k : 544 + (k - 256));
            v = We1[(size_t)kk * 256 + j];
        }
        WpqT[i] = __float2half_rn(v);
    }
}

// ---------------- fp16 GEMM common ----------------
#define HAS 56
#define HA_SZ (128 * HAS)
#define HNSTG 3
#define HSMEM_BYTES (HNSTG * 2 * HA_SZ * 2)

// ---------------- hgemm: half A (cp.async), single-sync mainloop ----------------
template <int ACT, bool FUSE_AGG, bool OUT_HALF>
__global__ __launch_bounds__(512, 2) void hgemm_kernel(
    const __half* __restrict__ A, int lda,
    const __half* __restrict__ B,
    const float* __restrict__ bias, const float* __restrict__ rowscale,
    void* __restrict__ Cv,
    const int* __restrict__ el, float* __restrict__ agg,
    int M, int Nc, int K)
{
    extern __shared__ __half hsm[];
    uint32_t su = (uint32_t)__cvta_generic_to_shared(hsm);

    int tid = threadIdx.x;
    int rowBase = blockIdx.y * 128, colBase = blockIdx.x * 128;
    int warp = tid >> 5, lane = tid & 31;
    int wm = warp >> 2, wn = warp & 3;
    int gr = lane >> 2, gc = lane & 3;

    uint32_t aoff = (uint32_t)((wm * 32 + ((lane >> 3) & 1) * 8 + (lane & 7)) * HAS
                               + (lane >> 4) * 8);
    uint32_t boff = (uint32_t)((wn * 32 + (lane >> 4) * 8 + (lane & 7)) * HAS
                               + ((lane >> 3) & 1) * 8);
    uint32_t aBase = su + aoff * 2;
    uint32_t bBase = su + (uint32_t)(HNSTG * HA_SZ) * 2 + boff * 2;

    float c_[2][4][4];
#pragma unroll
    for (int i = 0; i < 2; i++)
#pragma unroll
        for (int j = 0; j < 4; j++)
#pragma unroll
            for (int q = 0; q < 4; q++) c_[i][j][q] = 0.0f;

    int nt = K >> 5;

    auto load_stage = [&](int s, int t) {
        int k0 = t << 5;
        {
            int arow = tid >> 2, ach = (tid & 3) * 8;
            int r = rowBase + arow;
            cp_async16(su + (uint32_t)(s * HA_SZ + arow * HAS + ach) * 2,
                       A + (size_t)r * lda + k0 + ach, r < M);
        }
        {
            int nrow = tid >> 2, bch = (tid & 3) * 8;
            cp_async16(su + (uint32_t)(HNSTG * HA_SZ + s * HA_SZ + nrow * HAS + bch) * 2,
                       B + (size_t)(colBase + nrow) * K + k0 + bch, true);
        }
        cp_commit();
    };

#pragma unroll
    for (int s = 0; s < HNSTG - 1; s++) {
        if (s < nt) load_stage(s, s); else cp_commit();
    }

    for (int t = 0; t < nt; t++) {
        cp_wait<HNSTG - 2>();
        __syncthreads();
        int cur = t % HNSTG;
        if (t + HNSTG - 1 < nt) load_stage((t + HNSTG - 1) % HNSTG, t + HNSTG - 1);
        else cp_commit();
        uint32_t aS = aBase + (uint32_t)(cur * HA_SZ) * 2;
        uint32_t bS = bBase + (uint32_t)(cur * HA_SZ) * 2;
#pragma unroll
        for (int kk = 0; kk < 32; kk += 16) {
            uint32_t af[2][4], bf[4][2];
            LDSM_X4(af[0][0], af[0][1], af[0][2], af[0][3], aS + kk * 2);
            LDSM_X4(af[1][0], af[1][1], af[1][2], af[1][3], aS + (16 * HAS + kk) * 2);
            LDSM_X4(bf[0][0], bf[0][1], bf[1][0], bf[1][1], bS + kk * 2);
            LDSM_X4(bf[2][0], bf[2][1], bf[3][0], bf[3][1], bS + (16 * HAS + kk) * 2);
#pragma unroll
            for (int i = 0; i < 2; i++)
#pragma unroll
                for (int j = 0; j < 4; j++) {
                    asm volatile(
                        "mma.sync.aligned.m16n8k16.row.col.f32.f16.f16.f32 "
                        "{%0,%1,%2,%3}, {%4,%5,%6,%7}, {%8,%9}, {%0,%1,%2,%3};\n"
                        : "+f"(c_[i][j][0]), "+f"(c_[i][j][1]),
                          "+f"(c_[i][j][2]), "+f"(c_[i][j][3])
                        : "r"(af[i][0]), "r"(af[i][1]), "r"(af[i][2]), "r"(af[i][3]),
                          "r"(bf[j][0]), "r"(bf[j][1]));
                }
        }
    }

    // epilogue (no smem use)
#pragma unroll
    for (int i = 0; i < 2; i++) {
        int rr0 = rowBase + wm * 32 + i * 16 + gr;
#pragma unroll
        for (int half = 0; half < 2; half++) {
            int r = rr0 + half * 8;
            if (r >= M) continue;
            float sc = (ACT == 2) ? rowscale[r] : 1.0f;
            size_t ab = 0;
            if (FUSE_AGG) {
                int cc = el[3 * r + 1], rl = el[3 * r + 2];
                ab = ((size_t)cc * RR + rl) * 256;
            }
#pragma unroll
            for (int j = 0; j < 4; j++) {
                int cn = colBase + wn * 32 + j * 8 + gc * 2;
                float b0 = bias ? bias[cn] : 0.f;
                float b1 = bias ? bias[cn + 1] : 0.f;
                float v0 = c_[i][j][half * 2 + 0] + b0;
                float v1 = c_[i][j][half * 2 + 1] + b1;
                if (ACT >= 1) { v0 = silu_f(v0); v1 = silu_f(v1); }
                if (ACT == 2) { v0 *= sc; v1 *= sc; }
                if (OUT_HALF) {
                    *(uint32_t*)&((__half*)Cv)[(size_t)r * Nc + cn] = pack_h2(v0, v1);
                } else {
                    *(float2*)&((float*)Cv)[(size_t)r * Nc + cn] = make_float2(v0, v1);
                }
                if (FUSE_AGG) red_add_v2(&agg[ab + cn], v0, v1);
            }
        }
    }
}

// ---------------- hgemm_f32a: fp32 dual-source A (LDG+cvt+STS), B via cp.async ----------------
// A cols [0,K1) from A (f32, stride lda); [K1, K1+K2v) from A2 (f32, stride lda2); rest zero.
template <int ACT, bool OUT_HALF>
__global__ __launch_bounds__(512, 2) void hgemm_f32a_kernel(
    const float* __restrict__ A, int lda,
    const float* __restrict__ A2, int lda2, int K1, int K2v,
    const __half* __restrict__ B,
    const float* __restrict__ bias,
    void* __restrict__ Cv,
    int M, int Nc, int K)
{
    extern __shared__ __half hsm[];
    uint32_t su = (uint32_t)__cvta_generic_to_shared(hsm);

    int tid = threadIdx.x;
    int rowBase = blockIdx.y * 128, colBase = blockIdx.x * 128;
    int warp = tid >> 5, lane = tid & 31;
    int wm = warp >> 2, wn = warp & 3;
    int gr = lane >> 2, gc = lane & 3;

    uint32_t aoff = (uint32_t)((wm * 32 + ((lane >> 3) & 1) * 8 + (lane & 7)) * HAS
                               + (lane >> 4) * 8);
    uint32_t boff = (uint32_t)((wn * 32 + (lane >> 4) * 8 + (lane & 7)) * HAS
                               + ((lane >> 3) & 1) * 8);
    uint32_t aBase = su + aoff * 2;
    uint32_t bBase = su + (uint32_t)(HNSTG * HA_SZ) * 2 + boff * 2;

    int arow = tid >> 2, akg = (tid & 3) * 8;
    int ar = rowBase + arow;
    bool arok = ar < M;

    float c_[2][4][4];
#pragma unroll
    for (int i = 0; i < 2; i++)
#pragma unroll
        for (int j = 0; j < 4; j++)
#pragma unroll
            for (int q = 0; q < 4; q++) c_[i][j][q] = 0.0f;

    int nt = K >> 5;

    auto ldgA = [&](int t, uint32_t* r4) {
        int k = (t << 5) + akg;
        float4 v0 = make_float4(0.f, 0.f, 0.f, 0.f);
        float4 v1 = v0;
        if (arok) {
            if (k < K1) {
                const float* s = A + (size_t)ar * lda + k;
                v0 = *(const float4*)s; v1 = *(const float4*)(s + 4);
            } else {
                int kk = k - K1;
                if (kk < K2v) {
                    const float* s = A2 + (size_t)ar * lda2 + kk;
                    v0 = *(const float4*)s; v1 = *(const float4*)(s + 4);
                }
            }
        }
        r4[0] = pack_h2(v0.x, v0.y);
        r4[1] = pack_h2(v0.z, v0.w);
        r4[2] = pack_h2(v1.x, v1.y);
        r4[3] = pack_h2(v1.z, v1.w);
    };
    auto stsA = [&](int s, const uint32_t* r4) {
        uint4 u = make_uint4(r4[0], r4[1], r4[2], r4[3]);
        *(uint4*)&hsm[s * HA_SZ + arow * HAS + akg] = u;
    };
    auto loadB = [&](int s, int t) {
        int k0 = t << 5;
        int nrow = tid >> 2, bch = (tid & 3) * 8;
        cp_async16(su + (uint32_t)(HNSTG * HA_SZ + s * HA_SZ + nrow * HAS + bch) * 2,
                   B + (size_t)(colBase + nrow) * K + k0 + bch, true);
        cp_commit();
    };

    // prologue
    uint32_t ra[4];
    ldgA(0, ra); stsA(0, ra);
    if (1 < nt) ldgA(1, ra);
    loadB(0, 0);
    if (1 < nt) loadB(1, 1); else cp_commit();

    for (int t = 0; t < nt; t++) {
        cp_wait<HNSTG - 2>();
        __syncthreads();
        int cur = t % HNSTG;
        if (t + 2 < nt) loadB((t + 2) % HNSTG, t + 2); else cp_commit();
        if (t + 1 < nt) stsA((t + 1) % HNSTG, ra);
        if (t + 2 < nt) ldgA(t + 2, ra);
        uint32_t aS = aBase + (uint32_t)(cur * HA_SZ) * 2;
        uint32_t bS = bBase + (uint32_t)(cur * HA_SZ) * 2;
#pragma unroll
        for (int kk = 0; kk < 32; kk += 16) {
            uint32_t af[2][4], bf[4][2];
            LDSM_X4(af[0][0], af[0][1], af[0][2], af[0][3], aS + kk * 2);
            LDSM_X4(af[1][0], af[1][1], af[1][2], af[1][3], aS + (16 * HAS + kk) * 2);
            LDSM_X4(bf[0][0], bf[0][1], bf[1][0], bf[1][1], bS + kk * 2);
            LDSM_X4(bf[2][0], bf[2][1], bf[3][0], bf[3][1], bS + (16 * HAS + kk) * 2);
#pragma unroll
            for (int i = 0; i < 2; i++)
#pragma unroll
                for (int j = 0; j < 4; j++) {
                    asm volatile(
                        "mma.sync.aligned.m16n8k16.row.col.f32.f16.f16.f32 "
                        "{%0,%1,%2,%3}, {%4,%5,%6,%7}, {%8,%9}, {%0,%1,%2,%3};\n"
                        : "+f"(c_[i][j][0]), "+f"(c_[i][j][1]),
                          "+f"(c_[i][j][2]), "+f"(c_[i][j][3])
                        : "r"(af[i][0]), "r"(af[i][1]), "r"(af[i][2]), "r"(af[i][3]),
                          "r"(bf[j][0]), "r"(bf[j][1]));
                }
        }
    }

    // epilogue
#pragma unroll
    for (int i = 0; i < 2; i++) {
        int rr0 = rowBase + wm * 32 + i * 16 + gr;
#pragma unroll
        for (int half = 0; half < 2; half++) {
            int r = rr0 + half * 8;
            if (r >= M) continue;
#pragma unroll
            for (int j = 0; j < 4; j++) {
                int cn = colBase + wn * 32 + j * 8 + gc * 2;
                float b0 = bias ? bias[cn] : 0.f;
                float b1 = bias ? bias[cn + 1] : 0.f;
                float v0 = c_[i][j][half * 2 + 0] + b0;
                float v1 = c_[i][j][half * 2 + 1] + b1;
                if (ACT >= 1) { v0 = silu_f(v0); v1 = silu_f(v1); }
                if (OUT_HALF) {
                    *(uint32_t*)&((__half*)Cv)[(size_t)r * Nc + cn] = pack_h2(v0, v1);
                } else {
                    *(float2*)&((float*)Cv)[(size_t)r * Nc + cn] = make_float2(v0, v1);
                }
            }
        }
    }
}

// ---------------- fused Wc1 fp16 GEMM + phi + x-scatter (single-sync) ----------------
__global__ __launch_bounds__(512, 2) void gemm_phix_kernel(
    const __half* __restrict__ A,           // m half, E x 256
    const __half* __restrict__ B,           // Wc1T half [256][256]
    const float* __restrict__ bc1,
    const float* __restrict__ Wc2,          // [256,16] fp32
    const float* __restrict__ x, const int* __restrict__ el,
    float* __restrict__ xacc)
{
    extern __shared__ __half hsm[];
    uint32_t su = (uint32_t)__cvta_generic_to_shared(hsm);

    int tid = threadIdx.x;
    int rowBase = blockIdx.y * 128, colBase = blockIdx.x * 128;
    int warp = tid >> 5, lane = tid & 31;
    int wm = warp >> 2, wn = warp & 3;
    int gr = lane >> 2, gc = lane & 3;

    uint32_t aoff = (uint32_t)((wm * 32 + ((lane >> 3) & 1) * 8 + (lane & 7)) * HAS
                               + (lane >> 4) * 8);
    uint32_t boff = (uint32_t)((wn * 32 + (lane >> 4) * 8 + (lane & 7)) * HAS
                               + ((lane >> 3) & 1) * 8);
    uint32_t aBase = su + aoff * 2;
    uint32_t bBase = su + (uint32_t)(HNSTG * HA_SZ) * 2 + boff * 2;

    float c_[2][4][4];
#pragma unroll
    for (int i = 0; i < 2; i++)
#pragma unroll
        for (int j = 0; j < 4; j++)
#pragma unroll
            for (int q = 0; q < 4; q++) c_[i][j][q] = 0.0f;

    const int nt = 8;   // K=256

    auto load_stage = [&](int s, int t) {
        int k0 = t << 5;
        {
            int arow = tid >> 2, ach = (tid & 3) * 8;
            cp_async16(su + (uint32_t)(s * HA_SZ + arow * HAS + ach) * 2,
                       A + (size_t)(rowBase + arow) * 256 + k0 + ach, true);
        }
        {
            int nrow = tid >> 2, bch = (tid & 3) * 8;
            cp_async16(su + (uint32_t)(HNSTG * HA_SZ + s * HA_SZ + nrow * HAS + bch) * 2,
                       B + (size_t)(colBase + nrow) * 256 + k0 + bch, true);
        }
        cp_commit();
    };

#pragma unroll
    for (int s = 0; s < HNSTG - 1; s++) load_stage(s, s);

    for (int t = 0; t < nt; t++) {
        cp_wait<HNSTG - 2>();
        __syncthreads();
        int cur = t % HNSTG;
        if (t + HNSTG - 1 < nt) load_stage((t + HNSTG - 1) % HNSTG, t + HNSTG - 1);
        else cp_commit();
        uint32_t aS = aBase + (uint32_t)(cur * HA_SZ) * 2;
        uint32_t bS = bBase + (uint32_t)(cur * HA_SZ) * 2;
#pragma unroll
        for (int kk = 0; kk < 32; kk += 16) {
            uint32_t af[2][4], bf[4][2];
            LDSM_X4(af[0][0], af[0][1], af[0][2], af[0][3], aS + kk * 2);
            LDSM_X4(af[1][0], af[1][1], af[1][2], af[1][3], aS + (16 * HAS + kk) * 2);
            LDSM_X4(bf[0][0], bf[0][1], bf[1][0], bf[1][1], bS + kk * 2);
            LDSM_X4(bf[2][0], bf[2][1], bf[3][0], bf[3][1], bS + (16 * HAS + kk) * 2);
#pragma unroll
            for (int i = 0; i < 2; i++)
#pragma unroll
                for (int j = 0; j < 4; j++) {
                    asm volatile(
                        "mma.sync.aligned.m16n8k16.row.col.f32.f16.f16.f32 "
                        "{%0,%1,%2,%3}, {%4,%5,%6,%7}, {%8,%9}, {%0,%1,%2,%3};\n"
                        : "+f"(c_[i][j][0]), "+f"(c_[i][j][1]),
                          "+f"(c_[i][j][2]), "+f"(c_[i][j][3])
                        : "r"(af[i][0]), "r"(af[i][1]), "r"(af[i][2]), "r"(af[i][3]),
                          "r"(bf[j][0]), "r"(bf[j][1]));
                }
        }
    }
    __syncthreads();   // protect smem reuse below

    // ---- epilogue: phi partial over this CTA's 128 cols ----
    float* sT  = (float*)hsm;             // [128][36]
    float* sW2 = (float*)hsm + 128 * 36;  // [128][17]
    float* sB1 = sW2 + 128 * 17;          // [128]

    if (tid < 128) sB1[tid] = bc1[colBase + tid];
    for (int idx = tid; idx < 128 * 16; idx += 512) {
        int rr = idx >> 4, n = idx & 15;
        sW2[rr * 17 + n] = Wc2[(size_t)(colBase + rr) * 16 + n];
    }

    float p[4];
#pragma unroll
    for (int n = 0; n < 4; n++) p[n] = 0.0f;
    int pr = tid >> 2;
    int pn0 = (tid & 3) * 4;

#pragma unroll 1
    for (int ch = 0; ch < 4; ch++) {
        __syncthreads();
        if (wn == ch) {
#pragma unroll
            for (int j = 0; j < 4; j++) {
                int lcol = j * 8 + gc * 2;
                float bb0 = sB1[ch * 32 + lcol];
                float bb1 = sB1[ch * 32 + lcol + 1];
#pragma unroll
                for (int i = 0; i < 2; i++)
#pragma unroll
                    for (int half = 0; half < 2; half++) {
                        int lr = wm * 32 + i * 16 + half * 8 + gr;
                        float v0 = silu_f(c_[i][j][half * 2 + 0] + bb0);
                        float v1 = silu_f(c_[i][j][half * 2 + 1] + bb1);
                        *(float2*)&sT[lr * 36 + lcol] = make_float2(v0, v1);
                    }
            }
        }
        __syncthreads();
#pragma unroll
        for (int cb = 0; cb < 8; cb++) {
            float4 t4 = *(const float4*)&sT[pr * 36 + cb * 4];
#pragma unroll
            for (int k = 0; k < 4; k++) {
                float tv = (&t4.x)[k];
                int wr = ch * 32 + cb * 4 + k;
#pragma unroll
                for (int n = 0; n < 4; n++)
                    p[n] = fmaf(tv, sW2[wr * 17 + pn0 + n], p[n]);
            }
        }
    }

    {
        int i2 = tid & 3;
        int e = rowBase + pr;
        int rw = el[3 * e], cl = el[3 * e + 1];
        float xr0 = x[rw * 12 + i2 * 3 + 0];
        float xr1 = x[rw * 12 + i2 * 3 + 1];
        float xr2 = x[rw * 12 + i2 * 3 + 2];
        float s0 = 0.f, s1 = 0.f, s2 = 0.f;
#pragma unroll
        for (int j2 = 0; j2 < 4; j2++) {
            float ph = p[j2];
            s0 = fmaf(xr0 - x[cl * 12 + j2 * 3 + 0], ph, s0);
            s1 = fmaf(xr1 - x[cl * 12 + j2 * 3 + 1], ph, s1);
            s2 = fmaf(xr2 - x[cl * 12 + j2 * 3 + 2], ph, s2);
        }
        atomicAdd(&xacc[rw * 12 + i2 * 3 + 0], 0.25f * s0);
        atomicAdd(&xacc[rw * 12 + i2 * 3 + 1], 0.25f * s1);
        atomicAdd(&xacc[rw * 12 + i2 * 3 + 2], 0.25f * s2);
    }
}

// ---------------- edge fuse (half out) ----------------
__global__ __launch_bounds__(256) void edge_fuse_kernel(
    const float* __restrict__ PQ,
    const float* __restrict__ x, const int* __restrict__ el,
    const float* __restrict__ cw,
    const float* __restrict__ Wrad, const float* __restrict__ brad,
    const float* __restrict__ W1c, const float* __restrict__ be1,
    __half* __restrict__ m1)
{
    __shared__ __align__(16) float sW1c[16][256];
    __shared__ float sWrad[16][16];
    __shared__ float sbrad[16];
    __shared__ __align__(16) float sbe1[256];
    __shared__ float srad[8][16];
    __shared__ float srf[8][16];
    int tid = threadIdx.x;
    for (int i = tid; i < 16 * 256; i += 256) sW1c[i >> 8][i & 255] = W1c[i];
    sbe1[tid] = be1[tid];
    { int r = tid >> 4, c = tid & 15; sWrad[r][c] = Wrad[tid]; }
    if (tid < 16) sbrad[tid] = brad[tid];
    __syncthreads();

    int warp = tid >> 5, lane = tid & 31;
#pragma unroll 1
    for (int ei = 0; ei < 8; ei++) {
        int e = blockIdx.x * 64 + warp * 8 + ei;
        int row = el[3*e], col = el[3*e+1];

        if (lane < 16) {
            int i = lane >> 2, j = lane & 3;
            float dx = x[row*12 + i*3 + 0] - x[col*12 + j*3 + 0];
            float dy = x[row*12 + i*3 + 1] - x[col*12 + j*3 + 1];
            float dz = x[row*12 + i*3 + 2] - x[col*12 + j*3 + 2];
            srad[warp][lane] = (dx*dx + dy*dy + dz*dz) * cw[row*4 + i] * cw[col*4 + j];
        }
        __syncwarp();
        if (lane < 16) {
            float acc = sbrad[lane];
#pragma unroll
            for (int k = 0; k < 16; k++) acc = fmaf(srad[warp][k], sWrad[k][lane], acc);
            srf[warp][lane] = silu_f(acc);
        }
        __syncwarp();

        const float4* Pr = (const float4*)(PQ + (size_t)row * 512);
        const float4* Qc = (const float4*)(PQ + (size_t)col * 512 + 256);
        __half* Om = m1 + (size_t)e * 256;
#pragma unroll
        for (int half = 0; half < 2; half++) {
            int o4 = lane * 2 + half;
            float4 pv = Pr[o4], qv = Qc[o4];
            float4 b = ((const float4*)sbe1)[o4];
            float4 s = make_float4(pv.x + qv.x + b.x, pv.y + qv.y + b.y,
                                   pv.z + qv.z + b.z, pv.w + qv.w + b.w);
#pragma unroll
            for (int k = 0; k < 16; k++) {
                float rk = srf[warp][k];
                float4 w = ((const float4*)&sW1c[k][0])[o4];
                s.x = fmaf(rk, w.x, s.x); s.y = fmaf(rk, w.y, s.y);
                s.z = fmaf(rk, w.z, s.z); s.w = fmaf(rk, w.w, s.w);
            }
            *(uint32_t*)&Om[o4 * 4]     = pack_h2(silu_f(s.x), silu_f(s.y));
            *(uint32_t*)&Om[o4 * 4 + 2] = pack_h2(silu_f(s.z), silu_f(s.w));
        }
        __syncwarp();
    }
}

// ---------------- layernorm ----------------
__global__ void ln_kernel(const float* __restrict__ h2, const float* __restrict__ g,
                          const float* __restrict__ b, float* __restrict__ out) {
    int n = blockIdx.x;
    int t = threadIdx.x;
    float v = h2[(size_t)n * 256 + t];
    float a = v, sq = v * v;
#pragma unroll
    for (int o = 16; o > 0; o >>= 1) {
        a  += __shfl_down_sync(0xFFFFFFFFu, a, o);
        sq += __shfl_down_sync(0xFFFFFFFFu, sq, o);
    }
    __shared__ float s1[8], s2[8];
    if ((t & 31) == 0) { s1[t >> 5] = a; s2[t >> 5] = sq; }
    __syncthreads();
    __shared__ float mu, rs;
    if (t == 0) {
        float A = 0.f, B = 0.f;
#pragma unroll
        for (int i = 0; i < 8; i++) { A += s1[i]; B += s2[i]; }
        float m = A * (1.0f / 256.0f);
        mu = m;
        rs = rsqrtf(B * (1.0f / 256.0f) - m * m + EPSV);
    }
    __syncthreads();
    out[(size_t)n * 256 + t] = (v - mu) * rs * g[t] + b[t];
}

__global__ void x_final_kernel(const float* __restrict__ xin, const float* __restrict__ xacc,
                               const float* __restrict__ cnt, float* __restrict__ xout) {
    int i = blockIdx.x * blockDim.x + threadIdx.x;
    if (i >= NN * 12) return;
    int n = i / 12;
    xout[i] = xin[i] + xacc[i] / fmaxf(cnt[n], 1.0f);
}

// ---------------- host ----------------
extern "C" void kernel_launch(void* const* d_in, const int* in_sizes, int n_in,
                              void* d_out, int out_size) {
    const float* input  = nullptr;
    const float* coords = nullptr;
    const float* attr   = nullptr;
    const float* cw     = nullptr;
    const float* ew     = nullptr;
    const int*   el     = nullptr;
    for (int i = 0; i < 6; i++) {
        switch (in_sizes[i]) {
            case NN * HH:     input  = (const float*)d_in[i]; break;
            case NN * 4 * 3:  coords = (const float*)d_in[i]; break;
            case NN * 4 * 16: attr   = (const float*)d_in[i]; break;
            case NN * 4:      cw     = (const float*)d_in[i]; break;
            case EE:          ew     = (const float*)d_in[i]; break;
            case EE * 3:      el     = (const int*)  d_in[i]; break;
        }
    }
    const float* W_rad = (const float*)d_in[6];
    const float* b_rad = (const float*)d_in[7];
    const float* W_e1  = (const float*)d_in[8];
    const float* b_e1  = (const float*)d_in[9];
    const float* W_e2  = (const float*)d_in[10];
    const float* b_e2  = (const float*)d_in[11];
    const float* W_c1  = (const float*)d_in[12];
    const float* b_c1  = (const float*)d_in[13];
    const float* W_c2  = (const float*)d_in[14];
    const float* W_n1  = (const float*)d_in[15];
    const float* b_n1  = (const float*)d_in[16];
    const float* W_n2  = (const float*)d_in[17];
    const float* b_n2  = (const float*)d_in[18];
    const float* ln_g  = (const float*)d_in[19];
    const float* ln_b  = (const float*)d_in[20];

    float* buf = nullptr;
    cudaGetSymbolAddress((void**)&buf, g_buf);

    float*  g_ca   = buf + OFF_CA;
    float*  g_pq   = buf + OFF_PQ;
    __half* g_m1h  = (__half*)(buf + OFF_M1H);
    __half* g_mh   = (__half*)(buf + OFF_MH);
    float*  g_agg  = buf + OFF_AGG;
    __half* g_h1h  = (__half*)(buf + OFF_H1H);
    float*  g_hbuf = buf + OFF_HBUF;
    float*  g_xbuf = buf + OFF_XBUF;
    float*  g_xacc = buf + OFF_XACC;
    float*  g_cnt  = buf + OFF_CNT;
    __half* g_wpqt = (__half*)(buf + OFF_WPQT);
    __half* g_we2t = (__half*)(buf + OFF_WE2T);
    __half* g_wc1t = (__half*)(buf + OFF_WC1T);
    __half* g_wn2t = (__half*)(buf + OFF_WN2T);
    __half* g_wn1t = (__half*)(buf + OFF_WN1T);

    cudaFuncSetAttribute((const void*)hgemm_kernel<2, true, true>,
                         cudaFuncAttributeMaxDynamicSharedMemorySize, HSMEM_BYTES);
    cudaFuncSetAttribute((const void*)hgemm_kernel<0, false, false>,
                         cudaFuncAttributeMaxDynamicSharedMemorySize, HSMEM_BYTES);
    cudaFuncSetAttribute((const void*)hgemm_f32a_kernel<0, false>,
                         cudaFuncAttributeMaxDynamicSharedMemorySize, HSMEM_BYTES);
    cudaFuncSetAttribute((const void*)hgemm_f32a_kernel<1, true>,
                         cudaFuncAttributeMaxDynamicSharedMemorySize, HSMEM_BYTES);
    cudaFuncSetAttribute((const void*)gemm_phix_kernel,
                         cudaFuncAttributeMaxDynamicSharedMemorySize, HSMEM_BYTES);

    // one-time: ca, cnt
    ca_kernel<<<(NN + 255) / 256, 256>>>(attr, cw, g_ca);
    zero4_kernel<<<(NN/4 + 255) / 256, 256>>>((float4*)g_cnt, (size_t)NN / 4);
    cnt_kernel<<<(EE + 255) / 256, 256>>>(el, g_cnt);

    for (int l = 0; l < LL; l++) {
        const float* h_in = (l == 0) ? input  : g_hbuf;
        const float* x_in = (l == 0) ? coords : g_xbuf;
        float* h_out = (l == LL - 1) ? (float*)d_out : g_hbuf;
        float* x_out = (l == LL - 1) ? ((float*)d_out + (size_t)NN * HH) : g_xbuf;

        const float* Wr  = W_rad + (size_t)l * 256;
        const float* br  = b_rad + (size_t)l * 16;
        const float* We1 = W_e1 + (size_t)l * 560 * 256;
        const float* be1 = b_e1 + (size_t)l * 256;
        const float* We2 = W_e2 + (size_t)l * 256 * 256;
        const float* be2 = b_e2 + (size_t)l * 256;
        const float* Wc1 = W_c1 + (size_t)l * 256 * 256;
        const float* bc1 = b_c1 + (size_t)l * 256;
        const float* Wc2 = W_c2 + (size_t)l * 256 * 16;
        const float* Wn1 = W_n1 + (size_t)l * 2048 * 256;
        const float* bn1 = b_n1 + (size_t)l * 256;
        const float* Wn2 = W_n2 + (size_t)l * 256 * 256;
        const float* bn2 = b_n2 + (size_t)l * 256;
        const float* lg  = ln_g + (size_t)l * 256;
        const float* lb  = ln_b + (size_t)l * 256;

        wprep_all<<<1280, 256>>>(We2, Wc1, Wn2, Wn1, We1,
                                 g_we2t, g_wc1t, g_wn2t, g_wn1t, g_wpqt);
        zero4_kernel<<<(unsigned)(((size_t)NN*1792/4 + 255) / 256), 256>>>(
            (float4*)g_agg, (size_t)NN*1792/4);
        zero4_kernel<<<(NN*12/4 + 255) / 256, 256>>>((float4*)g_xacc, (size_t)NN*12/4);

        // PQ = [h|ca] @ WpqT^T  (f32 A dual source, f32 out)
        hgemm_f32a_kernel<0, false><<<dim3(4, (NN + 127) / 128), 512, HSMEM_BYTES>>>(
            h_in, 256, g_ca, 16, 256, 16,
            g_wpqt, nullptr, g_pq, NN, 512, 288);
        // m1
        edge_fuse_kernel<<<EE / 64, 256>>>(g_pq, x_in, el, cw,
                                           Wr, br, We1 + (size_t)512 * 256, be1, g_m1h);
        // m + agg scatter
        hgemm_kernel<2, true, true><<<dim3(2, EE / 128), 512, HSMEM_BYTES>>>(
            g_m1h, 256, g_we2t, be2, ew, g_mh, el, g_agg, EE, 256, 256);
        // fused Wc1 GEMM + phi + x scatter
        gemm_phix_kernel<<<dim3(2, EE / 128), 512, HSMEM_BYTES>>>(
            g_mh, g_wc1t, bc1, Wc2, x_in, el, g_xacc);
        // h1 = silu([agg|h]@Wn1+bn1)  (f32 A dual source, half out)
        hgemm_f32a_kernel<1, true><<<dim3(2, (NN + 127) / 128), 512, HSMEM_BYTES>>>(
            g_agg, 1792, h_in, 256, 1792, 256,
            g_wn1t, bn1, g_h1h, NN, 256, 2048);
        // h2 = h1@Wn2+bn2 (half A, f32 out)
        hgemm_kernel<0, false, false><<<dim3(2, (NN + 127) / 128), 512, HSMEM_BYTES>>>(
            g_h1h, 256, g_wn2t, bn2, nullptr, g_pq, nullptr, nullptr, NN, 256, 256);

        ln_kernel<<<NN, 256>>>(g_pq, lg, lb, h_out);
        x_final_kernel<<<(NN * 12 + 255) / 256, 256>>>(x_in, g_xacc, g_cnt, x_out);
    }
}

// round 17
// speedup vs baseline: 4.6007x; 1.0098x over previous
#include <cuda_runtime.h>
#include <cuda_fp16.h>
#include <cstddef>
#include <cstdint>

#define NN 10000
#define EE 160000
#define RR 7
#define HH 256
#define LL 2
#define EPSV 1e-5f

// ---------------- scratch (float units) ----------------
#define OFF_CA    ((size_t)0)                          // N*16
#define OFF_PQ    (OFF_CA   + (size_t)160000)          // N*512 f32
#define OFF_M1H   (OFF_PQ   + (size_t)5120000)         // E*256 half
#define OFF_AGG   (OFF_M1H  + (size_t)20480000)        // N*1792 f32
#define OFF_H1H   (OFF_AGG  + (size_t)17920000)        // N*256 half
#define OFF_HBUF  (OFF_H1H  + (size_t)1280000)         // N*256 f32
#define OFF_XBUF  (OFF_HBUF + (size_t)2560000)         // N*12
#define OFF_XACC  (OFF_XBUF + (size_t)120000)          // N*12
#define OFF_CNT   (OFF_XACC + (size_t)120000)          // N
#define OFF_WPQT  (OFF_CNT  + (size_t)10000)           // 512*288 half
#define OFF_WE2T  (OFF_WPQT + (size_t)73728)           // 256*256 half
#define OFF_WC1T  (OFF_WE2T + (size_t)32768)
#define OFF_WN2T  (OFF_WC1T + (size_t)32768)
#define OFF_WN1T  (OFF_WN2T + (size_t)32768)           // 256*2048 half
#define TOTAL_F   (OFF_WN1T + (size_t)262144)

__device__ float g_buf[TOTAL_F];

__device__ __forceinline__ float silu_f(float v) { return v / (1.0f + __expf(-v)); }

__device__ __forceinline__ uint32_t pack_h2(float lo, float hi) {
    uint32_t u;
    asm("cvt.rn.f16x2.f32 %0, %1, %2;" : "=r"(u) : "f"(hi), "f"(lo));
    return u;
}

__device__ __forceinline__ void cp_async16(uint32_t dst, const void* src, bool p) {
    asm volatile("cp.async.cg.shared.global [%0], [%1], 16, %2;\n"
                 :: "r"(dst), "l"(src), "r"(p ? 16 : 0));
}
__device__ __forceinline__ void cp_commit() {
    asm volatile("cp.async.commit_group;\n");
}
template <int Np> __device__ __forceinline__ void cp_wait() {
    asm volatile("cp.async.wait_group %0;\n" :: "n"(Np));
}
__device__ __forceinline__ void red_add_v2(float* addr, float a, float b) {
    asm volatile("red.global.add.v2.f32 [%0], {%1, %2};"
                 :: "l"(addr), "f"(a), "f"(b) : "memory");
}
#define LDSM_X4(r0, r1, r2, r3, addr) \
    asm volatile("ldmatrix.sync.aligned.m8n8.x4.shared.b16 {%0,%1,%2,%3}, [%4];" \
                 : "=r"(r0), "=r"(r1), "=r"(r2), "=r"(r3) : "r"(addr))
#define MMA16816(c0, c1, c2, c3, a0, a1, a2, a3, b0, b1) \
    asm volatile("mma.sync.aligned.m16n8k16.row.col.f32.f16.f16.f32 " \
                 "{%0,%1,%2,%3}, {%4,%5,%6,%7}, {%8,%9}, {%0,%1,%2,%3};\n" \
                 : "+f"(c0), "+f"(c1), "+f"(c2), "+f"(c3) \
                 : "r"(a0), "r"(a1), "r"(a2), "r"(a3), "r"(b0), "r"(b1))

// ---------------- small kernels ----------------
__global__ void zero4_kernel(float4* __restrict__ p, size_t n4) {
    size_t i = (size_t)blockIdx.x * blockDim.x + threadIdx.x;
    if (i < n4) p[i] = make_float4(0.f, 0.f, 0.f, 0.f);
}

__global__ void ca_kernel(const float* __restrict__ attr, const float* __restrict__ cw,
                          float* __restrict__ ca) {
    int n = blockIdx.x * blockDim.x + threadIdx.x;
    if (n >= NN) return;
    float w0 = cw[n*4+0], w1 = cw[n*4+1], w2 = cw[n*4+2], w3 = cw[n*4+3];
    float inv = 1.0f / (w0 + w1 + w2 + w3);
    const float* a = attr + (size_t)n * 64;
#pragma unroll
    for (int f = 0; f < 16; f++)
        ca[n*16+f] = (a[f]*w0 + a[16+f]*w1 + a[32+f]*w2 + a[48+f]*w3) * inv;
}

__global__ void cnt_kernel(const int* __restrict__ el, float* __restrict__ cnt) {
    int e = blockIdx.x * blockDim.x + threadIdx.x;
    if (e >= EE) return;
    atomicAdd(&cnt[el[3*e]], 1.0f);
}

// 32x32 tile transpose: W [K][256] f32 -> WT [256][K] half
__device__ __forceinline__ void transpose_tile(const float* __restrict__ W,
                                               __half* __restrict__ WT,
                                               int kb, int nb, int K) {
    __shared__ float t[32][33];
    int tx = threadIdx.x & 31, ty = threadIdx.x >> 5;
#pragma unroll
    for (int d = 0; d < 32; d += 8)
        t[ty + d][tx] = W[(size_t)(kb + ty + d) * 256 + nb + tx];
    __syncthreads();
#pragma unroll
    for (int d = 0; d < 32; d += 8)
        WT[(size_t)(nb + ty + d) * K + kb + tx] = __float2half_rn(t[tx][ty + d]);
}

// merged weight prep: 1280 blocks
__global__ void wprep_all(const float* __restrict__ We2, const float* __restrict__ Wc1,
                          const float* __restrict__ Wn2, const float* __restrict__ Wn1,
                          const float* __restrict__ We1,
                          __half* __restrict__ We2T, __half* __restrict__ Wc1T,
                          __half* __restrict__ Wn2T, __half* __restrict__ Wn1T,
                          __half* __restrict__ WpqT) {
    int bid = blockIdx.x;
    if (bid < 192) {
        int w = bid >> 6;
        const float* W = (w == 0) ? We2 : (w == 1) ? Wc1 : Wn2;
        __half* O = (w == 0) ? We2T : (w == 1) ? Wc1T : Wn2T;
        int t = bid & 63;
        transpose_tile(W, O, (t >> 3) * 32, (t & 7) * 32, 256);
    } else if (bid < 704) {
        int t = bid - 192;
        transpose_tile(Wn1, Wn1T, (t >> 3) * 32, (t & 7) * 32, 2048);
    } else {
        int i = (bid - 704) * 256 + threadIdx.x;   // over 512*288
        int n = i / 288, k = i % 288;
        float v = 0.f;
        if (k < 272) {
            int j = (n < 256) ? n : n - 256;
            int kk = (n < 256) ? ((k < 256) ? k : 528 + (k - 256))
                               : ((k < 256) ? 256 + k : 544 + (k - 256));
            v = We1[(size_t)kk * 256 + j];
        }
        WpqT[i] = __float2half_rn(v);
    }
}

// ---------------- fp16 GEMM common ----------------
#define HAS 56
#define HA_SZ (128 * HAS)
#define HNSTG 3
#define HSMEM_BYTES (HNSTG * 2 * HA_SZ * 2)

// ---------------- hgemm: half A (cp.async), single-sync mainloop ----------------
template <int ACT, bool OUT_HALF>
__global__ __launch_bounds__(512, 2) void hgemm_kernel(
    const __half* __restrict__ A, int lda,
    const __half* __restrict__ B,
    const float* __restrict__ bias,
    void* __restrict__ Cv,
    int M, int Nc, int K)
{
    extern __shared__ __half hsm[];
    uint32_t su = (uint32_t)__cvta_generic_to_shared(hsm);

    int tid = threadIdx.x;
    int rowBase = blockIdx.y * 128, colBase = blockIdx.x * 128;
    int warp = tid >> 5, lane = tid & 31;
    int wm = warp >> 2, wn = warp & 3;
    int gr = lane >> 2, gc = lane & 3;

    uint32_t aoff = (uint32_t)((wm * 32 + ((lane >> 3) & 1) * 8 + (lane & 7)) * HAS
                               + (lane >> 4) * 8);
    uint32_t boff = (uint32_t)((wn * 32 + (lane >> 4) * 8 + (lane & 7)) * HAS
                               + ((lane >> 3) & 1) * 8);
    uint32_t aBase = su + aoff * 2;
    uint32_t bBase = su + (uint32_t)(HNSTG * HA_SZ) * 2 + boff * 2;

    float c_[2][4][4];
#pragma unroll
    for (int i = 0; i < 2; i++)
#pragma unroll
        for (int j = 0; j < 4; j++)
#pragma unroll
            for (int q = 0; q < 4; q++) c_[i][j][q] = 0.0f;

    int nt = K >> 5;

    auto load_stage = [&](int s, int t) {
        int k0 = t << 5;
        {
            int arow = tid >> 2, ach = (tid & 3) * 8;
            int r = rowBase + arow;
            cp_async16(su + (uint32_t)(s * HA_SZ + arow * HAS + ach) * 2,
                       A + (size_t)r * lda + k0 + ach, r < M);
        }
        {
            int nrow = tid >> 2, bch = (tid & 3) * 8;
            cp_async16(su + (uint32_t)(HNSTG * HA_SZ + s * HA_SZ + nrow * HAS + bch) * 2,
                       B + (size_t)(colBase + nrow) * K + k0 + bch, true);
        }
        cp_commit();
    };

#pragma unroll
    for (int s = 0; s < HNSTG - 1; s++) {
        if (s < nt) load_stage(s, s); else cp_commit();
    }

    for (int t = 0; t < nt; t++) {
        cp_wait<HNSTG - 2>();
        __syncthreads();
        int cur = t % HNSTG;
        if (t + HNSTG - 1 < nt) load_stage((t + HNSTG - 1) % HNSTG, t + HNSTG - 1);
        else cp_commit();
        uint32_t aS = aBase + (uint32_t)(cur * HA_SZ) * 2;
        uint32_t bS = bBase + (uint32_t)(cur * HA_SZ) * 2;
#pragma unroll
        for (int kk = 0; kk < 32; kk += 16) {
            uint32_t af[2][4], bf[4][2];
            LDSM_X4(af[0][0], af[0][1], af[0][2], af[0][3], aS + kk * 2);
            LDSM_X4(af[1][0], af[1][1], af[1][2], af[1][3], aS + (16 * HAS + kk) * 2);
            LDSM_X4(bf[0][0], bf[0][1], bf[1][0], bf[1][1], bS + kk * 2);
            LDSM_X4(bf[2][0], bf[2][1], bf[3][0], bf[3][1], bS + (16 * HAS + kk) * 2);
#pragma unroll
            for (int i = 0; i < 2; i++)
#pragma unroll
                for (int j = 0; j < 4; j++)
                    MMA16816(c_[i][j][0], c_[i][j][1], c_[i][j][2], c_[i][j][3],
                             af[i][0], af[i][1], af[i][2], af[i][3],
                             bf[j][0], bf[j][1]);
        }
    }

#pragma unroll
    for (int i = 0; i < 2; i++) {
        int rr0 = rowBase + wm * 32 + i * 16 + gr;
#pragma unroll
        for (int half = 0; half < 2; half++) {
            int r = rr0 + half * 8;
            if (r >= M) continue;
#pragma unroll
            for (int j = 0; j < 4; j++) {
                int cn = colBase + wn * 32 + j * 8 + gc * 2;
                float v0 = c_[i][j][half * 2 + 0] + bias[cn];
                float v1 = c_[i][j][half * 2 + 1] + bias[cn + 1];
                if (ACT >= 1) { v0 = silu_f(v0); v1 = silu_f(v1); }
                if (OUT_HALF) {
                    *(uint32_t*)&((__half*)Cv)[(size_t)r * Nc + cn] = pack_h2(v0, v1);
                } else {
                    *(float2*)&((float*)Cv)[(size_t)r * Nc + cn] = make_float2(v0, v1);
                }
            }
        }
    }
}

// ---------------- hgemm_f32a: fp32 dual-source A (LDG+cvt+STS), B via cp.async ----------------
template <int ACT, bool OUT_HALF>
__global__ __launch_bounds__(512, 2) void hgemm_f32a_kernel(
    const float* __restrict__ A, int lda,
    const float* __restrict__ A2, int lda2, int K1, int K2v,
    const __half* __restrict__ B,
    const float* __restrict__ bias,
    void* __restrict__ Cv,
    int M, int Nc, int K)
{
    extern __shared__ __half hsm[];
    uint32_t su = (uint32_t)__cvta_generic_to_shared(hsm);

    int tid = threadIdx.x;
    int rowBase = blockIdx.y * 128, colBase = blockIdx.x * 128;
    int warp = tid >> 5, lane = tid & 31;
    int wm = warp >> 2, wn = warp & 3;
    int gr = lane >> 2, gc = lane & 3;

    uint32_t aoff = (uint32_t)((wm * 32 + ((lane >> 3) & 1) * 8 + (lane & 7)) * HAS
                               + (lane >> 4) * 8);
    uint32_t boff = (uint32_t)((wn * 32 + (lane >> 4) * 8 + (lane & 7)) * HAS
                               + ((lane >> 3) & 1) * 8);
    uint32_t aBase = su + aoff * 2;
    uint32_t bBase = su + (uint32_t)(HNSTG * HA_SZ) * 2 + boff * 2;

    int arow = tid >> 2, akg = (tid & 3) * 8;
    int ar = rowBase + arow;
    bool arok = ar < M;

    float c_[2][4][4];
#pragma unroll
    for (int i = 0; i < 2; i++)
#pragma unroll
        for (int j = 0; j < 4; j++)
#pragma unroll
            for (int q = 0; q < 4; q++) c_[i][j][q] = 0.0f;

    int nt = K >> 5;

    auto ldgA = [&](int t, uint32_t* r4) {
        int k = (t << 5) + akg;
        float4 v0 = make_float4(0.f, 0.f, 0.f, 0.f);
        float4 v1 = v0;
        if (arok) {
            if (k < K1) {
                const float* s = A + (size_t)ar * lda + k;
                v0 = *(const float4*)s; v1 = *(const float4*)(s + 4);
            } else {
                int kk = k - K1;
                if (kk < K2v) {
                    const float* s = A2 + (size_t)ar * lda2 + kk;
                    v0 = *(const float4*)s; v1 = *(const float4*)(s + 4);
                }
            }
        }
        r4[0] = pack_h2(v0.x, v0.y);
        r4[1] = pack_h2(v0.z, v0.w);
        r4[2] = pack_h2(v1.x, v1.y);
        r4[3] = pack_h2(v1.z, v1.w);
    };
    auto stsA = [&](int s, const uint32_t* r4) {
        uint4 u = make_uint4(r4[0], r4[1], r4[2], r4[3]);
        *(uint4*)&hsm[s * HA_SZ + arow * HAS + akg] = u;
    };
    auto loadB = [&](int s, int t) {
        int k0 = t << 5;
        int nrow = tid >> 2, bch = (tid & 3) * 8;
        cp_async16(su + (uint32_t)(HNSTG * HA_SZ + s * HA_SZ + nrow * HAS + bch) * 2,
                   B + (size_t)(colBase + nrow) * K + k0 + bch, true);
        cp_commit();
    };

    uint32_t ra[4];
    ldgA(0, ra); stsA(0, ra);
    if (1 < nt) ldgA(1, ra);
    loadB(0, 0);
    if (1 < nt) loadB(1, 1); else cp_commit();

    for (int t = 0; t < nt; t++) {
        cp_wait<HNSTG - 2>();
        __syncthreads();
        int cur = t % HNSTG;
        if (t + 2 < nt) loadB((t + 2) % HNSTG, t + 2); else cp_commit();
        if (t + 1 < nt) stsA((t + 1) % HNSTG, ra);
        if (t + 2 < nt) ldgA(t + 2, ra);
        uint32_t aS = aBase + (uint32_t)(cur * HA_SZ) * 2;
        uint32_t bS = bBase + (uint32_t)(cur * HA_SZ) * 2;
#pragma unroll
        for (int kk = 0; kk < 32; kk += 16) {
            uint32_t af[2][4], bf[4][2];
            LDSM_X4(af[0][0], af[0][1], af[0][2], af[0][3], aS + kk * 2);
            LDSM_X4(af[1][0], af[1][1], af[1][2], af[1][3], aS + (16 * HAS + kk) * 2);
            LDSM_X4(bf[0][0], bf[0][1], bf[1][0], bf[1][1], bS + kk * 2);
            LDSM_X4(bf[2][0], bf[2][1], bf[3][0], bf[3][1], bS + (16 * HAS + kk) * 2);
#pragma unroll
            for (int i = 0; i < 2; i++)
#pragma unroll
                for (int j = 0; j < 4; j++)
                    MMA16816(c_[i][j][0], c_[i][j][1], c_[i][j][2], c_[i][j][3],
                             af[i][0], af[i][1], af[i][2], af[i][3],
                             bf[j][0], bf[j][1]);
        }
    }

#pragma unroll
    for (int i = 0; i < 2; i++) {
        int rr0 = rowBase + wm * 32 + i * 16 + gr;
#pragma unroll
        for (int half = 0; half < 2; half++) {
            int r = rr0 + half * 8;
            if (r >= M) continue;
#pragma unroll
            for (int j = 0; j < 4; j++) {
                int cn = colBase + wn * 32 + j * 8 + gc * 2;
                float v0 = c_[i][j][half * 2 + 0] + (bias ? bias[cn] : 0.f);
                float v1 = c_[i][j][half * 2 + 1] + (bias ? bias[cn + 1] : 0.f);
                if (ACT >= 1) { v0 = silu_f(v0); v1 = silu_f(v1); }
                if (OUT_HALF) {
                    *(uint32_t*)&((__half*)Cv)[(size_t)r * Nc + cn] = pack_h2(v0, v1);
                } else {
                    *(float2*)&((float*)Cv)[(size_t)r * Nc + cn] = make_float2(v0, v1);
                }
            }
        }
    }
}

// ---------------- edge_mega: We2 GEMM + agg + Wc1 GEMM + phi + x-scatter ----------------
// 1024 threads, CTA tile 128 edges x 256 cols. m lives only in smem.
#define SMS 264
#define MG_AS 7168          // halves per A1 stage (128*56)
#define MG_BS 14336         // halves per B stage (256*56)
#define MG_B1 21504         // halves offset of B1 stages
#define MG_B2 33792         // halves offset of B2 stages (= sM size 128*264)
#define MG_SMEM 153600      // bytes

__global__ __launch_bounds__(1024, 1) void edge_mega_kernel(
    const __half* __restrict__ m1, const __half* __restrict__ We2T,
    const float* __restrict__ be2, const float* __restrict__ ew,
    const __half* __restrict__ Wc1T, const float* __restrict__ bc1,
    const float* __restrict__ Wc2,
    const float* __restrict__ x, const int* __restrict__ el,
    float* __restrict__ agg, float* __restrict__ xacc)
{
    extern __shared__ __half hsm[];
    uint32_t su = (uint32_t)__cvta_generic_to_shared(hsm);
    int tid = threadIdx.x;
    int rowBase = blockIdx.x * 128;
    int warp = tid >> 5, lane = tid & 31;
    int wm = warp >> 3, wn = warp & 7;
    int gr = lane >> 2, gc = lane & 3;

    uint32_t afrag = (uint32_t)((wm * 32 + ((lane >> 3) & 1) * 8 + (lane & 7)) * HAS
                                + (lane >> 4) * 8);
    uint32_t bfrag = (uint32_t)((wn * 32 + (lane >> 4) * 8 + (lane & 7)) * HAS
                                + ((lane >> 3) & 1) * 8);
    uint32_t a2frag = (uint32_t)((wm * 32 + ((lane >> 3) & 1) * 8 + (lane & 7)) * SMS
                                 + (lane >> 4) * 8);

    auto load1 = [&](int s, int t) {
        int k0 = t << 5;
        if (tid < 512) {
            int arow = tid >> 2, ach = (tid & 3) * 8;
            cp_async16(su + (uint32_t)(s * MG_AS + arow * HAS + ach) * 2,
                       m1 + (size_t)(rowBase + arow) * 256 + k0 + ach, true);
        }
        {
            int nrow = tid >> 2, bch = (tid & 3) * 8;
            cp_async16(su + (uint32_t)(MG_B1 + s * MG_BS + (nrow & 255) * HAS + bch) * 2,
                       We2T + (size_t)(nrow & 255) * 256 + k0 + bch, true);
        }
        cp_commit();
    };
    auto load2 = [&](int s, int t) {
        int k0 = t << 5;
        int nrow = tid >> 2, bch = (tid & 3) * 8;
        cp_async16(su + (uint32_t)(MG_B2 + s * MG_BS + (nrow & 255) * HAS + bch) * 2,
                   Wc1T + (size_t)(nrow & 255) * 256 + k0 + bch, true);
        cp_commit();
    };

    // ---- GEMM1: m = silu(m1 @ We2T^T + be2) * ew ----
    float c_[2][4][4];
#pragma unroll
    for (int i = 0; i < 2; i++)
#pragma unroll
        for (int j = 0; j < 4; j++)
#pragma unroll
            for (int q = 0; q < 4; q++) c_[i][j][q] = 0.0f;

    load1(0, 0);
    load1(1, 1);
    for (int t = 0; t < 8; t++) {
        cp_wait<1>();
        __syncthreads();
        int cur = t % 3;
        if (t + 2 < 8) load1((t + 2) % 3, t + 2); else cp_commit();
        uint32_t aS = su + (uint32_t)(cur * MG_AS) * 2 + afrag * 2;
        uint32_t bS = su + (uint32_t)(MG_B1 + cur * MG_BS) * 2 + bfrag * 2;
#pragma unroll
        for (int kk = 0; kk < 32; kk += 16) {
            uint32_t af[2][4], bf[4][2];
            LDSM_X4(af[0][0], af[0][1], af[0][2], af[0][3], aS + kk * 2);
            LDSM_X4(af[1][0], af[1][1], af[1][2], af[1][3], aS + (16 * HAS + kk) * 2);
            LDSM_X4(bf[0][0], bf[0][1], bf[1][0], bf[1][1], bS + kk * 2);
            LDSM_X4(bf[2][0], bf[2][1], bf[3][0], bf[3][1], bS + (16 * HAS + kk) * 2);
#pragma unroll
            for (int i = 0; i < 2; i++)
#pragma unroll
                for (int j = 0; j < 4; j++)
                    MMA16816(c_[i][j][0], c_[i][j][1], c_[i][j][2], c_[i][j][3],
                             af[i][0], af[i][1], af[i][2], af[i][3],
                             bf[j][0], bf[j][1]);
        }
    }
    __syncthreads();   // all reads of GEMM1 stages done

    // prefetch GEMM2 B stages 0,1 (targets old B1 region base MG_B2 — disjoint from sM)
    load2(0, 0);
    load2(1, 1);

    // epilogue1: silu(+be2)*ew -> sM (half) + agg atomics
#pragma unroll
    for (int i = 0; i < 2; i++)
#pragma unroll
        for (int half = 0; half < 2; half++) {
            int rl = wm * 32 + i * 16 + half * 8 + gr;
            int r = rowBase + rl;
            float sc = ew[r];
            int cc = el[3 * r + 1], rlx = el[3 * r + 2];
            size_t ab = ((size_t)cc * RR + rlx) * 256;
#pragma unroll
            for (int j = 0; j < 4; j++) {
                int cn = wn * 32 + j * 8 + gc * 2;
                float v0 = silu_f(c_[i][j][half * 2 + 0] + be2[cn]) * sc;
                float v1 = silu_f(c_[i][j][half * 2 + 1] + be2[cn + 1]) * sc;
                *(uint32_t*)&hsm[rl * SMS + cn] = pack_h2(v0, v1);
                red_add_v2(&agg[ab + cn], v0, v1);
            }
        }
    __syncthreads();

    // ---- GEMM2: t1 = silu(m(sM) @ Wc1T^T + bc1) ----
    float c2[2][4][4];
#pragma unroll
    for (int i = 0; i < 2; i++)
#pragma unroll
        for (int j = 0; j < 4; j++)
#pragma unroll
            for (int q = 0; q < 4; q++) c2[i][j][q] = 0.0f;

    for (int t = 0; t < 8; t++) {
        cp_wait<1>();
        __syncthreads();
        int cur = t % 3;
        if (t + 2 < 8) load2((t + 2) % 3, t + 2); else cp_commit();
        uint32_t aS = su + (a2frag + (uint32_t)(t * 32)) * 2;
        uint32_t bS = su + (uint32_t)(MG_B2 + cur * MG_BS) * 2 + bfrag * 2;
#pragma unroll
        for (int kk = 0; kk < 32; kk += 16) {
            uint32_t af[2][4], bf[4][2];
            LDSM_X4(af[0][0], af[0][1], af[0][2], af[0][3], aS + kk * 2);
            LDSM_X4(af[1][0], af[1][1], af[1][2], af[1][3], aS + (16 * SMS + kk) * 2);
            LDSM_X4(bf[0][0], bf[0][1], bf[1][0], bf[1][1], bS + kk * 2);
            LDSM_X4(bf[2][0], bf[2][1], bf[3][0], bf[3][1], bS + (16 * HAS + kk) * 2);
#pragma unroll
            for (int i = 0; i < 2; i++)
#pragma unroll
                for (int j = 0; j < 4; j++)
                    MMA16816(c2[i][j][0], c2[i][j][1], c2[i][j][2], c2[i][j][3],
                             af[i][0], af[i][1], af[i][2], af[i][3],
                             bf[j][0], bf[j][1]);
        }
    }
    __syncthreads();   // B2 stage reads done; safe to overwrite with phi arrays

    // ---- phi epilogue ----
    float* fs   = (float*)hsm;
    float* sW2  = fs + 16896;    // [256][17]
    float* sB1c = fs + 21248;    // [256]
    float* sT   = fs + 21504;    // [128][72]

    for (int idx = tid; idx < 4096; idx += 1024) {
        int rr = idx >> 4, n = idx & 15;
        sW2[rr * 17 + n] = Wc2[(size_t)rr * 16 + n];
    }
    if (tid < 256) sB1c[tid] = bc1[tid];

    float p0 = 0.f, p1 = 0.f;
    int pr = tid >> 3, pq = tid & 7;
    int pn0 = pq * 2;

#pragma unroll 1
    for (int ch = 0; ch < 4; ch++) {
        __syncthreads();
        if ((wn >> 1) == ch) {
#pragma unroll
            for (int j = 0; j < 4; j++) {
                int cn = wn * 32 + j * 8 + gc * 2;
                int lcol = (wn & 1) * 32 + j * 8 + gc * 2;
                float bb0 = sB1c[cn], bb1 = sB1c[cn + 1];
#pragma unroll
                for (int i = 0; i < 2; i++)
#pragma unroll
                    for (int half = 0; half < 2; half++) {
                        int lr = wm * 32 + i * 16 + half * 8 + gr;
                        float v0 = silu_f(c2[i][j][half * 2 + 0] + bb0);
                        float v1 = silu_f(c2[i][j][half * 2 + 1] + bb1);
                        *(float2*)&sT[lr * 72 + lcol] = make_float2(v0, v1);
                    }
            }
        }
        __syncthreads();
#pragma unroll
        for (int cb = 0; cb < 16; cb++) {
            float4 t4 = *(const float4*)&sT[pr * 72 + cb * 4];
#pragma unroll
            for (int k = 0; k < 4; k++) {
                float tv = (&t4.x)[k];
                int wr = ch * 64 + cb * 4 + k;
                p0 = fmaf(tv, sW2[wr * 17 + pn0], p0);
                p1 = fmaf(tv, sW2[wr * 17 + pn0 + 1], p1);
            }
        }
    }

    // x scatter: thread holds phi cols pn0, pn0+1 of row pr
    {
        int i2 = pq >> 1;
        int j2a = pn0 & 3, j2b = (pn0 + 1) & 3;
        int e = rowBase + pr;
        int rw = el[3 * e], cl = el[3 * e + 1];
        float xr0 = x[rw * 12 + i2 * 3 + 0];
        float xr1 = x[rw * 12 + i2 * 3 + 1];
        float xr2 = x[rw * 12 + i2 * 3 + 2];
        float s0 = (xr0 - x[cl * 12 + j2a * 3 + 0]) * p0 + (xr0 - x[cl * 12 + j2b * 3 + 0]) * p1;
        float s1 = (xr1 - x[cl * 12 + j2a * 3 + 1]) * p0 + (xr1 - x[cl * 12 + j2b * 3 + 1]) * p1;
        float s2 = (xr2 - x[cl * 12 + j2a * 3 + 2]) * p0 + (xr2 - x[cl * 12 + j2b * 3 + 2]) * p1;
        s0 += __shfl_xor_sync(0xFFFFFFFFu, s0, 1);
        s1 += __shfl_xor_sync(0xFFFFFFFFu, s1, 1);
        s2 += __shfl_xor_sync(0xFFFFFFFFu, s2, 1);
        if ((tid & 1) == 0) {
            atomicAdd(&xacc[rw * 12 + i2 * 3 + 0], 0.25f * s0);
            atomicAdd(&xacc[rw * 12 + i2 * 3 + 1], 0.25f * s1);
            atomicAdd(&xacc[rw * 12 + i2 * 3 + 2], 0.25f * s2);
        }
    }
}

// ---------------- edge fuse (half out) ----------------
__global__ __launch_bounds__(256) void edge_fuse_kernel(
    const float* __restrict__ PQ,
    const float* __restrict__ x, const int* __restrict__ el,
    const float* __restrict__ cw,
    const float* __restrict__ Wrad, const float* __restrict__ brad,
    const float* __restrict__ W1c, const float* __restrict__ be1,
    __half* __restrict__ m1)
{
    __shared__ __align__(16) float sW1c[16][256];
    __shared__ float sWrad[16][16];
    __shared__ float sbrad[16];
    __shared__ __align__(16) float sbe1[256];
    __shared__ float srad[8][16];
    __shared__ float srf[8][16];
    int tid = threadIdx.x;
    for (int i = tid; i < 16 * 256; i += 256) sW1c[i >> 8][i & 255] = W1c[i];
    sbe1[tid] = be1[tid];
    { int r = tid >> 4, c = tid & 15; sWrad[r][c] = Wrad[tid]; }
    if (tid < 16) sbrad[tid] = brad[tid];
    __syncthreads();

    int warp = tid >> 5, lane = tid & 31;
#pragma unroll 1
    for (int ei = 0; ei < 8; ei++) {
        int e = blockIdx.x * 64 + warp * 8 + ei;
        int row = el[3*e], col = el[3*e+1];

        if (lane < 16) {
            int i = lane >> 2, j = lane & 3;
            float dx = x[row*12 + i*3 + 0] - x[col*12 + j*3 + 0];
            float dy = x[row*12 + i*3 + 1] - x[col*12 + j*3 + 1];
            float dz = x[row*12 + i*3 + 2] - x[col*12 + j*3 + 2];
            srad[warp][lane] = (dx*dx + dy*dy + dz*dz) * cw[row*4 + i] * cw[col*4 + j];
        }
        __syncwarp();
        if (lane < 16) {
            float acc = sbrad[lane];
#pragma unroll
            for (int k = 0; k < 16; k++) acc = fmaf(srad[warp][k], sWrad[k][lane], acc);
            srf[warp][lane] = silu_f(acc);
        }
        __syncwarp();

        const float4* Pr = (const float4*)(PQ + (size_t)row * 512);
        const float4* Qc = (const float4*)(PQ + (size_t)col * 512 + 256);
        __half* Om = m1 + (size_t)e * 256;
#pragma unroll
        for (int half = 0; half < 2; half++) {
            int o4 = lane * 2 + half;
            float4 pv = Pr[o4], qv = Qc[o4];
            float4 b = ((const float4*)sbe1)[o4];
            float4 s = make_float4(pv.x + qv.x + b.x, pv.y + qv.y + b.y,
                                   pv.z + qv.z + b.z, pv.w + qv.w + b.w);
#pragma unroll
            for (int k = 0; k < 16; k++) {
                float rk = srf[warp][k];
                float4 w = ((const float4*)&sW1c[k][0])[o4];
                s.x = fmaf(rk, w.x, s.x); s.y = fmaf(rk, w.y, s.y);
                s.z = fmaf(rk, w.z, s.z); s.w = fmaf(rk, w.w, s.w);
            }
            *(uint32_t*)&Om[o4 * 4]     = pack_h2(silu_f(s.x), silu_f(s.y));
            *(uint32_t*)&Om[o4 * 4 + 2] = pack_h2(silu_f(s.z), silu_f(s.w));
        }
        __syncwarp();
    }
}

// ---------------- layernorm ----------------
__global__ void ln_kernel(const float* __restrict__ h2, const float* __restrict__ g,
                          const float* __restrict__ b, float* __restrict__ out) {
    int n = blockIdx.x;
    int t = threadIdx.x;
    float v = h2[(size_t)n * 256 + t];
    float a = v, sq = v * v;
#pragma unroll
    for (int o = 16; o > 0; o >>= 1) {
        a  += __shfl_down_sync(0xFFFFFFFFu, a, o);
        sq += __shfl_down_sync(0xFFFFFFFFu, sq, o);
    }
    __shared__ float s1[8], s2[8];
    if ((t & 31) == 0) { s1[t >> 5] = a; s2[t >> 5] = sq; }
    __syncthreads();
    __shared__ float mu, rs;
    if (t == 0) {
        float A = 0.f, B = 0.f;
#pragma unroll
        for (int i = 0; i < 8; i++) { A += s1[i]; B += s2[i]; }
        float m = A * (1.0f / 256.0f);
        mu = m;
        rs = rsqrtf(B * (1.0f / 256.0f) - m * m + EPSV);
    }
    __syncthreads();
    out[(size_t)n * 256 + t] = (v - mu) * rs * g[t] + b[t];
}

__global__ void x_final_kernel(const float* __restrict__ xin, const float* __restrict__ xacc,
                               const float* __restrict__ cnt, float* __restrict__ xout) {
    int i = blockIdx.x * blockDim.x + threadIdx.x;
    if (i >= NN * 12) return;
    int n = i / 12;
    xout[i] = xin[i] + xacc[i] / fmaxf(cnt[n], 1.0f);
}

// ---------------- host ----------------
extern "C" void kernel_launch(void* const* d_in, const int* in_sizes, int n_in,
                              void* d_out, int out_size) {
    const float* input  = nullptr;
    const float* coords = nullptr;
    const float* attr   = nullptr;
    const float* cw     = nullptr;
    const float* ew     = nullptr;
    const int*   el     = nullptr;
    for (int i = 0; i < 6; i++) {
        switch (in_sizes[i]) {
            case NN * HH:     input  = (const float*)d_in[i]; break;
            case NN * 4 * 3:  coords = (const float*)d_in[i]; break;
            case NN * 4 * 16: attr   = (const float*)d_in[i]; break;
            case NN * 4:      cw     = (const float*)d_in[i]; break;
            case EE:          ew     = (const float*)d_in[i]; break;
            case EE * 3:      el     = (const int*)  d_in[i]; break;
        }
    }
    const float* W_rad = (const float*)d_in[6];
    const float* b_rad = (const float*)d_in[7];
    const float* W_e1  = (const float*)d_in[8];
    const float* b_e1  = (const float*)d_in[9];
    const float* W_e2  = (const float*)d_in[10];
    const float* b_e2  = (const float*)d_in[11];
    const float* W_c1  = (const float*)d_in[12];
    const float* b_c1  = (const float*)d_in[13];
    const float* W_c2  = (const float*)d_in[14];
    const float* W_n1  = (const float*)d_in[15];
    const float* b_n1  = (const float*)d_in[16];
    const float* W_n2  = (const float*)d_in[17];
    const float* b_n2  = (const float*)d_in[18];
    const float* ln_g  = (const float*)d_in[19];
    const float* ln_b  = (const float*)d_in[20];

    float* buf = nullptr;
    cudaGetSymbolAddress((void**)&buf, g_buf);

    float*  g_ca   = buf + OFF_CA;
    float*  g_pq   = buf + OFF_PQ;
    __half* g_m1h  = (__half*)(buf + OFF_M1H);
    float*  g_agg  = buf + OFF_AGG;
    __half* g_h1h  = (__half*)(buf + OFF_H1H);
    float*  g_hbuf = buf + OFF_HBUF;
    float*  g_xbuf = buf + OFF_XBUF;
    float*  g_xacc = buf + OFF_XACC;
    float*  g_cnt  = buf + OFF_CNT;
    __half* g_wpqt = (__half*)(buf + OFF_WPQT);
    __half* g_we2t = (__half*)(buf + OFF_WE2T);
    __half* g_wc1t = (__half*)(buf + OFF_WC1T);
    __half* g_wn2t = (__half*)(buf + OFF_WN2T);
    __half* g_wn1t = (__half*)(buf + OFF_WN1T);

    cudaFuncSetAttribute((const void*)hgemm_kernel<0, false>,
                         cudaFuncAttributeMaxDynamicSharedMemorySize, HSMEM_BYTES);
    cudaFuncSetAttribute((const void*)hgemm_f32a_kernel<0, false>,
                         cudaFuncAttributeMaxDynamicSharedMemorySize, HSMEM_BYTES);
    cudaFuncSetAttribute((const void*)hgemm_f32a_kernel<1, true>,
                         cudaFuncAttributeMaxDynamicSharedMemorySize, HSMEM_BYTES);
    cudaFuncSetAttribute((const void*)edge_mega_kernel,
                         cudaFuncAttributeMaxDynamicSharedMemorySize, MG_SMEM);

    // one-time: ca, cnt
    ca_kernel<<<(NN + 255) / 256, 256>>>(attr, cw, g_ca);
    zero4_kernel<<<(NN/4 + 255) / 256, 256>>>((float4*)g_cnt, (size_t)NN / 4);
    cnt_kernel<<<(EE + 255) / 256, 256>>>(el, g_cnt);

    for (int l = 0; l < LL; l++) {
        const float* h_in = (l == 0) ? input  : g_hbuf;
        const float* x_in = (l == 0) ? coords : g_xbuf;
        float* h_out = (l == LL - 1) ? (float*)d_out : g_hbuf;
        float* x_out = (l == LL - 1) ? ((float*)d_out + (size_t)NN * HH) : g_xbuf;

        const float* Wr  = W_rad + (size_t)l * 256;
        const float* br  = b_rad + (size_t)l * 16;
        const float* We1 = W_e1 + (size_t)l * 560 * 256;
        const float* be1 = b_e1 + (size_t)l * 256;
        const float* We2 = W_e2 + (size_t)l * 256 * 256;
        const float* be2 = b_e2 + (size_t)l * 256;
        const float* Wc1 = W_c1 + (size_t)l * 256 * 256;
        const float* bc1 = b_c1 + (size_t)l * 256;
        const float* Wc2 = W_c2 + (size_t)l * 256 * 16;
        const float* Wn1 = W_n1 + (size_t)l * 2048 * 256;
        const float* bn1 = b_n1 + (size_t)l * 256;
        const float* Wn2 = W_n2 + (size_t)l * 256 * 256;
        const float* bn2 = b_n2 + (size_t)l * 256;
        const float* lg  = ln_g + (size_t)l * 256;
        const float* lb  = ln_b + (size_t)l * 256;

        wprep_all<<<1280, 256>>>(We2, Wc1, Wn2, Wn1, We1,
                                 g_we2t, g_wc1t, g_wn2t, g_wn1t, g_wpqt);
        zero4_kernel<<<(unsigned)(((size_t)NN*1792/4 + 255) / 256), 256>>>(
            (float4*)g_agg, (size_t)NN*1792/4);
        zero4_kernel<<<(NN*12/4 + 255) / 256, 256>>>((float4*)g_xacc, (size_t)NN*12/4);

        // PQ = [h|ca] @ WpqT^T  (f32 A dual source, f32 out)
        hgemm_f32a_kernel<0, false><<<dim3(4, (NN + 127) / 128), 512, HSMEM_BYTES>>>(
            h_in, 256, g_ca, 16, 256, 16,
            g_wpqt, nullptr, g_pq, NN, 512, 288);
        // m1
        edge_fuse_kernel<<<EE / 64, 256>>>(g_pq, x_in, el, cw,
                                           Wr, br, We1 + (size_t)512 * 256, be1, g_m1h);
        // fused We2 GEMM + agg + Wc1 GEMM + phi + x scatter
        edge_mega_kernel<<<EE / 128, 1024, MG_SMEM>>>(
            g_m1h, g_we2t, be2, ew, g_wc1t, bc1, Wc2, x_in, el, g_agg, g_xacc);
        // h1 = silu([agg|h]@Wn1+bn1)  (f32 A dual source, half out)
        hgemm_f32a_kernel<1, true><<<dim3(2, (NN + 127) / 128), 512, HSMEM_BYTES>>>(
            g_agg, 1792, h_in, 256, 1792, 256,
            g_wn1t, bn1, g_h1h, NN, 256, 2048);
        // h2 = h1@Wn2+bn2 (half A, f32 out)
        hgemm_kernel<0, false><<<dim3(2, (NN + 127) / 128), 512, HSMEM_BYTES>>>(
            g_h1h, 256, g_wn2t, bn2, g_pq, NN, 256, 256);

        ln_kernel<<<NN, 256>>>(g_pq, lg, lb, h_out);
        x_final_kernel<<<(NN * 12 + 255) / 256, 256>>>(x_in, g_xacc, g_cnt, x_out);
    }
}